// round 2
// baseline (speedup 1.0000x reference)
#include <cuda_runtime.h>
#include <math.h>

// ---------------- problem dims ----------------
#define B_    32
#define C_    8
#define T_    20000
#define P_    25
#define D_    512
#define H_    8
#define M_    256
#define NL_   2
#define FFN_  1024
#define NC_   10
#define HID_  128
#define DH_   64
#define L_    800            // 20000 / 25, exact (no pad)
#define R_    (B_*L_)        // 25600 token rows

// ---------------- scratch (device globals; no allocation allowed) ----------------
__device__ float g_tok[R_*C_*P_];          // 5.12M
__device__ float g_h[R_*D_];               // 13.1M
__device__ float g_x1[R_*D_];              // 13.1M
__device__ float g_tmp[R_*FFN_];           // 26.2M (patch pre-LN / FFN mid / pool T)
__device__ float g_Q[R_*D_];
__device__ float g_K[R_*D_];
__device__ float g_V[R_*D_];
__device__ float g_Qf[B_*H_*L_*M_];        // 52.4M
__device__ float g_Kf[B_*H_*L_*M_];        // 52.4M
__device__ float g_KV[B_*H_*M_*DH_];       // 4.2M
__device__ float g_Ksum[B_*H_*M_];
__device__ float g_attno[R_*D_];
__device__ float g_scores[R_];
__device__ float g_feat[B_*2*D_];

// ---------------- helpers ----------------
__device__ __forceinline__ float block_sum_256(float v, volatile float* red){
    int lane = threadIdx.x & 31, w = threadIdx.x >> 5;
    #pragma unroll
    for(int o=16;o;o>>=1) v += __shfl_xor_sync(0xffffffffu, v, o);
    if(lane==0) red[w] = v;
    __syncthreads();
    if(threadIdx.x < 32){
        float r = (threadIdx.x < 8) ? red[threadIdx.x] : 0.f;
        #pragma unroll
        for(int o=4;o;o>>=1) r += __shfl_xor_sync(0xffffffffu, r, o);
        if(threadIdx.x==0) red[0] = r;
    }
    __syncthreads();
    float out = red[0];
    __syncthreads();
    return out;
}

// ---------------- patchify: tok[b,l,c*P+p] = x[b,c,l*P+p] ----------------
__global__ void patchify_kernel(const float* __restrict__ x){
    int idx = blockIdx.x*blockDim.x + threadIdx.x;
    if(idx >= B_*C_*T_) return;
    int t  = idx % T_;
    int bc = idx / T_;
    int c  = bc % C_;
    int b  = bc / C_;
    int l = t / P_, p = t % P_;
    g_tok[((size_t)(b*L_ + l)*C_ + c)*P_ + p] = x[idx];
}

// ---------------- LayerNorm over 512 ----------------
__global__ void __launch_bounds__(256) ln_kernel(const float* __restrict__ X,
        const float* __restrict__ g, const float* __restrict__ be, float* __restrict__ Y){
    __shared__ float red[32];
    int row = blockIdx.x, t = threadIdx.x;
    const float* xr = X + (size_t)row*D_;
    float v0 = xr[t], v1 = xr[t+256];
    float mu = block_sum_256(v0+v1, red) * (1.f/512.f);
    float d0 = v0-mu, d1 = v1-mu;
    float var = block_sum_256(d0*d0 + d1*d1, red) * (1.f/512.f);
    float inv = rsqrtf(var + 1e-5f);
    float* yr = Y + (size_t)row*D_;
    yr[t]     = d0*inv*g[t]     + be[t];
    yr[t+256] = d1*inv*g[t+256] + be[t+256];
}

// ---------------- SGEMM 128x128x16, 8x8 micro-tiles ----------------
template<bool GELU>
__global__ void __launch_bounds__(256) gemm128(
        const float* __restrict__ A, const float* __restrict__ Bm,
        const float* __restrict__ bias, const float* __restrict__ res,
        float* __restrict__ C, int M, int N, int K)
{
    __shared__ float As[16][132];   // +4 pad: breaks transpose-write conflicts
    __shared__ float Bs[16][128];
    int tid = threadIdx.x;
    int tx = tid & 15, ty = tid >> 4;
    int row0 = blockIdx.y*128, col0 = blockIdx.x*128;
    float acc[8][8];
    #pragma unroll
    for(int i=0;i<8;i++)
        #pragma unroll
        for(int j=0;j<8;j++) acc[i][j] = 0.f;

    for(int k0=0;k0<K;k0+=16){
        #pragma unroll
        for(int i=0;i<8;i++){
            int idx = tid + i*256;
            int m = idx >> 4, k = idx & 15;
            int gk = k0 + k, gm = row0 + m;
            float v = (gk < K && gm < M) ? A[(size_t)gm*K + gk] : 0.f;
            As[k][m] = v;
        }
        #pragma unroll
        for(int i=0;i<8;i++){
            int idx = tid + i*256;
            int k = idx >> 7, n = idx & 127;
            int gk = k0 + k, gn = col0 + n;
            float v = (gk < K && gn < N) ? Bm[(size_t)gk*N + gn] : 0.f;
            Bs[k][n] = v;
        }
        __syncthreads();
        #pragma unroll
        for(int k=0;k<16;k++){
            float a[8], b[8];
            float4 a0 = *(const float4*)&As[k][ty*8];
            float4 a1 = *(const float4*)&As[k][ty*8+4];
            a[0]=a0.x; a[1]=a0.y; a[2]=a0.z; a[3]=a0.w;
            a[4]=a1.x; a[5]=a1.y; a[6]=a1.z; a[7]=a1.w;
            float4 b0 = *(const float4*)&Bs[k][tx*8];
            float4 b1 = *(const float4*)&Bs[k][tx*8+4];
            b[0]=b0.x; b[1]=b0.y; b[2]=b0.z; b[3]=b0.w;
            b[4]=b1.x; b[5]=b1.y; b[6]=b1.z; b[7]=b1.w;
            #pragma unroll
            for(int i=0;i<8;i++)
                #pragma unroll
                for(int j=0;j<8;j++) acc[i][j] += a[i]*b[j];
        }
        __syncthreads();
    }
    #pragma unroll
    for(int i=0;i<8;i++){
        int r = row0 + ty*8 + i;
        if(r >= M) continue;
        #pragma unroll
        for(int j=0;j<8;j++){
            int c = col0 + tx*8 + j;
            if(c >= N) continue;
            float v = acc[i][j];
            if(bias) v += bias[c];
            if(GELU) v = 0.5f*v*(1.f + erff(v*0.70710678118f));
            if(res)  v += res[(size_t)r*N + c];
            C[(size_t)r*N + c] = v;
        }
    }
}

// ---------------- FAVOR+ feature map (per (b,h), omega cached in smem) ----------------
__global__ void __launch_bounds__(256) phi_kernel(const float* __restrict__ X,
        const float* __restrict__ omg, float* __restrict__ F){
    extern __shared__ float sm[];
    float* om = sm;             // [64][256]
    float* xs = sm + 64*256;    // [8 warps][64]
    int bh = blockIdx.x;
    int b = bh >> 3, h = bh & 7;
    int tid = threadIdx.x, wid = tid >> 5, lane = tid & 31;
    for(int i=tid;i<64*256;i+=256) om[i] = omg[i];
    __syncthreads();
    const float sc = 0.3535533906f;   // 1 / 64^{1/4}
    float* xw = xs + wid*64;
    for(int l=wid; l<L_; l+=8){
        const float* xr = X + ((size_t)(b*L_ + l))*D_ + h*DH_;
        xw[lane]    = xr[lane]    * sc;
        xw[lane+32] = xr[lane+32] * sc;
        __syncwarp();
        float n2 = xw[lane]*xw[lane] + xw[lane+32]*xw[lane+32];
        #pragma unroll
        for(int o=16;o;o>>=1) n2 += __shfl_xor_sync(0xffffffffu, n2, o);
        n2 *= 0.5f;
        float acc[8];
        #pragma unroll
        for(int j=0;j<8;j++) acc[j]=0.f;
        #pragma unroll 8
        for(int d=0; d<64; d++){
            float xv = xw[d];
            #pragma unroll
            for(int j=0;j<8;j++) acc[j] += xv*om[d*256 + lane + 32*j];
        }
        float* o = F + ((size_t)bh*L_ + l)*M_;
        #pragma unroll
        for(int j=0;j<8;j++) o[lane + 32*j] = expf(acc[j]-n2)*0.0625f;  // / sqrt(256)
        __syncwarp();
    }
}

// ---------------- KV = Kf^T V, Ksum = sum_l Kf  (one block per (b,h)) ----------------
__global__ void __launch_bounds__(256) kv_kernel(const float* __restrict__ Kf,
        const float* __restrict__ V, float* __restrict__ KV, float* __restrict__ Ks){
    __shared__ float Kfs[32*256];
    __shared__ float Vs[32*64];
    int bh = blockIdx.x;
    int b = bh >> 3, h = bh & 7;
    int t = threadIdx.x;          // t = m
    float acc[64];
    #pragma unroll
    for(int d=0;d<64;d++) acc[d]=0.f;
    float ks = 0.f;
    for(int l0=0;l0<L_;l0+=32){
        __syncthreads();
        #pragma unroll 4
        for(int i=0;i<32;i++) Kfs[i*256+t] = Kf[((size_t)bh*L_ + l0+i)*M_ + t];
        #pragma unroll
        for(int i=0;i<8;i++){
            int idx = t + i*256;
            int l = idx >> 6, d = idx & 63;
            Vs[idx] = V[((size_t)(b*L_ + l0 + l))*D_ + h*DH_ + d];
        }
        __syncthreads();
        for(int l=0;l<32;l++){
            float kf = Kfs[l*256+t];
            ks += kf;
            #pragma unroll
            for(int q=0;q<16;q++){
                float4 v = *(const float4*)&Vs[l*64 + q*4];
                acc[q*4+0] += kf*v.x;
                acc[q*4+1] += kf*v.y;
                acc[q*4+2] += kf*v.z;
                acc[q*4+3] += kf*v.w;
            }
        }
    }
    float* o = KV + (size_t)bh*M_*DH_ + t*DH_;
    #pragma unroll
    for(int d=0;d<64;d++) o[d] = acc[d];
    Ks[bh*M_ + t] = ks;
}

// ---------------- out = (Qf @ KV) / max(Qf @ Ksum, 1e-6) ----------------
__global__ void __launch_bounds__(256) attn_out_kernel(const float* __restrict__ Qf,
        const float* __restrict__ KV, const float* __restrict__ Ks, float* __restrict__ out){
    extern __shared__ float sm[];
    float* KVs = sm;              // [256][64]
    float* Kss = sm + 16384;      // [256]
    float* Qfs = sm + 16640;      // [8 warps][4 tok][256]
    int bh = blockIdx.x;
    int b = bh >> 3, h = bh & 7;
    int l0 = blockIdx.y*32;
    int tid = threadIdx.x, wid = tid >> 5, lane = tid & 31;
    const float* KVg = KV + (size_t)bh*M_*DH_;
    for(int i=tid;i<16384;i+=256) KVs[i] = KVg[i];
    Kss[tid] = Ks[bh*M_ + tid];
    __syncthreads();
    int lb = l0 + wid*4;
    float* Qw = Qfs + wid*1024;
    const float* Qg = Qf + ((size_t)bh*L_ + lb)*M_;
    for(int i=lane;i<1024;i+=32) Qw[i] = Qg[i];
    __syncwarp();
    float nr[4];
    #pragma unroll
    for(int tt=0;tt<4;tt++){
        float s2 = 0.f;
        #pragma unroll
        for(int j=0;j<8;j++){ int m = lane + 32*j; s2 += Qw[tt*256+m]*Kss[m]; }
        #pragma unroll
        for(int o=16;o;o>>=1) s2 += __shfl_xor_sync(0xffffffffu, s2, o);
        nr[tt] = 1.f/fmaxf(s2, 1e-6f);
    }
    float ax[4] = {0.f,0.f,0.f,0.f};
    float ay[4] = {0.f,0.f,0.f,0.f};
    int d2 = lane*2;
    #pragma unroll 4
    for(int m=0;m<256;m++){
        float2 kv = *(const float2*)&KVs[m*64 + d2];
        #pragma unroll
        for(int tt=0;tt<4;tt++){
            float q = Qw[tt*256+m];
            ax[tt] += q*kv.x;
            ay[tt] += q*kv.y;
        }
    }
    #pragma unroll
    for(int tt=0;tt<4;tt++){
        int l = lb + tt;
        float* o = out + ((size_t)(b*L_ + l))*D_ + h*DH_ + d2;
        o[0] = ax[tt]*nr[tt];
        o[1] = ay[tt]*nr[tt];
    }
}

// ---------------- pooling scores: sc[r] = tanh(T_row) . W2 ----------------
__global__ void score2_kernel(const float* __restrict__ Tt, const float* __restrict__ W2,
                              float* __restrict__ sc){
    int r = blockIdx.x*blockDim.x + threadIdx.x;
    if(r >= R_) return;
    const float* tr = Tt + (size_t)r*HID_;
    float s = 0.f;
    #pragma unroll 8
    for(int j=0;j<HID_;j++) s += tanhf(tr[j]) * __ldg(&W2[j]);
    sc[r] = s;
}

// ---------------- softmax over L + attentive stats ----------------
__global__ void __launch_bounds__(256) pool_kernel(const float* __restrict__ h,
        const float* __restrict__ sc, float* __restrict__ feat){
    __shared__ float al[L_];
    __shared__ float red[32];
    int b = blockIdx.x, t = threadIdx.x;
    float lmax = -1e30f;
    for(int i=t;i<L_;i+=256){ float v = sc[b*L_+i]; al[i]=v; lmax=fmaxf(lmax,v); }
    #pragma unroll
    for(int o=16;o;o>>=1) lmax = fmaxf(lmax, __shfl_xor_sync(0xffffffffu, lmax, o));
    if((t&31)==0) red[t>>5] = lmax;
    __syncthreads();
    if(t < 32){
        float r = (t < 8) ? red[t] : -1e30f;
        #pragma unroll
        for(int o=4;o;o>>=1) r = fmaxf(r, __shfl_xor_sync(0xffffffffu, r, o));
        if(t==0) red[0] = r;
    }
    __syncthreads();
    float mx = red[0];
    __syncthreads();
    float ls = 0.f;
    for(int i=t;i<L_;i+=256){ float e = expf(al[i]-mx); al[i]=e; ls += e; }
    float tot = block_sum_256(ls, red);   // contains syncs -> al[] visible after
    float inv = 1.f/tot;
    for(int dd=t; dd<D_; dd+=256){
        float mu = 0.f, m2 = 0.f;
        for(int l=0;l<L_;l++){
            float a  = al[l];
            float hv = h[((size_t)(b*L_ + l))*D_ + dd];
            mu += a*hv;
            m2 += a*hv*hv;
        }
        mu *= inv; m2 *= inv;
        feat[b*1024 + dd]       = mu;
        feat[b*1024 + 512 + dd] = sqrtf(fmaxf(m2 - mu*mu, 1e-8f));
    }
}

// ---------------- final classifier head ----------------
__global__ void head_kernel(const float* __restrict__ feat, const float* __restrict__ W,
                            const float* __restrict__ bb, float* __restrict__ out){
    __shared__ float fs[1024];
    int b = blockIdx.x, t = threadIdx.x;   // 320 threads
    for(int i=t;i<1024;i+=320) fs[i] = feat[b*1024 + i];
    __syncthreads();
    int w = t >> 5, lane = t & 31;
    if(w < NC_){
        float s = 0.f;
        for(int k=lane;k<1024;k+=32) s += fs[k]*W[k*NC_ + w];
        #pragma unroll
        for(int o=16;o;o>>=1) s += __shfl_xor_sync(0xffffffffu, s, o);
        if(lane==0) out[b*NC_ + w] = s + bb[w];
    }
}

// ---------------- launch ----------------
template<typename T> static float* symaddr(T& s){
    void* p = nullptr;
    cudaGetSymbolAddress(&p, s);
    return (float*)p;
}

extern "C" void kernel_launch(void* const* d_in, const int* in_sizes, int n_in,
                              void* d_out, int out_size){
    const float* x        = (const float*)d_in[0];
    const float* patch_W  = (const float*)d_in[1];
    const float* patch_b  = (const float*)d_in[2];
    const float* patch_g  = (const float*)d_in[3];
    const float* patch_be = (const float*)d_in[4];
    const float* ln1_g    = (const float*)d_in[5];
    const float* ln1_b    = (const float*)d_in[6];
    const float* qW       = (const float*)d_in[7];
    const float* kW       = (const float*)d_in[8];
    const float* vW       = (const float*)d_in[9];
    const float* oW       = (const float*)d_in[10];
    const float* ob       = (const float*)d_in[11];
    const float* omega    = (const float*)d_in[12];
    const float* ln2_g    = (const float*)d_in[13];
    const float* ln2_b    = (const float*)d_in[14];
    const float* f1W      = (const float*)d_in[15];
    const float* f1b      = (const float*)d_in[16];
    const float* f2W      = (const float*)d_in[17];
    const float* f2b      = (const float*)d_in[18];
    const float* poolW1   = (const float*)d_in[19];
    const float* poolW2   = (const float*)d_in[20];
    const float* headW    = (const float*)d_in[21];
    const float* headb    = (const float*)d_in[22];
    float* out = (float*)d_out;

    float* tok   = symaddr(g_tok);
    float* h     = symaddr(g_h);
    float* x1    = symaddr(g_x1);
    float* tmp   = symaddr(g_tmp);
    float* Q     = symaddr(g_Q);
    float* K     = symaddr(g_K);
    float* V     = symaddr(g_V);
    float* Qf    = symaddr(g_Qf);
    float* Kf    = symaddr(g_Kf);
    float* KV    = symaddr(g_KV);
    float* Ksum  = symaddr(g_Ksum);
    float* attno = symaddr(g_attno);
    float* sc    = symaddr(g_scores);
    float* feat  = symaddr(g_feat);

    static const int PHI_SMEM  = (64*256 + 8*64)*4;              // 67584
    static const int ATTN_SMEM = (16384 + 256 + 8*1024)*4;       // 99328
    cudaFuncSetAttribute(phi_kernel,      cudaFuncAttributeMaxDynamicSharedMemorySize, PHI_SMEM);
    cudaFuncSetAttribute(attn_out_kernel, cudaFuncAttributeMaxDynamicSharedMemorySize, ATTN_SMEM);

    // 1. patchify
    patchify_kernel<<<(B_*C_*T_ + 255)/256, 256>>>(x);

    // 2. patch embed + LN
    gemm128<false><<<dim3((D_+127)/128, (R_+127)/128), 256>>>(tok, patch_W, patch_b, nullptr, tmp, R_, D_, C_*P_);
    ln_kernel<<<R_, 256>>>(tmp, patch_g, patch_be, h);

    for(int l=0;l<NL_;l++){
        const float* qWl = qW + (size_t)l*D_*D_;
        const float* kWl = kW + (size_t)l*D_*D_;
        const float* vWl = vW + (size_t)l*D_*D_;
        const float* oWl = oW + (size_t)l*D_*D_;
        const float* obl = ob + l*D_;
        const float* oml = omega + (size_t)l*DH_*M_;

        // attention branch
        ln_kernel<<<R_, 256>>>(h, ln1_g + l*D_, ln1_b + l*D_, x1);
        dim3 gq((D_+127)/128, (R_+127)/128);
        gemm128<false><<<gq, 256>>>(x1, qWl, nullptr, nullptr, Q, R_, D_, D_);
        gemm128<false><<<gq, 256>>>(x1, kWl, nullptr, nullptr, K, R_, D_, D_);
        gemm128<false><<<gq, 256>>>(x1, vWl, nullptr, nullptr, V, R_, D_, D_);
        phi_kernel<<<B_*H_, 256, PHI_SMEM>>>(Q, oml, Qf);
        phi_kernel<<<B_*H_, 256, PHI_SMEM>>>(K, oml, Kf);
        kv_kernel<<<B_*H_, 256>>>(Kf, V, KV, Ksum);
        attn_out_kernel<<<dim3(B_*H_, L_/32), 256, ATTN_SMEM>>>(Qf, KV, Ksum, attno);
        gemm128<false><<<gq, 256>>>(attno, oWl, obl, h, h, R_, D_, D_);  // h += attn@oW+ob

        // FFN branch
        ln_kernel<<<R_, 256>>>(h, ln2_g + l*D_, ln2_b + l*D_, x1);
        gemm128<true><<<dim3((FFN_+127)/128, (R_+127)/128), 256>>>(
            x1, f1W + (size_t)l*D_*FFN_, f1b + l*FFN_, nullptr, tmp, R_, FFN_, D_);
        gemm128<false><<<gq, 256>>>(
            tmp, f2W + (size_t)l*FFN_*D_, f2b + l*D_, h, h, R_, D_, FFN_);
    }

    // pooling + head
    gemm128<false><<<dim3(1, (R_+127)/128), 256>>>(h, poolW1, nullptr, nullptr, tmp, R_, HID_, D_);
    score2_kernel<<<(R_+255)/256, 256>>>(tmp, poolW2, sc);
    pool_kernel<<<B_, 256>>>(h, sc, feat);
    head_kernel<<<B_, 320>>>(feat, headW, headb, out);
}

// round 3
// speedup vs baseline: 2.0841x; 2.0841x over previous
#include <cuda_runtime.h>
#include <cuda_bf16.h>
#include <math.h>
#include <stdint.h>

// ---------------- problem dims ----------------
#define B_    32
#define C_    8
#define T_    20000
#define P_    25
#define D_    512
#define H_    8
#define M_    256
#define NL_   2
#define FFN_  1024
#define NC_   10
#define HID_  128
#define DH_   64
#define L_    800
#define R_    (B_*L_)        // 25600
#define KPATCH 224           // 200 padded to mult of 32

// ---------------- scratch (device globals; zero-initialized at load) ----------------
__device__ float g_h[R_*D_];
__device__ float g_tmp[R_*D_];             // patch pre-LN / pool T
__device__ float g_Q[R_*D_];
__device__ float g_K[R_*D_];
__device__ float g_V[R_*D_];
__device__ float g_Qf[B_*H_*L_*M_];
__device__ float g_Kf[B_*H_*L_*M_];
__device__ float g_KV[B_*H_*M_*DH_];
__device__ float g_Ksum[B_*H_*M_];
__device__ float g_scores[R_];
__device__ float g_feat[B_*2*D_];

__device__ __nv_bfloat16 g_tokb[R_*KPATCH];   // padded patch tokens (pad stays 0)
__device__ __nv_bfloat16 g_x1b[R_*D_];
__device__ __nv_bfloat16 g_tmpb[R_*FFN_];
__device__ __nv_bfloat16 g_attnob[R_*D_];
__device__ __nv_bfloat16 g_hb[R_*D_];
// transposed bf16 weights  WT[N][K]
__device__ __nv_bfloat16 g_qWT[NL_*D_*D_];
__device__ __nv_bfloat16 g_kWT[NL_*D_*D_];
__device__ __nv_bfloat16 g_vWT[NL_*D_*D_];
__device__ __nv_bfloat16 g_oWT[NL_*D_*D_];
__device__ __nv_bfloat16 g_f1WT[NL_*FFN_*D_];
__device__ __nv_bfloat16 g_f2WT[NL_*D_*FFN_];
__device__ __nv_bfloat16 g_patchWT[D_*KPATCH];
__device__ __nv_bfloat16 g_poolW1T[HID_*D_];

// ---------------- helpers ----------------
__device__ __forceinline__ float block_sum_256(float v, volatile float* red){
    int lane = threadIdx.x & 31, w = threadIdx.x >> 5;
    #pragma unroll
    for(int o=16;o;o>>=1) v += __shfl_xor_sync(0xffffffffu, v, o);
    if(lane==0) red[w] = v;
    __syncthreads();
    if(threadIdx.x < 32){
        float r = (threadIdx.x < 8) ? red[threadIdx.x] : 0.f;
        #pragma unroll
        for(int o=4;o;o>>=1) r += __shfl_xor_sync(0xffffffffu, r, o);
        if(threadIdx.x==0) red[0] = r;
    }
    __syncthreads();
    float out = red[0];
    __syncthreads();
    return out;
}

// ---------------- weight prep: W[K][N] fp32 -> WT[N][Kpad] bf16 ----------------
__global__ void wprep(const float* __restrict__ W, __nv_bfloat16* __restrict__ WT,
                      int K, int N, int Kpad){
    __shared__ float t[32][33];
    int k0 = blockIdx.y*32, n0 = blockIdx.x*32;
    int tx = threadIdx.x, ty = threadIdx.y;   // 32 x 8
    #pragma unroll
    for(int i=ty;i<32;i+=8){
        int k = k0+i, n = n0+tx;
        t[i][tx] = (k<K && n<N) ? W[(size_t)k*N+n] : 0.f;
    }
    __syncthreads();
    #pragma unroll
    for(int i=ty;i<32;i+=8){
        int n = n0+i, k = k0+tx;
        if(n<N && k<Kpad) WT[(size_t)n*Kpad+k] = __float2bfloat16(t[tx][i]);
    }
}

// ---------------- patchify to bf16 (padded K) ----------------
__global__ void patchify_kernel(const float* __restrict__ x){
    int idx = blockIdx.x*blockDim.x + threadIdx.x;
    if(idx >= B_*C_*T_) return;
    int t  = idx % T_;
    int bc = idx / T_;
    int c  = bc % C_;
    int b  = bc / C_;
    int l = t / P_, p = t % P_;
    g_tokb[(size_t)(b*L_ + l)*KPATCH + c*P_ + p] = __float2bfloat16(x[idx]);
}

// ---------------- fp32 -> bf16 convert ----------------
__global__ void f2bf_kernel(const float* __restrict__ in, __nv_bfloat16* __restrict__ out, int n2){
    int i = blockIdx.x*blockDim.x + threadIdx.x;
    if(i >= n2) return;
    float2 v = ((const float2*)in)[i];
    ((__nv_bfloat162*)out)[i] = __floats2bfloat162_rn(v.x, v.y);
}

// ---------------- LayerNorm over 512, templated output type ----------------
template<bool BF16OUT>
__global__ void __launch_bounds__(256) ln_kernel(const float* __restrict__ X,
        const float* __restrict__ g, const float* __restrict__ be, void* __restrict__ Yv){
    __shared__ float red[32];
    int row = blockIdx.x, t = threadIdx.x;
    const float* xr = X + (size_t)row*D_;
    float v0 = xr[t], v1 = xr[t+256];
    float mu = block_sum_256(v0+v1, red) * (1.f/512.f);
    float d0 = v0-mu, d1 = v1-mu;
    float var = block_sum_256(d0*d0 + d1*d1, red) * (1.f/512.f);
    float inv = rsqrtf(var + 1e-5f);
    float y0 = d0*inv*g[t]     + be[t];
    float y1 = d1*inv*g[t+256] + be[t+256];
    if(BF16OUT){
        __nv_bfloat16* yr = (__nv_bfloat16*)Yv + (size_t)row*D_;
        yr[t] = __float2bfloat16(y0); yr[t+256] = __float2bfloat16(y1);
    }else{
        float* yr = (float*)Yv + (size_t)row*D_;
        yr[t] = y0; yr[t+256] = y1;
    }
}

// ---------------- bf16 tensor-core GEMM: C = A[M,K] * WT[N,K]^T ----------------
__device__ __forceinline__ void mma_bf16(float* d, const uint32_t* a, const uint32_t* b){
    asm volatile("mma.sync.aligned.m16n8k16.row.col.f32.bf16.bf16.f32 "
        "{%0,%1,%2,%3}, {%4,%5,%6,%7}, {%8,%9}, {%0,%1,%2,%3};"
        : "+f"(d[0]), "+f"(d[1]), "+f"(d[2]), "+f"(d[3])
        : "r"(a[0]), "r"(a[1]), "r"(a[2]), "r"(a[3]), "r"(b[0]), "r"(b[1]));
}

#define KT 32
#define SA 40   // smem row stride in halves (conflict-free fragment loads)

template<bool GELU, bool BF16OUT>
__global__ void __launch_bounds__(256) gemm_bf16(
        const __nv_bfloat16* __restrict__ A, const __nv_bfloat16* __restrict__ BT,
        const float* __restrict__ bias, const float* __restrict__ res,
        void* __restrict__ Cv, int M, int N, int K)
{
    __shared__ __nv_bfloat16 As[2][128*SA];
    __shared__ __nv_bfloat16 Bs[2][128*SA];
    int tid = threadIdx.x;
    int row0 = blockIdx.y*128, col0 = blockIdx.x*128;
    int wid = tid>>5, lane = tid&31;
    int wm = (wid>>2)*64, wn = (wid&3)*32;
    int g = lane>>2, t2 = (lane&3)*2;

    float acc[4][4][4];
    #pragma unroll
    for(int mi=0;mi<4;mi++)
        #pragma unroll
        for(int ni=0;ni<4;ni++)
            #pragma unroll
            for(int q=0;q<4;q++) acc[mi][ni][q]=0.f;

    // tile loaders: 128 rows x 32 halves, 8-half chunks
    auto loadT = [&](const __nv_bfloat16* __restrict__ G, __nv_bfloat16* S, int k0){
        #pragma unroll
        for(int it=0; it<2; it++){
            int c = tid + it*256;
            int r = c>>2, kq = (c&3)*8;
            uint4 v = *(const uint4*)&G[(size_t)r*K + k0 + kq];
            *(uint4*)&S[r*SA + kq] = v;
        }
    };

    loadT(A + (size_t)row0*K, As[0], 0);
    loadT(BT + (size_t)col0*K, Bs[0], 0);
    __syncthreads();

    int nsteps = K/KT;
    for(int s=0; s<nsteps; s++){
        int buf = s&1;
        if(s+1 < nsteps){
            loadT(A + (size_t)row0*K, As[buf^1], (s+1)*KT);
            loadT(BT + (size_t)col0*K, Bs[buf^1], (s+1)*KT);
        }
        #pragma unroll
        for(int ks=0; ks<2; ks++){
            uint32_t af[4][4], bfr[4][2];
            #pragma unroll
            for(int mi=0;mi<4;mi++){
                const __nv_bfloat16* base = &As[buf][(wm + mi*16 + g)*SA + ks*16 + t2];
                af[mi][0] = *(const uint32_t*)base;
                af[mi][1] = *(const uint32_t*)(base + 8*SA);
                af[mi][2] = *(const uint32_t*)(base + 8);
                af[mi][3] = *(const uint32_t*)(base + 8*SA + 8);
            }
            #pragma unroll
            for(int ni=0;ni<4;ni++){
                const __nv_bfloat16* base = &Bs[buf][(wn + ni*8 + g)*SA + ks*16 + t2];
                bfr[ni][0] = *(const uint32_t*)base;
                bfr[ni][1] = *(const uint32_t*)(base + 8);
            }
            #pragma unroll
            for(int mi=0;mi<4;mi++)
                #pragma unroll
                for(int ni=0;ni<4;ni++)
                    mma_bf16(acc[mi][ni], af[mi], bfr[ni]);
        }
        __syncthreads();
    }

    // epilogue
    #pragma unroll
    for(int mi=0;mi<4;mi++){
        #pragma unroll
        for(int ni=0;ni<4;ni++){
            int r  = row0 + wm + mi*16 + g;
            int cc = col0 + wn + ni*8 + t2;
            #pragma unroll
            for(int half=0; half<2; half++){
                int rr = r + half*8;
                float v0 = acc[mi][ni][half*2+0];
                float v1 = acc[mi][ni][half*2+1];
                if(bias){ v0 += bias[cc]; v1 += bias[cc+1]; }
                if(GELU){
                    v0 = 0.5f*v0*(1.f + erff(v0*0.70710678118f));
                    v1 = 0.5f*v1*(1.f + erff(v1*0.70710678118f));
                }
                if(res){
                    v0 += res[(size_t)rr*N + cc];
                    v1 += res[(size_t)rr*N + cc + 1];
                }
                if(BF16OUT){
                    *(__nv_bfloat162*)((__nv_bfloat16*)Cv + (size_t)rr*N + cc)
                        = __floats2bfloat162_rn(v0, v1);
                }else{
                    float* C = (float*)Cv;
                    C[(size_t)rr*N + cc]     = v0;
                    C[(size_t)rr*N + cc + 1] = v1;
                }
            }
        }
    }
}

// ---------------- FAVOR+ feature map ----------------
__global__ void __launch_bounds__(256) phi_kernel(const float* __restrict__ X,
        const float* __restrict__ omg, float* __restrict__ F){
    extern __shared__ float sm[];
    float* om = sm;             // [64][256]
    float* xs = sm + 64*256;    // [8 warps][64]
    int bh = blockIdx.x;
    int b = bh >> 3, h = bh & 7;
    int tid = threadIdx.x, wid = tid >> 5, lane = tid & 31;
    for(int i=tid;i<64*256;i+=256) om[i] = omg[i];
    __syncthreads();
    const float sc = 0.3535533906f;   // 1 / 64^{1/4}
    float* xw = xs + wid*64;
    for(int l=wid; l<L_; l+=8){
        const float* xr = X + ((size_t)(b*L_ + l))*D_ + h*DH_;
        xw[lane]    = xr[lane]    * sc;
        xw[lane+32] = xr[lane+32] * sc;
        __syncwarp();
        float n2 = xw[lane]*xw[lane] + xw[lane+32]*xw[lane+32];
        #pragma unroll
        for(int o=16;o;o>>=1) n2 += __shfl_xor_sync(0xffffffffu, n2, o);
        n2 *= 0.5f;
        float acc[8];
        #pragma unroll
        for(int j=0;j<8;j++) acc[j]=0.f;
        #pragma unroll 8
        for(int d=0; d<64; d++){
            float xv = xw[d];
            #pragma unroll
            for(int j=0;j<8;j++) acc[j] += xv*om[d*256 + lane + 32*j];
        }
        float* o = F + ((size_t)bh*L_ + l)*M_;
        #pragma unroll
        for(int j=0;j<8;j++) o[lane + 32*j] = expf(acc[j]-n2)*0.0625f;
        __syncwarp();
    }
}

// ---------------- KV = Kf^T V, Ksum = sum_l Kf ----------------
__global__ void __launch_bounds__(256) kv_kernel(const float* __restrict__ Kf,
        const float* __restrict__ V, float* __restrict__ KV, float* __restrict__ Ks){
    __shared__ float Kfs[32*256];
    __shared__ float Vs[32*64];
    int bh = blockIdx.x;
    int b = bh >> 3, h = bh & 7;
    int t = threadIdx.x;
    float acc[64];
    #pragma unroll
    for(int d=0;d<64;d++) acc[d]=0.f;
    float ks = 0.f;
    for(int l0=0;l0<L_;l0+=32){
        __syncthreads();
        #pragma unroll 4
        for(int i=0;i<32;i++) Kfs[i*256+t] = Kf[((size_t)bh*L_ + l0+i)*M_ + t];
        #pragma unroll
        for(int i=0;i<8;i++){
            int idx = t + i*256;
            int l = idx >> 6, d = idx & 63;
            Vs[idx] = V[((size_t)(b*L_ + l0 + l))*D_ + h*DH_ + d];
        }
        __syncthreads();
        for(int l=0;l<32;l++){
            float kf = Kfs[l*256+t];
            ks += kf;
            #pragma unroll
            for(int q=0;q<16;q++){
                float4 v = *(const float4*)&Vs[l*64 + q*4];
                acc[q*4+0] += kf*v.x;
                acc[q*4+1] += kf*v.y;
                acc[q*4+2] += kf*v.z;
                acc[q*4+3] += kf*v.w;
            }
        }
    }
    float* o = KV + (size_t)bh*M_*DH_ + t*DH_;
    #pragma unroll
    for(int d=0;d<64;d++) o[d] = acc[d];
    Ks[bh*M_ + t] = ks;
}

// ---------------- out = (Qf @ KV) / max(Qf @ Ksum, 1e-6), bf16 out ----------------
__global__ void __launch_bounds__(256) attn_out_kernel(const float* __restrict__ Qf,
        const float* __restrict__ KV, const float* __restrict__ Ks,
        __nv_bfloat16* __restrict__ out){
    extern __shared__ float sm[];
    float* KVs = sm;              // [256][64]
    float* Kss = sm + 16384;      // [256]
    float* Qfs = sm + 16640;      // [8 warps][4 tok][256]
    int bh = blockIdx.x;
    int b = bh >> 3, h = bh & 7;
    int l0 = blockIdx.y*32;
    int tid = threadIdx.x, wid = tid >> 5, lane = tid & 31;
    const float* KVg = KV + (size_t)bh*M_*DH_;
    for(int i=tid;i<16384;i+=256) KVs[i] = KVg[i];
    Kss[tid] = Ks[bh*M_ + tid];
    __syncthreads();
    int lb = l0 + wid*4;
    float* Qw = Qfs + wid*1024;
    const float* Qg = Qf + ((size_t)bh*L_ + lb)*M_;
    for(int i=lane;i<1024;i+=32) Qw[i] = Qg[i];
    __syncwarp();
    float nr[4];
    #pragma unroll
    for(int tt=0;tt<4;tt++){
        float s2 = 0.f;
        #pragma unroll
        for(int j=0;j<8;j++){ int m = lane + 32*j; s2 += Qw[tt*256+m]*Kss[m]; }
        #pragma unroll
        for(int o=16;o;o>>=1) s2 += __shfl_xor_sync(0xffffffffu, s2, o);
        nr[tt] = 1.f/fmaxf(s2, 1e-6f);
    }
    float ax[4] = {0.f,0.f,0.f,0.f};
    float ay[4] = {0.f,0.f,0.f,0.f};
    int d2 = lane*2;
    #pragma unroll 4
    for(int m=0;m<256;m++){
        float2 kv = *(const float2*)&KVs[m*64 + d2];
        #pragma unroll
        for(int tt=0;tt<4;tt++){
            float q = Qw[tt*256+m];
            ax[tt] += q*kv.x;
            ay[tt] += q*kv.y;
        }
    }
    #pragma unroll
    for(int tt=0;tt<4;tt++){
        int l = lb + tt;
        __nv_bfloat16* o = out + ((size_t)(b*L_ + l))*D_ + h*DH_ + d2;
        *(__nv_bfloat162*)o = __floats2bfloat162_rn(ax[tt]*nr[tt], ay[tt]*nr[tt]);
    }
}

// ---------------- pooling scores ----------------
__global__ void score2_kernel(const float* __restrict__ Tt, const float* __restrict__ W2,
                              float* __restrict__ sc){
    int r = blockIdx.x*blockDim.x + threadIdx.x;
    if(r >= R_) return;
    const float* tr = Tt + (size_t)r*HID_;
    float s = 0.f;
    #pragma unroll 8
    for(int j=0;j<HID_;j++) s += tanhf(tr[j]) * __ldg(&W2[j]);
    sc[r] = s;
}

// ---------------- softmax over L + attentive stats ----------------
__global__ void __launch_bounds__(256) pool_kernel(const float* __restrict__ h,
        const float* __restrict__ sc, float* __restrict__ feat){
    __shared__ float al[L_];
    __shared__ float red[32];
    int b = blockIdx.x, t = threadIdx.x;
    float lmax = -1e30f;
    for(int i=t;i<L_;i+=256){ float v = sc[b*L_+i]; al[i]=v; lmax=fmaxf(lmax,v); }
    #pragma unroll
    for(int o=16;o;o>>=1) lmax = fmaxf(lmax, __shfl_xor_sync(0xffffffffu, lmax, o));
    if((t&31)==0) red[t>>5] = lmax;
    __syncthreads();
    if(t < 32){
        float r = (t < 8) ? red[t] : -1e30f;
        #pragma unroll
        for(int o=4;o;o>>=1) r = fmaxf(r, __shfl_xor_sync(0xffffffffu, r, o));
        if(t==0) red[0] = r;
    }
    __syncthreads();
    float mx = red[0];
    __syncthreads();
    float ls = 0.f;
    for(int i=t;i<L_;i+=256){ float e = expf(al[i]-mx); al[i]=e; ls += e; }
    float tot = block_sum_256(ls, red);
    float inv = 1.f/tot;
    for(int dd=t; dd<D_; dd+=256){
        float mu = 0.f, m2 = 0.f;
        for(int l=0;l<L_;l++){
            float a  = al[l];
            float hv = h[((size_t)(b*L_ + l))*D_ + dd];
            mu += a*hv;
            m2 += a*hv*hv;
        }
        mu *= inv; m2 *= inv;
        feat[b*1024 + dd]       = mu;
        feat[b*1024 + 512 + dd] = sqrtf(fmaxf(m2 - mu*mu, 1e-8f));
    }
}

// ---------------- final classifier head ----------------
__global__ void head_kernel(const float* __restrict__ feat, const float* __restrict__ W,
                            const float* __restrict__ bb, float* __restrict__ out){
    __shared__ float fs[1024];
    int b = blockIdx.x, t = threadIdx.x;   // 320 threads
    for(int i=t;i<1024;i+=320) fs[i] = feat[b*1024 + i];
    __syncthreads();
    int w = t >> 5, lane = t & 31;
    if(w < NC_){
        float s = 0.f;
        for(int k=lane;k<1024;k+=32) s += fs[k]*W[k*NC_ + w];
        #pragma unroll
        for(int o=16;o;o>>=1) s += __shfl_xor_sync(0xffffffffu, s, o);
        if(lane==0) out[b*NC_ + w] = s + bb[w];
    }
}

// ---------------- launch ----------------
template<typename T> static void* symaddr_(T& s){
    void* p = nullptr;
    cudaGetSymbolAddress(&p, s);
    return p;
}

extern "C" void kernel_launch(void* const* d_in, const int* in_sizes, int n_in,
                              void* d_out, int out_size){
    const float* x        = (const float*)d_in[0];
    const float* patch_W  = (const float*)d_in[1];
    const float* patch_b  = (const float*)d_in[2];
    const float* patch_g  = (const float*)d_in[3];
    const float* patch_be = (const float*)d_in[4];
    const float* ln1_g    = (const float*)d_in[5];
    const float* ln1_b    = (const float*)d_in[6];
    const float* qW       = (const float*)d_in[7];
    const float* kW       = (const float*)d_in[8];
    const float* vW       = (const float*)d_in[9];
    const float* oW       = (const float*)d_in[10];
    const float* ob       = (const float*)d_in[11];
    const float* omega    = (const float*)d_in[12];
    const float* ln2_g    = (const float*)d_in[13];
    const float* ln2_b    = (const float*)d_in[14];
    const float* f1W      = (const float*)d_in[15];
    const float* f1b      = (const float*)d_in[16];
    const float* f2W      = (const float*)d_in[17];
    const float* f2b      = (const float*)d_in[18];
    const float* poolW1   = (const float*)d_in[19];
    const float* poolW2   = (const float*)d_in[20];
    const float* headW    = (const float*)d_in[21];
    const float* headb    = (const float*)d_in[22];
    float* out = (float*)d_out;

    float* h     = (float*)symaddr_(g_h);
    float* tmp   = (float*)symaddr_(g_tmp);
    float* Q     = (float*)symaddr_(g_Q);
    float* K     = (float*)symaddr_(g_K);
    float* V     = (float*)symaddr_(g_V);
    float* Qf    = (float*)symaddr_(g_Qf);
    float* Kf    = (float*)symaddr_(g_Kf);
    float* KV    = (float*)symaddr_(g_KV);
    float* Ksum  = (float*)symaddr_(g_Ksum);
    float* sc    = (float*)symaddr_(g_scores);
    float* feat  = (float*)symaddr_(g_feat);
    __nv_bfloat16* tokb   = (__nv_bfloat16*)symaddr_(g_tokb);
    __nv_bfloat16* x1b    = (__nv_bfloat16*)symaddr_(g_x1b);
    __nv_bfloat16* tmpb   = (__nv_bfloat16*)symaddr_(g_tmpb);
    __nv_bfloat16* attnob = (__nv_bfloat16*)symaddr_(g_attnob);
    __nv_bfloat16* hb     = (__nv_bfloat16*)symaddr_(g_hb);
    __nv_bfloat16* qWT    = (__nv_bfloat16*)symaddr_(g_qWT);
    __nv_bfloat16* kWT    = (__nv_bfloat16*)symaddr_(g_kWT);
    __nv_bfloat16* vWT    = (__nv_bfloat16*)symaddr_(g_vWT);
    __nv_bfloat16* oWT    = (__nv_bfloat16*)symaddr_(g_oWT);
    __nv_bfloat16* f1WT   = (__nv_bfloat16*)symaddr_(g_f1WT);
    __nv_bfloat16* f2WT   = (__nv_bfloat16*)symaddr_(g_f2WT);
    __nv_bfloat16* patchWT= (__nv_bfloat16*)symaddr_(g_patchWT);
    __nv_bfloat16* poolW1T= (__nv_bfloat16*)symaddr_(g_poolW1T);

    static const int PHI_SMEM  = (64*256 + 8*64)*4;
    static const int ATTN_SMEM = (16384 + 256 + 8*1024)*4;
    cudaFuncSetAttribute(phi_kernel,      cudaFuncAttributeMaxDynamicSharedMemorySize, PHI_SMEM);
    cudaFuncSetAttribute(attn_out_kernel, cudaFuncAttributeMaxDynamicSharedMemorySize, ATTN_SMEM);

    // weight prep (bf16 transpose)
    dim3 wb(32,8);
    auto tg = [](int N, int Kpad){ return dim3((N+31)/32, (Kpad+31)/32); };
    for(int l=0;l<NL_;l++){
        wprep<<<tg(D_,D_), wb>>>(qW + (size_t)l*D_*D_, qWT + (size_t)l*D_*D_, D_, D_, D_);
        wprep<<<tg(D_,D_), wb>>>(kW + (size_t)l*D_*D_, kWT + (size_t)l*D_*D_, D_, D_, D_);
        wprep<<<tg(D_,D_), wb>>>(vW + (size_t)l*D_*D_, vWT + (size_t)l*D_*D_, D_, D_, D_);
        wprep<<<tg(D_,D_), wb>>>(oW + (size_t)l*D_*D_, oWT + (size_t)l*D_*D_, D_, D_, D_);
        wprep<<<tg(FFN_,D_), wb>>>(f1W + (size_t)l*D_*FFN_, f1WT + (size_t)l*FFN_*D_, D_, FFN_, D_);
        wprep<<<tg(D_,FFN_), wb>>>(f2W + (size_t)l*FFN_*D_, f2WT + (size_t)l*D_*FFN_, FFN_, D_, FFN_);
    }
    wprep<<<tg(D_,KPATCH), wb>>>(patch_W, patchWT, C_*P_, D_, KPATCH);
    wprep<<<tg(HID_,D_), wb>>>(poolW1, poolW1T, D_, HID_, D_);

    // patchify + patch embed + LN
    patchify_kernel<<<(B_*C_*T_ + 255)/256, 256>>>(x);
    gemm_bf16<false,false><<<dim3(D_/128, R_/128), 256>>>(tokb, patchWT, patch_b, nullptr, tmp, R_, D_, KPATCH);
    ln_kernel<false><<<R_, 256>>>(tmp, patch_g, patch_be, h);

    for(int l=0;l<NL_;l++){
        const float* obl = ob + l*D_;
        const float* oml = omega + (size_t)l*DH_*M_;
        dim3 gq(D_/128, R_/128);

        // attention branch
        ln_kernel<true><<<R_, 256>>>(h, ln1_g + l*D_, ln1_b + l*D_, x1b);
        gemm_bf16<false,false><<<gq, 256>>>(x1b, qWT + (size_t)l*D_*D_, nullptr, nullptr, Q, R_, D_, D_);
        gemm_bf16<false,false><<<gq, 256>>>(x1b, kWT + (size_t)l*D_*D_, nullptr, nullptr, K, R_, D_, D_);
        gemm_bf16<false,false><<<gq, 256>>>(x1b, vWT + (size_t)l*D_*D_, nullptr, nullptr, V, R_, D_, D_);
        phi_kernel<<<B_*H_, 256, PHI_SMEM>>>(Q, oml, Qf);
        phi_kernel<<<B_*H_, 256, PHI_SMEM>>>(K, oml, Kf);
        kv_kernel<<<B_*H_, 256>>>(Kf, V, KV, Ksum);
        attn_out_kernel<<<dim3(B_*H_, L_/32), 256, ATTN_SMEM>>>(Qf, KV, Ksum, attnob);
        gemm_bf16<false,false><<<gq, 256>>>(attnob, oWT + (size_t)l*D_*D_, obl, h, h, R_, D_, D_);

        // FFN branch
        ln_kernel<true><<<R_, 256>>>(h, ln2_g + l*D_, ln2_b + l*D_, x1b);
        gemm_bf16<true,true><<<dim3(FFN_/128, R_/128), 256>>>(
            x1b, f1WT + (size_t)l*FFN_*D_, f1b + l*FFN_, nullptr, tmpb, R_, FFN_, D_);
        gemm_bf16<false,false><<<gq, 256>>>(
            tmpb, f2WT + (size_t)l*D_*FFN_, f2b + l*D_, h, h, R_, D_, FFN_);
    }

    // pooling + head
    f2bf_kernel<<<(R_*D_/2 + 255)/256, 256>>>(h, hb, R_*D_/2);
    gemm_bf16<false,false><<<dim3(HID_/128, R_/128), 256>>>(hb, poolW1T, nullptr, nullptr, tmp, R_, HID_, D_);
    score2_kernel<<<(R_+255)/256, 256>>>(tmp, poolW2, sc);
    pool_kernel<<<B_, 256>>>(h, sc, feat);
    head_kernel<<<B_, 320>>>(feat, headW, headb, out);
}

// round 6
// speedup vs baseline: 2.7126x; 1.3016x over previous
#include <cuda_runtime.h>
#include <cuda_bf16.h>
#include <math.h>
#include <stdint.h>

// ---------------- problem dims ----------------
#define B_    32
#define C_    8
#define T_    20000
#define P_    25
#define D_    512
#define H_    8
#define M_    256
#define NL_   2
#define FFN_  1024
#define NC_   10
#define HID_  128
#define DH_   64
#define L_    800
#define R_    (B_*L_)        // 25600
#define KPATCH 224
#define LP_   896            // L padded to 7*128 (pad rows stay zero)

// ---------------- scratch (device globals; zero-initialized at load) ----------------
__device__ float g_h[R_*D_];
__device__ float g_tmp[R_*D_];             // patch pre-LN / pool T
__device__ float g_Ksum[B_*H_*M_];
__device__ float g_norm[B_*H_*LP_];
__device__ float g_scores[R_];
__device__ float g_alpha[R_];
__device__ float g_feat[B_*2*D_];

__device__ __nv_bfloat16 g_tokb[R_*KPATCH];
__device__ __nv_bfloat16 g_x1b[R_*D_];
__device__ __nv_bfloat16 g_QKV[R_*3*D_];
__device__ __nv_bfloat16 g_tmpb[R_*FFN_];
__device__ __nv_bfloat16 g_attnob[R_*D_];
__device__ __nv_bfloat16 g_hb[R_*D_];
__device__ __nv_bfloat16 g_Qf[(size_t)B_*H_*LP_*M_];
__device__ __nv_bfloat16 g_Kf[(size_t)B_*H_*LP_*M_];
__device__ __nv_bfloat16 g_KVT[B_*H_*DH_*M_];
// transposed bf16 weights WT[N][K]
__device__ __nv_bfloat16 g_qkvWT[NL_*3*D_*D_];
__device__ __nv_bfloat16 g_oWT[NL_*D_*D_];
__device__ __nv_bfloat16 g_f1WT[NL_*FFN_*D_];
__device__ __nv_bfloat16 g_f2WT[NL_*D_*FFN_];
__device__ __nv_bfloat16 g_patchWT[D_*KPATCH];
__device__ __nv_bfloat16 g_poolW1T[HID_*D_];

// ---------------- batched weight prep ----------------
struct WDesc { const float* src; __nv_bfloat16* dst; int K, N, Kpad; };
struct WAll  { WDesc d[14]; };

__global__ void wprep_all(WAll wa){
    WDesc w = wa.d[blockIdx.z];
    int k0 = blockIdx.y*32, n0 = blockIdx.x*32;
    if(k0 >= w.Kpad || n0 >= w.N) return;
    __shared__ float t[32][33];
    int tx = threadIdx.x, ty = threadIdx.y;   // 32 x 8
    #pragma unroll
    for(int i=ty;i<32;i+=8){
        int k = k0+i, n = n0+tx;
        t[i][tx] = (k<w.K && n<w.N) ? w.src[(size_t)k*w.N+n] : 0.f;
    }
    __syncthreads();
    #pragma unroll
    for(int i=ty;i<32;i+=8){
        int n = n0+i, k = k0+tx;
        if(n<w.N && k<w.Kpad) w.dst[(size_t)n*w.Kpad+k] = __float2bfloat16(t[tx][i]);
    }
}

// ---------------- patchify to bf16 (padded K) ----------------
__global__ void patchify_kernel(const float* __restrict__ x){
    int idx = blockIdx.x*blockDim.x + threadIdx.x;
    if(idx >= B_*C_*T_) return;
    int t  = idx % T_;
    int bc = idx / T_;
    int c  = bc % C_;
    int b  = bc / C_;
    int l = t / P_, p = t % P_;
    g_tokb[(size_t)(b*L_ + l)*KPATCH + c*P_ + p] = __float2bfloat16(x[idx]);
}

// ---------------- fp32 -> bf16 convert ----------------
__global__ void f2bf_kernel(const float* __restrict__ in, __nv_bfloat16* __restrict__ out, int n2){
    int i = blockIdx.x*blockDim.x + threadIdx.x;
    if(i >= n2) return;
    float2 v = ((const float2*)in)[i];
    ((__nv_bfloat162*)out)[i] = __floats2bfloat162_rn(v.x, v.y);
}

// ---------------- LayerNorm: 4 rows/block, float4, single pass ----------------
template<bool BF16OUT>
__global__ void __launch_bounds__(256) ln_kernel(const float* __restrict__ X,
        const float* __restrict__ gg, const float* __restrict__ be, void* __restrict__ Yv){
    __shared__ float2 red[8];
    int t = threadIdx.x;
    int row = blockIdx.x*4 + (t>>6);
    int c = t & 63;
    const float4* xr = (const float4*)(X + (size_t)row*D_);
    float4 v0 = xr[c*2], v1 = xr[c*2+1];
    float s = v0.x+v0.y+v0.z+v0.w + v1.x+v1.y+v1.z+v1.w;
    float q = v0.x*v0.x+v0.y*v0.y+v0.z*v0.z+v0.w*v0.w
            + v1.x*v1.x+v1.y*v1.y+v1.z*v1.z+v1.w*v1.w;
    #pragma unroll
    for(int o=16;o;o>>=1){
        s += __shfl_xor_sync(0xffffffffu, s, o);
        q += __shfl_xor_sync(0xffffffffu, q, o);
    }
    int w = t>>5;
    if((t&31)==0) red[w] = make_float2(s, q);
    __syncthreads();
    float2 A = red[w], Bp = red[w^1];
    float mu  = (A.x + Bp.x) * (1.f/512.f);
    float msq = (A.y + Bp.y) * (1.f/512.f);
    float inv = rsqrtf(fmaxf(msq - mu*mu, 0.f) + 1e-5f);
    float4 g0 = ((const float4*)gg)[c*2], g1 = ((const float4*)gg)[c*2+1];
    float4 b0 = ((const float4*)be)[c*2], b1 = ((const float4*)be)[c*2+1];
    float y[8];
    y[0]=(v0.x-mu)*inv*g0.x+b0.x; y[1]=(v0.y-mu)*inv*g0.y+b0.y;
    y[2]=(v0.z-mu)*inv*g0.z+b0.z; y[3]=(v0.w-mu)*inv*g0.w+b0.w;
    y[4]=(v1.x-mu)*inv*g1.x+b1.x; y[5]=(v1.y-mu)*inv*g1.y+b1.y;
    y[6]=(v1.z-mu)*inv*g1.z+b1.z; y[7]=(v1.w-mu)*inv*g1.w+b1.w;
    if(BF16OUT){
        __nv_bfloat162 p[4];
        #pragma unroll
        for(int i=0;i<4;i++) p[i] = __floats2bfloat162_rn(y[2*i], y[2*i+1]);
        ((uint4*)((__nv_bfloat16*)Yv + (size_t)row*D_))[c] = *(uint4*)p;
    }else{
        float* yr = (float*)Yv + (size_t)row*D_;
        ((float4*)yr)[c*2]   = make_float4(y[0],y[1],y[2],y[3]);
        ((float4*)yr)[c*2+1] = make_float4(y[4],y[5],y[6],y[7]);
    }
}

// ---------------- mma primitive ----------------
__device__ __forceinline__ void mma_bf16(float* d, const uint32_t* a, const uint32_t* b){
    asm volatile("mma.sync.aligned.m16n8k16.row.col.f32.bf16.bf16.f32 "
        "{%0,%1,%2,%3}, {%4,%5,%6,%7}, {%8,%9}, {%0,%1,%2,%3};"
        : "+f"(d[0]), "+f"(d[1]), "+f"(d[2]), "+f"(d[3])
        : "r"(a[0]), "r"(a[1]), "r"(a[2]), "r"(a[3]), "r"(b[0]), "r"(b[1]));
}

// ---------------- bf16 tensor-core GEMM: C = A[M,K] * WT[N,K]^T ----------------
#define KT 32
#define SA 40

template<bool GELU, bool BF16OUT>
__global__ void __launch_bounds__(256) gemm_bf16(
        const __nv_bfloat16* __restrict__ A, const __nv_bfloat16* __restrict__ BT,
        const float* __restrict__ bias, const float* __restrict__ res,
        void* __restrict__ Cv, int M, int N, int K)
{
    __shared__ __nv_bfloat16 As[2][128*SA];
    __shared__ __nv_bfloat16 Bs[2][128*SA];
    int tid = threadIdx.x;
    int row0 = blockIdx.y*128, col0 = blockIdx.x*128;
    int wid = tid>>5, lane = tid&31;
    int wm = (wid>>2)*64, wn = (wid&3)*32;
    int g = lane>>2, t2 = (lane&3)*2;

    float acc[4][4][4];
    #pragma unroll
    for(int mi=0;mi<4;mi++)
        #pragma unroll
        for(int ni=0;ni<4;ni++)
            #pragma unroll
            for(int q=0;q<4;q++) acc[mi][ni][q]=0.f;

    auto loadT = [&](const __nv_bfloat16* __restrict__ G, __nv_bfloat16* S, int k0){
        #pragma unroll
        for(int it=0; it<2; it++){
            int c = tid + it*256;
            int r = c>>2, kq = (c&3)*8;
            uint4 v = *(const uint4*)&G[(size_t)r*K + k0 + kq];
            *(uint4*)&S[r*SA + kq] = v;
        }
    };

    loadT(A + (size_t)row0*K, As[0], 0);
    loadT(BT + (size_t)col0*K, Bs[0], 0);
    __syncthreads();

    int nsteps = K/KT;
    for(int s=0; s<nsteps; s++){
        int buf = s&1;
        if(s+1 < nsteps){
            loadT(A + (size_t)row0*K, As[buf^1], (s+1)*KT);
            loadT(BT + (size_t)col0*K, Bs[buf^1], (s+1)*KT);
        }
        #pragma unroll
        for(int ks=0; ks<2; ks++){
            uint32_t af[4][4], bfr[4][2];
            #pragma unroll
            for(int mi=0;mi<4;mi++){
                const __nv_bfloat16* base = &As[buf][(wm + mi*16 + g)*SA + ks*16 + t2];
                af[mi][0] = *(const uint32_t*)base;
                af[mi][1] = *(const uint32_t*)(base + 8*SA);
                af[mi][2] = *(const uint32_t*)(base + 8);
                af[mi][3] = *(const uint32_t*)(base + 8*SA + 8);
            }
            #pragma unroll
            for(int ni=0;ni<4;ni++){
                const __nv_bfloat16* base = &Bs[buf][(wn + ni*8 + g)*SA + ks*16 + t2];
                bfr[ni][0] = *(const uint32_t*)base;
                bfr[ni][1] = *(const uint32_t*)(base + 8);
            }
            #pragma unroll
            for(int mi=0;mi<4;mi++)
                #pragma unroll
                for(int ni=0;ni<4;ni++)
                    mma_bf16(acc[mi][ni], af[mi], bfr[ni]);
        }
        __syncthreads();
    }

    #pragma unroll
    for(int mi=0;mi<4;mi++){
        #pragma unroll
        for(int ni=0;ni<4;ni++){
            int r  = row0 + wm + mi*16 + g;
            int cc = col0 + wn + ni*8 + t2;
            #pragma unroll
            for(int half=0; half<2; half++){
                int rr = r + half*8;
                float v0 = acc[mi][ni][half*2+0];
                float v1 = acc[mi][ni][half*2+1];
                if(bias){ v0 += bias[cc]; v1 += bias[cc+1]; }
                if(GELU){
                    v0 = 0.5f*v0*(1.f + erff(v0*0.70710678118f));
                    v1 = 0.5f*v1*(1.f + erff(v1*0.70710678118f));
                }
                if(res){
                    v0 += res[(size_t)rr*N + cc];
                    v1 += res[(size_t)rr*N + cc + 1];
                }
                if(BF16OUT){
                    *(__nv_bfloat162*)((__nv_bfloat16*)Cv + (size_t)rr*N + cc)
                        = __floats2bfloat162_rn(v0, v1);
                }else{
                    float* C = (float*)Cv;
                    C[(size_t)rr*N + cc]     = v0;
                    C[(size_t)rr*N + cc + 1] = v1;
                }
            }
        }
    }
}

// ---------------- FAVOR+ feature map (bf16 in/out, optional fused normalizer) ----------------
template<bool NORM>
__global__ void __launch_bounds__(256) phi_kernel(const __nv_bfloat16* __restrict__ X,
        const float* __restrict__ omg, __nv_bfloat16* __restrict__ F,
        const float* __restrict__ Ksum, float* __restrict__ normOut){
    extern __shared__ float sm[];
    float* om = sm;                 // [64][256]
    float* xs = sm + 64*256;        // [8 warps][64]
    float* ks = sm + 64*256 + 8*64; // [256]
    int bh = blockIdx.x;
    int b = bh >> 3, h = bh & 7;
    int tid = threadIdx.x, wid = tid >> 5, lane = tid & 31;
    for(int i=tid;i<64*256;i+=256) om[i] = omg[i];
    if(NORM) ks[tid] = Ksum[bh*M_ + tid];
    __syncthreads();
    const float sc = 0.3535533906f;   // 1 / 64^{1/4}
    float* xw = xs + wid*64;
    for(int l=wid; l<L_; l+=8){
        const __nv_bfloat16* xr = X + ((size_t)(b*L_ + l))*(3*D_) + h*DH_;
        xw[lane]    = __bfloat162float(xr[lane])    * sc;
        xw[lane+32] = __bfloat162float(xr[lane+32]) * sc;
        __syncwarp();
        float n2 = xw[lane]*xw[lane] + xw[lane+32]*xw[lane+32];
        #pragma unroll
        for(int o=16;o;o>>=1) n2 += __shfl_xor_sync(0xffffffffu, n2, o);
        n2 *= 0.5f;
        float acc[8];
        #pragma unroll
        for(int j=0;j<8;j++) acc[j]=0.f;
        #pragma unroll 8
        for(int d=0; d<64; d++){
            float xv = xw[d];
            #pragma unroll
            for(int j=0;j<8;j++) acc[j] += xv*om[d*256 + lane + 32*j];
        }
        __nv_bfloat16* o = F + ((size_t)bh*LP_ + l)*M_;
        float nsum = 0.f;
        #pragma unroll
        for(int j=0;j<8;j++){
            float e = __expf(acc[j]-n2)*0.0625f;
            __nv_bfloat16 eb = __float2bfloat16(e);
            o[lane + 32*j] = eb;
            if(NORM) nsum += __bfloat162float(eb) * ks[lane + 32*j];
        }
        if(NORM){
            #pragma unroll
            for(int of=16;of;of>>=1) nsum += __shfl_xor_sync(0xffffffffu, nsum, of);
            if(lane==0) normOut[(size_t)bh*LP_ + l] = nsum;
        }
        __syncwarp();
    }
}

// ---------------- KV^T = (Kf^T V)^T via tensor cores; also Ksum ----------------
__global__ void __launch_bounds__(256) kv_tc(const __nv_bfloat16* __restrict__ Kf,
        const __nv_bfloat16* __restrict__ QKV,
        __nv_bfloat16* __restrict__ KVT, float* __restrict__ Ksum){
    __shared__ __nv_bfloat16 KfT[256*40];
    __shared__ __nv_bfloat16 VT[64*40];
    int bh = blockIdx.x;
    int b = bh>>3, h = bh&7;
    int t = threadIdx.x, wid = t>>5, lane = t&31;
    int wm = (wid>>1)*64, wn = (wid&1)*32;
    int g = lane>>2, t2 = (lane&3)*2;
    float acc[4][4][4];
    #pragma unroll
    for(int mi=0;mi<4;mi++)
        #pragma unroll
        for(int ni=0;ni<4;ni++)
            #pragma unroll
            for(int q=0;q<4;q++) acc[mi][ni][q]=0.f;
    float kssum = 0.f;

    const __nv_bfloat16* Kfb = Kf + (size_t)bh*LP_*M_;
    const __nv_bfloat16* Vb  = QKV + ((size_t)b*L_)*(3*D_) + 2*D_ + h*DH_;
    int lrow = t>>3, lj = t&7;

    for(int l0=0;l0<L_;l0+=32){
        // load Kf tile [32 l][256 m] -> KfT[m][l]
        #pragma unroll
        for(int c=0;c<4;c++){
            int m0 = (lj + 8*c)*8;
            uint4 v = *(const uint4*)&Kfb[(size_t)(l0+lrow)*M_ + m0];
            const __nv_bfloat16* pv = (const __nv_bfloat16*)&v;
            #pragma unroll
            for(int i=0;i<8;i++) KfT[(m0+i)*40 + lrow] = pv[i];
        }
        // load V tile [32 l][64 d] -> VT[d][l]
        {
            int d0 = lj*8;
            uint4 v = *(const uint4*)&Vb[(size_t)(l0+lrow)*(3*D_) + d0];
            const __nv_bfloat16* pv = (const __nv_bfloat16*)&v;
            #pragma unroll
            for(int i=0;i<8;i++) VT[(d0+i)*40 + lrow] = pv[i];
        }
        __syncthreads();
        // Ksum partial: row m=t over 32 l
        #pragma unroll
        for(int u=0;u<16;u++){
            __nv_bfloat162 p = *(const __nv_bfloat162*)&KfT[t*40 + 2*u];
            float2 f = __bfloat1622float2(p);
            kssum += f.x + f.y;
        }
        // mma: two k-steps of 16
        #pragma unroll
        for(int kk=0;kk<2;kk++){
            int k0 = kk*16;
            uint32_t a[4][4], bb[4][2];
            #pragma unroll
            for(int mi=0;mi<4;mi++){
                int row = wm + mi*16 + g;
                a[mi][0] = *(const uint32_t*)&KfT[row*40 + k0+t2];
                a[mi][1] = *(const uint32_t*)&KfT[(row+8)*40 + k0+t2];
                a[mi][2] = *(const uint32_t*)&KfT[row*40 + k0+t2+8];
                a[mi][3] = *(const uint32_t*)&KfT[(row+8)*40 + k0+t2+8];
            }
            #pragma unroll
            for(int ni=0;ni<4;ni++){
                int n = wn + ni*8 + g;
                bb[ni][0] = *(const uint32_t*)&VT[n*40 + k0+t2];
                bb[ni][1] = *(const uint32_t*)&VT[n*40 + k0+t2+8];
            }
            #pragma unroll
            for(int mi=0;mi<4;mi++)
                #pragma unroll
                for(int ni=0;ni<4;ni++)
                    mma_bf16(acc[mi][ni], a[mi], bb[ni]);
        }
        __syncthreads();
    }
    // store KVT[d][m] bf16
    __nv_bfloat16* kvt = KVT + (size_t)bh*DH_*M_;
    #pragma unroll
    for(int mi=0;mi<4;mi++){
        #pragma unroll
        for(int ni=0;ni<4;ni++){
            int m = wm + mi*16 + g;
            int d = wn + ni*8 + t2;
            kvt[(size_t)d*M_ + m]       = __float2bfloat16(acc[mi][ni][0]);
            kvt[(size_t)(d+1)*M_ + m]   = __float2bfloat16(acc[mi][ni][1]);
            kvt[(size_t)d*M_ + m+8]     = __float2bfloat16(acc[mi][ni][2]);
            kvt[(size_t)(d+1)*M_ + m+8] = __float2bfloat16(acc[mi][ni][3]);
        }
    }
    Ksum[bh*M_ + t] = kssum;
}

// ---------------- attn out = (Qf @ KV) * (1/norm) via tensor cores ----------------
__global__ void __launch_bounds__(256) attn_tc(const __nv_bfloat16* __restrict__ Qf,
        const __nv_bfloat16* __restrict__ KVT, const float* __restrict__ norm,
        __nv_bfloat16* __restrict__ out){
    extern __shared__ __nv_bfloat16 smb[];
    __nv_bfloat16* KVs = smb;            // [64][264]
    __nv_bfloat16* Qs  = smb + 64*264;   // [128][72]
    int bh = blockIdx.x, lt = blockIdx.y;
    int b = bh>>3, h = bh&7;
    int t = threadIdx.x, wid = t>>5, lane = t&31;
    int g = lane>>2, t2 = (lane&3)*2;

    // load KVT [64][256] -> KVs padded
    {
        const __nv_bfloat16* kvt = KVT + (size_t)bh*DH_*M_;
        int r = t>>2, s = t&3;
        #pragma unroll
        for(int i=0;i<8;i++){
            int q = s*8 + i;
            uint4 v = *(const uint4*)&kvt[(size_t)r*M_ + q*8];
            *(uint4*)&KVs[r*264 + q*8] = v;
        }
    }
    float acc[8][4];
    #pragma unroll
    for(int ni=0;ni<8;ni++)
        #pragma unroll
        for(int q=0;q<4;q++) acc[ni][q]=0.f;

    int l0 = lt*128;
    const __nv_bfloat16* Qb = Qf + ((size_t)bh*LP_ + l0)*M_;
    for(int kc=0;kc<4;kc++){
        __syncthreads();
        // load Qf chunk [128][64] -> Qs
        {
            int r = t>>1, s = t&1;
            #pragma unroll
            for(int i=0;i<4;i++){
                int q = s*4 + i;
                uint4 v = *(const uint4*)&Qb[(size_t)r*M_ + kc*64 + q*8];
                *(uint4*)&Qs[r*72 + q*8] = v;
            }
        }
        __syncthreads();
        #pragma unroll
        for(int kk=0;kk<4;kk++){
            int k0 = kk*16;
            uint32_t a[4];
            int row = wid*16 + g;
            a[0] = *(const uint32_t*)&Qs[row*72 + k0+t2];
            a[1] = *(const uint32_t*)&Qs[(row+8)*72 + k0+t2];
            a[2] = *(const uint32_t*)&Qs[row*72 + k0+t2+8];
            a[3] = *(const uint32_t*)&Qs[(row+8)*72 + k0+t2+8];
            #pragma unroll
            for(int ni=0;ni<8;ni++){
                int n = ni*8 + g;
                uint32_t bb[2];
                bb[0] = *(const uint32_t*)&KVs[n*264 + kc*64 + k0+t2];
                bb[1] = *(const uint32_t*)&KVs[n*264 + kc*64 + k0+t2+8];
                mma_bf16(acc[ni], a, bb);
            }
        }
    }
    // epilogue
    int lr0 = l0 + wid*16 + g;
    float n0 = norm[(size_t)bh*LP_ + lr0];
    float n1 = norm[(size_t)bh*LP_ + lr0 + 8];
    float rn0 = 1.f/fmaxf(n0, 1e-6f);
    float rn1 = 1.f/fmaxf(n1, 1e-6f);
    #pragma unroll
    for(int ni=0;ni<8;ni++){
        int d = ni*8 + t2;
        if(lr0 < L_){
            __nv_bfloat16* o = out + ((size_t)(b*L_ + lr0))*D_ + h*DH_ + d;
            *(__nv_bfloat162*)o = __floats2bfloat162_rn(acc[ni][0]*rn0, acc[ni][1]*rn0);
        }
        if(lr0+8 < L_){
            __nv_bfloat16* o = out + ((size_t)(b*L_ + lr0 + 8))*D_ + h*DH_ + d;
            *(__nv_bfloat162*)o = __floats2bfloat162_rn(acc[ni][2]*rn1, acc[ni][3]*rn1);
        }
    }
}

// ---------------- pooling scores: warp per row ----------------
__global__ void __launch_bounds__(256) score2_kernel(const float* __restrict__ Tt,
        const float* __restrict__ W2, float* __restrict__ sc){
    int r = blockIdx.x*8 + (threadIdx.x>>5);
    int lane = threadIdx.x & 31;
    const float* tr = Tt + (size_t)r*HID_;
    float s = 0.f;
    #pragma unroll
    for(int i=0;i<4;i++){
        int j = lane + 32*i;
        s += tanhf(tr[j]) * __ldg(&W2[j]);
    }
    #pragma unroll
    for(int o=16;o;o>>=1) s += __shfl_xor_sync(0xffffffffu, s, o);
    if(lane==0) sc[r] = s;
}

// ---------------- softmax over L (normalized alpha out) ----------------
__global__ void __launch_bounds__(256) softmax_kernel(const float* __restrict__ sc,
        float* __restrict__ alpha){
    __shared__ float al[L_];
    __shared__ float red[32];
    int b = blockIdx.x, t = threadIdx.x;
    float lmax = -1e30f;
    for(int i=t;i<L_;i+=256){ float v = sc[b*L_+i]; al[i]=v; lmax=fmaxf(lmax,v); }
    #pragma unroll
    for(int o=16;o;o>>=1) lmax = fmaxf(lmax, __shfl_xor_sync(0xffffffffu, lmax, o));
    if((t&31)==0) red[t>>5] = lmax;
    __syncthreads();
    if(t < 32){
        float r = (t < 8) ? red[t] : -1e30f;
        #pragma unroll
        for(int o=4;o;o>>=1) r = fmaxf(r, __shfl_xor_sync(0xffffffffu, r, o));
        if(t==0) red[0] = r;
    }
    __syncthreads();
    float mx = red[0];
    __syncthreads();
    float ls = 0.f;
    for(int i=t;i<L_;i+=256){ float e = __expf(al[i]-mx); al[i]=e; ls += e; }
    // block sum
    #pragma unroll
    for(int o=16;o;o>>=1) ls += __shfl_xor_sync(0xffffffffu, ls, o);
    if((t&31)==0) red[t>>5] = ls;
    __syncthreads();
    if(t < 32){
        float r = (t < 8) ? red[t] : 0.f;
        #pragma unroll
        for(int o=4;o;o>>=1) r += __shfl_xor_sync(0xffffffffu, r, o);
        if(t==0) red[0] = r;
    }
    __syncthreads();
    float inv = 1.f/red[0];
    for(int i=t;i<L_;i+=256) alpha[b*L_+i] = al[i]*inv;
}

// ---------------- attentive stats (parallel over d) ----------------
__global__ void __launch_bounds__(128) stats_kernel(const float* __restrict__ h,
        const float* __restrict__ alpha, float* __restrict__ feat){
    __shared__ float al[L_];
    int b = blockIdx.x;
    int dd = blockIdx.y*128 + threadIdx.x;
    for(int i=threadIdx.x;i<L_;i+=128) al[i] = alpha[b*L_+i];
    __syncthreads();
    float mu = 0.f, m2 = 0.f;
    for(int l=0;l<L_;l++){
        float a  = al[l];
        float hv = h[((size_t)(b*L_ + l))*D_ + dd];
        mu += a*hv;
        m2 += a*hv*hv;
    }
    feat[b*1024 + dd]       = mu;
    feat[b*1024 + 512 + dd] = sqrtf(fmaxf(m2 - mu*mu, 1e-8f));
}

// ---------------- final classifier head ----------------
__global__ void head_kernel(const float* __restrict__ feat, const float* __restrict__ W,
                            const float* __restrict__ bb, float* __restrict__ out){
    __shared__ float fs[1024];
    int b = blockIdx.x, t = threadIdx.x;   // 320 threads
    for(int i=t;i<1024;i+=320) fs[i] = feat[b*1024 + i];
    __syncthreads();
    int w = t >> 5, lane = t & 31;
    if(w < NC_){
        float s = 0.f;
        for(int k=lane;k<1024;k+=32) s += fs[k]*W[k*NC_ + w];
        #pragma unroll
        for(int o=16;o;o>>=1) s += __shfl_xor_sync(0xffffffffu, s, o);
        if(lane==0) out[b*NC_ + w] = s + bb[w];
    }
}

// ---------------- launch ----------------
template<typename T> static void* symaddr_(T& s){
    void* p = nullptr;
    cudaGetSymbolAddress(&p, s);
    return p;
}

extern "C" void kernel_launch(void* const* d_in, const int* in_sizes, int n_in,
                              void* d_out, int out_size){
    const float* x        = (const float*)d_in[0];
    const float* patch_W  = (const float*)d_in[1];
    const float* patch_b  = (const float*)d_in[2];
    const float* patch_g  = (const float*)d_in[3];
    const float* patch_be = (const float*)d_in[4];
    const float* ln1_g    = (const float*)d_in[5];
    const float* ln1_b    = (const float*)d_in[6];
    const float* qW       = (const float*)d_in[7];
    const float* kW       = (const float*)d_in[8];
    const float* vW       = (const float*)d_in[9];
    const float* oW       = (const float*)d_in[10];
    const float* ob       = (const float*)d_in[11];
    const float* omega    = (const float*)d_in[12];
    const float* ln2_g    = (const float*)d_in[13];
    const float* ln2_b    = (const float*)d_in[14];
    const float* f1W      = (const float*)d_in[15];
    const float* f1b      = (const float*)d_in[16];
    const float* f2W      = (const float*)d_in[17];
    const float* f2b      = (const float*)d_in[18];
    const float* poolW1   = (const float*)d_in[19];
    const float* poolW2   = (const float*)d_in[20];
    const float* headW    = (const float*)d_in[21];
    const float* headb    = (const float*)d_in[22];
    float* out = (float*)d_out;

    float* h     = (float*)symaddr_(g_h);
    float* tmp   = (float*)symaddr_(g_tmp);
    float* Ksum  = (float*)symaddr_(g_Ksum);
    float* normp = (float*)symaddr_(g_norm);
    float* sc    = (float*)symaddr_(g_scores);
    float* alpha = (float*)symaddr_(g_alpha);
    float* feat  = (float*)symaddr_(g_feat);
    __nv_bfloat16* tokb   = (__nv_bfloat16*)symaddr_(g_tokb);
    __nv_bfloat16* x1b    = (__nv_bfloat16*)symaddr_(g_x1b);
    __nv_bfloat16* QKV    = (__nv_bfloat16*)symaddr_(g_QKV);
    __nv_bfloat16* tmpb   = (__nv_bfloat16*)symaddr_(g_tmpb);
    __nv_bfloat16* attnob = (__nv_bfloat16*)symaddr_(g_attnob);
    __nv_bfloat16* hb     = (__nv_bfloat16*)symaddr_(g_hb);
    __nv_bfloat16* Qf     = (__nv_bfloat16*)symaddr_(g_Qf);
    __nv_bfloat16* Kf     = (__nv_bfloat16*)symaddr_(g_Kf);
    __nv_bfloat16* KVT    = (__nv_bfloat16*)symaddr_(g_KVT);
    __nv_bfloat16* qkvWT  = (__nv_bfloat16*)symaddr_(g_qkvWT);
    __nv_bfloat16* oWT    = (__nv_bfloat16*)symaddr_(g_oWT);
    __nv_bfloat16* f1WT   = (__nv_bfloat16*)symaddr_(g_f1WT);
    __nv_bfloat16* f2WT   = (__nv_bfloat16*)symaddr_(g_f2WT);
    __nv_bfloat16* patchWT= (__nv_bfloat16*)symaddr_(g_patchWT);
    __nv_bfloat16* poolW1T= (__nv_bfloat16*)symaddr_(g_poolW1T);

    static const int PHI_SMEM  = (64*256 + 8*64 + 256)*4;       // 68608
    static const int ATTN_SMEM = (64*264 + 128*72)*2;           // 52224
    cudaFuncSetAttribute(phi_kernel<false>, cudaFuncAttributeMaxDynamicSharedMemorySize, PHI_SMEM);
    cudaFuncSetAttribute(phi_kernel<true>,  cudaFuncAttributeMaxDynamicSharedMemorySize, PHI_SMEM);
    cudaFuncSetAttribute(attn_tc,           cudaFuncAttributeMaxDynamicSharedMemorySize, ATTN_SMEM);

    // weight prep: one batched launch
    WAll wa;
    for(int l=0;l<NL_;l++){
        wa.d[l*6+0] = { qW + (size_t)l*D_*D_,    qkvWT + (size_t)l*3*D_*D_,             D_,  D_,   D_ };
        wa.d[l*6+1] = { kW + (size_t)l*D_*D_,    qkvWT + (size_t)l*3*D_*D_ + D_*D_,     D_,  D_,   D_ };
        wa.d[l*6+2] = { vW + (size_t)l*D_*D_,    qkvWT + (size_t)l*3*D_*D_ + 2*D_*D_,   D_,  D_,   D_ };
        wa.d[l*6+3] = { oW + (size_t)l*D_*D_,    oWT + (size_t)l*D_*D_,                 D_,  D_,   D_ };
        wa.d[l*6+4] = { f1W + (size_t)l*D_*FFN_, f1WT + (size_t)l*FFN_*D_,              D_,  FFN_, D_ };
        wa.d[l*6+5] = { f2W + (size_t)l*FFN_*D_, f2WT + (size_t)l*D_*FFN_,              FFN_, D_,  FFN_ };
    }
    wa.d[12] = { patch_W, patchWT, C_*P_, D_,   KPATCH };
    wa.d[13] = { poolW1,  poolW1T, D_,    HID_, D_ };
    wprep_all<<<dim3(32,32,14), dim3(32,8)>>>(wa);

    // patchify + patch embed + LN
    patchify_kernel<<<(B_*C_*T_ + 255)/256, 256>>>(x);
    gemm_bf16<false,false><<<dim3(D_/128, R_/128), 256>>>(tokb, patchWT, patch_b, nullptr, tmp, R_, D_, KPATCH);
    ln_kernel<false><<<R_/4, 256>>>(tmp, patch_g, patch_be, h);

    for(int l=0;l<NL_;l++){
        const float* obl = ob + l*D_;
        const float* oml = omega + (size_t)l*DH_*M_;
        dim3 gq(D_/128, R_/128);

        // attention branch
        ln_kernel<true><<<R_/4, 256>>>(h, ln1_g + l*D_, ln1_b + l*D_, x1b);
        gemm_bf16<false,true><<<dim3(3*D_/128, R_/128), 256>>>(
            x1b, qkvWT + (size_t)l*3*D_*D_, nullptr, nullptr, QKV, R_, 3*D_, D_);
        phi_kernel<false><<<B_*H_, 256, PHI_SMEM>>>(QKV + D_, oml, Kf, nullptr, nullptr);
        kv_tc<<<B_*H_, 256>>>(Kf, QKV, KVT, Ksum);
        phi_kernel<true><<<B_*H_, 256, PHI_SMEM>>>(QKV, oml, Qf, Ksum, normp);
        attn_tc<<<dim3(B_*H_, LP_/128), 256, ATTN_SMEM>>>(Qf, KVT, normp, attnob);
        gemm_bf16<false,false><<<gq, 256>>>(attnob, oWT + (size_t)l*D_*D_, obl, h, h, R_, D_, D_);

        // FFN branch
        ln_kernel<true><<<R_/4, 256>>>(h, ln2_g + l*D_, ln2_b + l*D_, x1b);
        gemm_bf16<true,true><<<dim3(FFN_/128, R_/128), 256>>>(
            x1b, f1WT + (size_t)l*FFN_*D_, f1b + l*FFN_, nullptr, tmpb, R_, FFN_, D_);
        gemm_bf16<false,false><<<gq, 256>>>(
            tmpb, f2WT + (size_t)l*D_*FFN_, f2b + l*D_, h, h, R_, D_, FFN_);
    }

    // pooling + head
    f2bf_kernel<<<(R_*D_/2 + 255)/256, 256>>>(h, hb, R_*D_/2);
    gemm_bf16<false,false><<<dim3(HID_/128, R_/128), 256>>>(hb, poolW1T, nullptr, nullptr, tmp, R_, HID_, D_);
    score2_kernel<<<R_/8, 256>>>(tmp, poolW2, sc);
    softmax_kernel<<<B_, 256>>>(sc, alpha);
    stats_kernel<<<dim3(B_, 4), 128>>>(h, alpha, feat);
    head_kernel<<<B_, 320>>>(feat, headW, headb, out);
}

// round 12
// speedup vs baseline: 5.8150x; 2.1437x over previous
#include <cuda_runtime.h>
#include <cuda_bf16.h>
#include <math.h>
#include <stdint.h>

// ---------------- problem dims ----------------
#define B_    32
#define C_    8
#define T_    20000
#define P_    25
#define D_    512
#define H_    8
#define M_    256
#define NL_   2
#define FFN_  1024
#define NC_   10
#define HID_  128
#define DH_   64
#define L_    800
#define R_    (B_*L_)        // 25600
#define KPATCH 224
#define LP_   896            // L padded to 7*128

// ---------------- scratch (device globals; zero-initialized at load) ----------------
__device__ float g_h[R_*D_];
__device__ float g_tmp[R_*D_];
__device__ float g_Ksum[B_*H_*M_];
__device__ float g_scores[R_];
__device__ float g_alpha[R_];
__device__ float g_feat[B_*2*D_];

__device__ __nv_bfloat16 g_tokb[R_*KPATCH];
__device__ __nv_bfloat16 g_x1b[R_*D_];
__device__ __nv_bfloat16 g_QKV[R_*3*D_];
__device__ __nv_bfloat16 g_tmpb[R_*FFN_];
__device__ __nv_bfloat16 g_attnob[R_*D_];
__device__ __nv_bfloat16 g_hb[R_*D_];
__device__ __nv_bfloat16 g_Qf[(size_t)B_*H_*LP_*M_];
__device__ __nv_bfloat16 g_Kf[(size_t)B_*H_*LP_*M_];
__device__ __nv_bfloat16 g_KVT[B_*H_*DH_*M_];
// transposed bf16 weights WT[N][K]
__device__ __nv_bfloat16 g_qkvWT[NL_*3*D_*D_];
__device__ __nv_bfloat16 g_oWT[NL_*D_*D_];
__device__ __nv_bfloat16 g_f1WT[NL_*FFN_*D_];
__device__ __nv_bfloat16 g_f2WT[NL_*D_*FFN_];
__device__ __nv_bfloat16 g_patchWT[D_*KPATCH];
__device__ __nv_bfloat16 g_poolW1T[HID_*D_];
__device__ __nv_bfloat16 g_omT[NL_*M_*DH_];   // omega^T * sc, [256][64] per layer

// ---------------- batched weight prep ----------------
struct WDesc { const float* src; __nv_bfloat16* dst; int K, N, Kpad; float scale; };
struct WAll  { WDesc d[16]; };

__global__ void wprep_all(WAll wa){
    WDesc w = wa.d[blockIdx.z];
    int k0 = blockIdx.y*32, n0 = blockIdx.x*32;
    if(k0 >= w.Kpad || n0 >= w.N) return;
    __shared__ float t[32][33];
    int tx = threadIdx.x, ty = threadIdx.y;
    #pragma unroll
    for(int i=ty;i<32;i+=8){
        int k = k0+i, n = n0+tx;
        t[i][tx] = (k<w.K && n<w.N) ? w.src[(size_t)k*w.N+n] : 0.f;
    }
    __syncthreads();
    #pragma unroll
    for(int i=ty;i<32;i+=8){
        int n = n0+i, k = k0+tx;
        if(n<w.N && k<w.Kpad) w.dst[(size_t)n*w.Kpad+k] = __float2bfloat16(t[tx][i]*w.scale);
    }
}

// ---------------- patchify ----------------
__global__ void patchify_kernel(const float* __restrict__ x){
    int idx = blockIdx.x*blockDim.x + threadIdx.x;
    if(idx >= B_*C_*T_) return;
    int t  = idx % T_;
    int bc = idx / T_;
    int c  = bc % C_;
    int b  = bc / C_;
    int l = t / P_, p = t % P_;
    g_tokb[(size_t)(b*L_ + l)*KPATCH + c*P_ + p] = __float2bfloat16(x[idx]);
}

// ---------------- fp32 -> bf16 convert ----------------
__global__ void f2bf_kernel(const float* __restrict__ in, __nv_bfloat16* __restrict__ out, int n2){
    int i = blockIdx.x*blockDim.x + threadIdx.x;
    if(i >= n2) return;
    float2 v = ((const float2*)in)[i];
    ((__nv_bfloat162*)out)[i] = __floats2bfloat162_rn(v.x, v.y);
}

// ---------------- LayerNorm ----------------
template<bool BF16OUT>
__global__ void __launch_bounds__(256) ln_kernel(const float* __restrict__ X,
        const float* __restrict__ gg, const float* __restrict__ be, void* __restrict__ Yv){
    __shared__ float2 red[8];
    int t = threadIdx.x;
    int row = blockIdx.x*4 + (t>>6);
    int c = t & 63;
    const float4* xr = (const float4*)(X + (size_t)row*D_);
    float4 v0 = xr[c*2], v1 = xr[c*2+1];
    float s = v0.x+v0.y+v0.z+v0.w + v1.x+v1.y+v1.z+v1.w;
    float q = v0.x*v0.x+v0.y*v0.y+v0.z*v0.z+v0.w*v0.w
            + v1.x*v1.x+v1.y*v1.y+v1.z*v1.z+v1.w*v1.w;
    #pragma unroll
    for(int o=16;o;o>>=1){
        s += __shfl_xor_sync(0xffffffffu, s, o);
        q += __shfl_xor_sync(0xffffffffu, q, o);
    }
    int w = t>>5;
    if((t&31)==0) red[w] = make_float2(s, q);
    __syncthreads();
    float2 A = red[w], Bp = red[w^1];
    float mu  = (A.x + Bp.x) * (1.f/512.f);
    float msq = (A.y + Bp.y) * (1.f/512.f);
    float inv = rsqrtf(fmaxf(msq - mu*mu, 0.f) + 1e-5f);
    float4 g0 = ((const float4*)gg)[c*2], g1 = ((const float4*)gg)[c*2+1];
    float4 b0 = ((const float4*)be)[c*2], b1 = ((const float4*)be)[c*2+1];
    float y[8];
    y[0]=(v0.x-mu)*inv*g0.x+b0.x; y[1]=(v0.y-mu)*inv*g0.y+b0.y;
    y[2]=(v0.z-mu)*inv*g0.z+b0.z; y[3]=(v0.w-mu)*inv*g0.w+b0.w;
    y[4]=(v1.x-mu)*inv*g1.x+b1.x; y[5]=(v1.y-mu)*inv*g1.y+b1.y;
    y[6]=(v1.z-mu)*inv*g1.z+b1.z; y[7]=(v1.w-mu)*inv*g1.w+b1.w;
    if(BF16OUT){
        __nv_bfloat162 p[4];
        #pragma unroll
        for(int i=0;i<4;i++) p[i] = __floats2bfloat162_rn(y[2*i], y[2*i+1]);
        ((uint4*)((__nv_bfloat16*)Yv + (size_t)row*D_))[c] = *(uint4*)p;
    }else{
        float* yr = (float*)Yv + (size_t)row*D_;
        ((float4*)yr)[c*2]   = make_float4(y[0],y[1],y[2],y[3]);
        ((float4*)yr)[c*2+1] = make_float4(y[4],y[5],y[6],y[7]);
    }
}

// ---------------- mma / ldmatrix / cp.async primitives ----------------
__device__ __forceinline__ void mma_bf16(float* d, const uint32_t* a, const uint32_t* b){
    asm volatile("mma.sync.aligned.m16n8k16.row.col.f32.bf16.bf16.f32 "
        "{%0,%1,%2,%3}, {%4,%5,%6,%7}, {%8,%9}, {%0,%1,%2,%3};"
        : "+f"(d[0]), "+f"(d[1]), "+f"(d[2]), "+f"(d[3])
        : "r"(a[0]), "r"(a[1]), "r"(a[2]), "r"(a[3]), "r"(b[0]), "r"(b[1]));
}
__device__ __forceinline__ void ldsm4(uint32_t* r, uint32_t addr){
    asm volatile("ldmatrix.sync.aligned.m8n8.x4.shared.b16 {%0,%1,%2,%3},[%4];"
        : "=r"(r[0]),"=r"(r[1]),"=r"(r[2]),"=r"(r[3]) : "r"(addr));
}
__device__ __forceinline__ void cp16(uint32_t saddr, const void* g){
    asm volatile("cp.async.cg.shared.global [%0],[%1],16;\n" :: "r"(saddr), "l"(g));
}

// ---------------- bf16 TC GEMM: C = A[M,K] * WT[N,K]^T, cp.async 3-stage + ldmatrix ----------------
#define KT 32
#define SA 40

template<bool GELU, bool BF16OUT>
__global__ void __launch_bounds__(256) gemm_bf16(
        const __nv_bfloat16* __restrict__ A, const __nv_bfloat16* __restrict__ BT,
        const float* __restrict__ bias, const float* __restrict__ res,
        void* __restrict__ Cv, int M, int N, int K)
{
    extern __shared__ __nv_bfloat16 smg[];
    __nv_bfloat16* As = smg;                 // [3][128*SA]
    __nv_bfloat16* Bs = smg + 3*128*SA;
    int tid = threadIdx.x;
    int row0 = blockIdx.y*128, col0 = blockIdx.x*128;
    int wid = tid>>5, lane = tid&31;
    int wm = (wid>>2)*64, wn = (wid&3)*32;
    int g = lane>>2, t2 = (lane&3)*2;
    int lr = tid>>2, lq = (tid&3)*8;

    uint32_t aBase = (uint32_t)__cvta_generic_to_shared(As);
    uint32_t bBase = (uint32_t)__cvta_generic_to_shared(Bs);
    const int stgH = 128*SA;
    const __nv_bfloat16* Ag = A + (size_t)(row0+lr)*K + lq;
    const __nv_bfloat16* Bg = BT + (size_t)(col0+lr)*K + lq;
    size_t rstep = (size_t)64*K;

    auto issue = [&](int stg, int k0){
        uint32_t sa = aBase + (stg*stgH + lr*SA + lq)*2;
        cp16(sa,             Ag + k0);
        cp16(sa + 64*SA*2,   Ag + rstep + k0);
        uint32_t sb = bBase + (stg*stgH + lr*SA + lq)*2;
        cp16(sb,             Bg + k0);
        cp16(sb + 64*SA*2,   Bg + rstep + k0);
        asm volatile("cp.async.commit_group;\n"::);
    };

    float acc[4][4][4];
    #pragma unroll
    for(int mi=0;mi<4;mi++)
        #pragma unroll
        for(int ni=0;ni<4;ni++)
            #pragma unroll
            for(int q=0;q<4;q++) acc[mi][ni][q]=0.f;

    int nsteps = K/KT;
    issue(0, 0);
    issue(1, KT);

    int aRow = wm + (lane&15);
    int aK   = (lane>>4)<<3;
    int bRow = wn + (lane&7) + ((lane>>4)<<3);
    int bK   = ((lane>>3)&1)<<3;

    for(int s=0; s<nsteps; s++){
        asm volatile("cp.async.wait_group 1;\n"::);
        __syncthreads();
        int buf = s % 3;
        uint32_t aS = aBase + buf*stgH*2;
        uint32_t bS = bBase + buf*stgH*2;
        #pragma unroll
        for(int ks=0; ks<2; ks++){
            int k0 = ks*16;
            uint32_t af[4][4], bfv[2][4];
            #pragma unroll
            for(int mi=0;mi<4;mi++)
                ldsm4(af[mi], aS + (((aRow+mi*16)*SA) + k0 + aK)*2);
            #pragma unroll
            for(int p=0;p<2;p++)
                ldsm4(bfv[p], bS + (((bRow+p*16)*SA) + k0 + bK)*2);
            #pragma unroll
            for(int mi=0;mi<4;mi++){
                #pragma unroll
                for(int ni=0;ni<4;ni++){
                    uint32_t bb[2] = { bfv[ni>>1][(ni&1)*2], bfv[ni>>1][(ni&1)*2+1] };
                    mma_bf16(acc[mi][ni], af[mi], bb);
                }
            }
        }
        if(s+2 < nsteps) issue((s+2)%3, (s+2)*KT);
        else asm volatile("cp.async.commit_group;\n"::);
    }

    #pragma unroll
    for(int mi=0;mi<4;mi++){
        #pragma unroll
        for(int ni=0;ni<4;ni++){
            int r  = row0 + wm + mi*16 + g;
            int cc = col0 + wn + ni*8 + t2;
            #pragma unroll
            for(int half=0; half<2; half++){
                int rr = r + half*8;
                float v0 = acc[mi][ni][half*2+0];
                float v1 = acc[mi][ni][half*2+1];
                if(bias){ v0 += bias[cc]; v1 += bias[cc+1]; }
                if(GELU){
                    v0 = 0.5f*v0*(1.f + erff(v0*0.70710678118f));
                    v1 = 0.5f*v1*(1.f + erff(v1*0.70710678118f));
                }
                if(res){
                    v0 += res[(size_t)rr*N + cc];
                    v1 += res[(size_t)rr*N + cc + 1];
                }
                if(BF16OUT){
                    *(__nv_bfloat162*)((__nv_bfloat16*)Cv + (size_t)rr*N + cc)
                        = __floats2bfloat162_rn(v0, v1);
                }else{
                    float* C = (float*)Cv;
                    C[(size_t)rr*N + cc]     = v0;
                    C[(size_t)rr*N + cc + 1] = v1;
                }
            }
        }
    }
}

// ---------------- FAVOR+ feature map via tensor cores ----------------
// F[bh, l, m] = exp( (X*sc) @ omega  - 0.5|X*sc|^2 ) / sqrt(M)   (sc folded into omT)
__global__ void __launch_bounds__(256) phi_tc(const __nv_bfloat16* __restrict__ X,
        const __nv_bfloat16* __restrict__ omT, __nv_bfloat16* __restrict__ F){
    __shared__ __nv_bfloat16 Xs[128*72];
    __shared__ __nv_bfloat16 Om[128*72];
    __shared__ float n2s[128];
    int bh = blockIdx.x, b = bh>>3, h = bh&7;
    int l0 = blockIdx.y*128;
    int nt = blockIdx.z;
    int tid = threadIdx.x, wid = tid>>5, lane = tid&31;
    {
        // full-row load: 2 threads per row, 32 halves each (row = 64 halves)
        int r = tid>>1, off = (tid&1)*32;
        int l = l0 + r;
        uint4 v0 = make_uint4(0,0,0,0), v1 = v0, v2 = v0, v3 = v0;
        if(l < L_){
            const __nv_bfloat16* xr = X + (size_t)(b*L_ + l)*(3*D_) + h*DH_ + off;
            v0 = *(const uint4*)xr;
            v1 = *(const uint4*)(xr+8);
            v2 = *(const uint4*)(xr+16);
            v3 = *(const uint4*)(xr+24);
        }
        *(uint4*)&Xs[r*72+off]    = v0;
        *(uint4*)&Xs[r*72+off+8]  = v1;
        *(uint4*)&Xs[r*72+off+16] = v2;
        *(uint4*)&Xs[r*72+off+24] = v3;
        const __nv_bfloat16* orow = omT + (size_t)(nt*128 + r)*DH_ + off;
        *(uint4*)&Om[r*72+off]    = *(const uint4*)orow;
        *(uint4*)&Om[r*72+off+8]  = *(const uint4*)(orow+8);
        *(uint4*)&Om[r*72+off+16] = *(const uint4*)(orow+16);
        *(uint4*)&Om[r*72+off+24] = *(const uint4*)(orow+24);
    }
    __syncthreads();
    if(tid < 128){
        float s = 0.f;
        #pragma unroll
        for(int u=0;u<32;u++){
            float2 f = __bfloat1622float2(*(const __nv_bfloat162*)&Xs[tid*72 + 2*u]);
            s += f.x*f.x + f.y*f.y;
        }
        n2s[tid] = 0.0625f * s;   // 0.5 * sc^2, sc^2 = 1/8
    }
    __syncthreads();

    int wm = (wid>>2)*64, wn = (wid&3)*32;
    int g = lane>>2, t2 = (lane&3)*2;
    int aRow = wm + (lane&15), aK = (lane>>4)<<3;
    int bRow = wn + (lane&7) + ((lane>>4)<<3), bK = ((lane>>3)&1)<<3;
    uint32_t xB = (uint32_t)__cvta_generic_to_shared(Xs);
    uint32_t oB = (uint32_t)__cvta_generic_to_shared(Om);
    float acc[4][4][4];
    #pragma unroll
    for(int mi=0;mi<4;mi++)
        #pragma unroll
        for(int ni=0;ni<4;ni++)
            #pragma unroll
            for(int q=0;q<4;q++) acc[mi][ni][q]=0.f;

    #pragma unroll
    for(int ks=0;ks<4;ks++){
        int k0 = ks*16;
        uint32_t af[4][4], bfv[2][4];
        #pragma unroll
        for(int mi=0;mi<4;mi++)
            ldsm4(af[mi], xB + (((aRow+mi*16)*72) + k0 + aK)*2);
        #pragma unroll
        for(int p=0;p<2;p++)
            ldsm4(bfv[p], oB + (((bRow+p*16)*72) + k0 + bK)*2);
        #pragma unroll
        for(int mi=0;mi<4;mi++){
            #pragma unroll
            for(int ni=0;ni<4;ni++){
                uint32_t bb[2] = { bfv[ni>>1][(ni&1)*2], bfv[ni>>1][(ni&1)*2+1] };
                mma_bf16(acc[mi][ni], af[mi], bb);
            }
        }
    }

    __nv_bfloat16* Fb = F + ((size_t)bh*LP_ + l0)*M_ + nt*128;
    #pragma unroll
    for(int mi=0;mi<4;mi++){
        #pragma unroll
        for(int ni=0;ni<4;ni++){
            int row = wm + mi*16 + g, col = wn + ni*8 + t2;
            float n2a = n2s[row], n2b = n2s[row+8];
            float e0 = __expf(acc[mi][ni][0]-n2a)*0.0625f;
            float e1 = __expf(acc[mi][ni][1]-n2a)*0.0625f;
            float e2 = __expf(acc[mi][ni][2]-n2b)*0.0625f;
            float e3 = __expf(acc[mi][ni][3]-n2b)*0.0625f;
            *(__nv_bfloat162*)&Fb[(size_t)row*M_ + col]     = __floats2bfloat162_rn(e0,e1);
            *(__nv_bfloat162*)&Fb[(size_t)(row+8)*M_ + col] = __floats2bfloat162_rn(e2,e3);
        }
    }
}

// ---------------- KV^T = (Kf^T V)^T via tensor cores; also Ksum ----------------
__global__ void __launch_bounds__(256) kv_tc(const __nv_bfloat16* __restrict__ Kf,
        const __nv_bfloat16* __restrict__ QKV,
        __nv_bfloat16* __restrict__ KVT, float* __restrict__ Ksum){
    __shared__ __nv_bfloat16 KfT[256*40];
    __shared__ __nv_bfloat16 VT[64*40];
    int bh = blockIdx.x;
    int b = bh>>3, h = bh&7;
    int t = threadIdx.x, wid = t>>5, lane = t&31;
    int wm = (wid>>1)*64, wn = (wid&1)*32;
    int g = lane>>2, t2 = (lane&3)*2;
    float acc[4][4][4];
    #pragma unroll
    for(int mi=0;mi<4;mi++)
        #pragma unroll
        for(int ni=0;ni<4;ni++)
            #pragma unroll
            for(int q=0;q<4;q++) acc[mi][ni][q]=0.f;
    float kssum = 0.f;

    const __nv_bfloat16* Kfb = Kf + (size_t)bh*LP_*M_;
    const __nv_bfloat16* Vb  = QKV + ((size_t)b*L_)*(3*D_) + 2*D_ + h*DH_;
    int lrow = t>>3, lj = t&7;

    for(int l0=0;l0<L_;l0+=32){
        #pragma unroll
        for(int c=0;c<4;c++){
            int m0 = (lj + 8*c)*8;
            uint4 v = *(const uint4*)&Kfb[(size_t)(l0+lrow)*M_ + m0];
            const __nv_bfloat16* pv = (const __nv_bfloat16*)&v;
            #pragma unroll
            for(int i=0;i<8;i++) KfT[(m0+i)*40 + lrow] = pv[i];
        }
        {
            int d0 = lj*8;
            uint4 v = *(const uint4*)&Vb[(size_t)(l0+lrow)*(3*D_) + d0];
            const __nv_bfloat16* pv = (const __nv_bfloat16*)&v;
            #pragma unroll
            for(int i=0;i<8;i++) VT[(d0+i)*40 + lrow] = pv[i];
        }
        __syncthreads();
        #pragma unroll
        for(int u=0;u<16;u++){
            __nv_bfloat162 p = *(const __nv_bfloat162*)&KfT[t*40 + 2*u];
            float2 f = __bfloat1622float2(p);
            kssum += f.x + f.y;
        }
        #pragma unroll
        for(int kk=0;kk<2;kk++){
            int k0 = kk*16;
            uint32_t a[4][4], bb[4][2];
            #pragma unroll
            for(int mi=0;mi<4;mi++){
                int row = wm + mi*16 + g;
                a[mi][0] = *(const uint32_t*)&KfT[row*40 + k0+t2];
                a[mi][1] = *(const uint32_t*)&KfT[(row+8)*40 + k0+t2];
                a[mi][2] = *(const uint32_t*)&KfT[row*40 + k0+t2+8];
                a[mi][3] = *(const uint32_t*)&KfT[(row+8)*40 + k0+t2+8];
            }
            #pragma unroll
            for(int ni=0;ni<4;ni++){
                int n = wn + ni*8 + g;
                bb[ni][0] = *(const uint32_t*)&VT[n*40 + k0+t2];
                bb[ni][1] = *(const uint32_t*)&VT[n*40 + k0+t2+8];
            }
            #pragma unroll
            for(int mi=0;mi<4;mi++)
                #pragma unroll
                for(int ni=0;ni<4;ni++)
                    mma_bf16(acc[mi][ni], a[mi], bb[ni]);
        }
        __syncthreads();
    }
    __nv_bfloat16* kvt = KVT + (size_t)bh*DH_*M_;
    #pragma unroll
    for(int mi=0;mi<4;mi++){
        #pragma unroll
        for(int ni=0;ni<4;ni++){
            int m = wm + mi*16 + g;
            int d = wn + ni*8 + t2;
            kvt[(size_t)d*M_ + m]       = __float2bfloat16(acc[mi][ni][0]);
            kvt[(size_t)(d+1)*M_ + m]   = __float2bfloat16(acc[mi][ni][1]);
            kvt[(size_t)d*M_ + m+8]     = __float2bfloat16(acc[mi][ni][2]);
            kvt[(size_t)(d+1)*M_ + m+8] = __float2bfloat16(acc[mi][ni][3]);
        }
    }
    Ksum[bh*M_ + t] = kssum;
}

// ---------------- attn out = (Qf @ KV) / max(Qf·Ksum, 1e-6), norm fused ----------------
__global__ void __launch_bounds__(256) attn_tc(const __nv_bfloat16* __restrict__ Qf,
        const __nv_bfloat16* __restrict__ KVT, const float* __restrict__ Ksum,
        __nv_bfloat16* __restrict__ out){
    extern __shared__ char smraw[];
    __nv_bfloat16* KVs = (__nv_bfloat16*)smraw;      // [64][264]
    __nv_bfloat16* Qs  = KVs + 64*264;               // [128][72]
    float* Kss = (float*)(Qs + 128*72);              // [256]
    float* nrm = Kss + 256;                          // [128]
    int bh = blockIdx.x, lt = blockIdx.y;
    int b = bh>>3, h = bh&7;
    int tid = threadIdx.x, wid = tid>>5, lane = tid&31;
    int g = lane>>2, t2 = (lane&3)*2;

    {
        const __nv_bfloat16* kvt = KVT + (size_t)bh*DH_*M_;
        int r = tid>>2, s4 = tid&3;
        #pragma unroll
        for(int i=0;i<8;i++){
            int q = s4*8 + i;
            *(uint4*)&KVs[r*264 + q*8] = *(const uint4*)&kvt[(size_t)r*M_ + q*8];
        }
    }
    Kss[tid] = Ksum[bh*M_ + tid];

    float acc[8][4];
    #pragma unroll
    for(int ni=0;ni<8;ni++)
        #pragma unroll
        for(int q=0;q<4;q++) acc[ni][q]=0.f;
    float nacc = 0.f;

    int l0 = lt*128;
    const __nv_bfloat16* Qb = Qf + ((size_t)bh*LP_ + l0)*M_;
    int aRow = wid*16 + (lane&15), aK = (lane>>4)<<3;
    int bRowB = (lane&7) + ((lane>>4)<<3), bK = ((lane>>3)&1)<<3;
    uint32_t qB = (uint32_t)__cvta_generic_to_shared(Qs);
    uint32_t kB = (uint32_t)__cvta_generic_to_shared(KVs);

    for(int kc=0;kc<4;kc++){
        __syncthreads();
        {
            // full-row chunk load: 2 threads per row, 32 halves each (chunk = 64 halves)
            int r = tid>>1, off = (tid&1)*32;
            const __nv_bfloat16* src = &Qb[(size_t)r*M_ + kc*64 + off];
            *(uint4*)&Qs[r*72+off]    = *(const uint4*)src;
            *(uint4*)&Qs[r*72+off+8]  = *(const uint4*)(src+8);
            *(uint4*)&Qs[r*72+off+16] = *(const uint4*)(src+16);
            *(uint4*)&Qs[r*72+off+24] = *(const uint4*)(src+24);
        }
        __syncthreads();
        {
            int rr = tid>>1, hf = (tid&1)*32;
            const __nv_bfloat16* qp = &Qs[rr*72 + hf];
            const float* kp = &Kss[kc*64 + hf];
            #pragma unroll
            for(int j=0;j<16;j++){
                float2 f = __bfloat1622float2(*(const __nv_bfloat162*)&qp[2*j]);
                nacc += f.x*kp[2*j] + f.y*kp[2*j+1];
            }
        }
        #pragma unroll
        for(int kk=0;kk<4;kk++){
            int k0 = kk*16;
            uint32_t a[4];
            ldsm4(a, qB + ((aRow*72) + k0 + aK)*2);
            uint32_t bv[4][4];
            #pragma unroll
            for(int p=0;p<4;p++)
                ldsm4(bv[p], kB + (((p*16+bRowB)*264) + kc*64 + k0 + bK)*2);
            #pragma unroll
            for(int ni=0;ni<8;ni++){
                uint32_t bb[2] = { bv[ni>>1][(ni&1)*2], bv[ni>>1][(ni&1)*2+1] };
                mma_bf16(acc[ni], a, bb);
            }
        }
    }
    nacc += __shfl_xor_sync(0xffffffffu, nacc, 1);
    if((tid&1)==0) nrm[tid>>1] = nacc;
    __syncthreads();

    int lr0 = l0 + wid*16 + g;
    float rn0 = 1.f/fmaxf(nrm[wid*16+g], 1e-6f);
    float rn1 = 1.f/fmaxf(nrm[wid*16+g+8], 1e-6f);
    #pragma unroll
    for(int ni=0;ni<8;ni++){
        int d = ni*8 + t2;
        if(lr0 < L_){
            __nv_bfloat16* o = out + ((size_t)(b*L_ + lr0))*D_ + h*DH_ + d;
            *(__nv_bfloat162*)o = __floats2bfloat162_rn(acc[ni][0]*rn0, acc[ni][1]*rn0);
        }
        if(lr0+8 < L_){
            __nv_bfloat16* o = out + ((size_t)(b*L_ + lr0 + 8))*D_ + h*DH_ + d;
            *(__nv_bfloat162*)o = __floats2bfloat162_rn(acc[ni][2]*rn1, acc[ni][3]*rn1);
        }
    }
}

// ---------------- pooling scores ----------------
__global__ void __launch_bounds__(256) score2_kernel(const float* __restrict__ Tt,
        const float* __restrict__ W2, float* __restrict__ sc){
    int r = blockIdx.x*8 + (threadIdx.x>>5);
    int lane = threadIdx.x & 31;
    const float* tr = Tt + (size_t)r*HID_;
    float s = 0.f;
    #pragma unroll
    for(int i=0;i<4;i++){
        int j = lane + 32*i;
        s += tanhf(tr[j]) * __ldg(&W2[j]);
    }
    #pragma unroll
    for(int o=16;o;o>>=1) s += __shfl_xor_sync(0xffffffffu, s, o);
    if(lane==0) sc[r] = s;
}

// ---------------- softmax over L ----------------
__global__ void __launch_bounds__(256) softmax_kernel(const float* __restrict__ sc,
        float* __restrict__ alpha){
    __shared__ float al[L_];
    __shared__ float red[32];
    int b = blockIdx.x, t = threadIdx.x;
    float lmax = -1e30f;
    for(int i=t;i<L_;i+=256){ float v = sc[b*L_+i]; al[i]=v; lmax=fmaxf(lmax,v); }
    #pragma unroll
    for(int o=16;o;o>>=1) lmax = fmaxf(lmax, __shfl_xor_sync(0xffffffffu, lmax, o));
    if((t&31)==0) red[t>>5] = lmax;
    __syncthreads();
    if(t < 32){
        float r = (t < 8) ? red[t] : -1e30f;
        #pragma unroll
        for(int o=4;o;o>>=1) r = fmaxf(r, __shfl_xor_sync(0xffffffffu, r, o));
        if(t==0) red[0] = r;
    }
    __syncthreads();
    float mx = red[0];
    __syncthreads();
    float ls = 0.f;
    for(int i=t;i<L_;i+=256){ float e = __expf(al[i]-mx); al[i]=e; ls += e; }
    #pragma unroll
    for(int o=16;o;o>>=1) ls += __shfl_xor_sync(0xffffffffu, ls, o);
    if((t&31)==0) red[t>>5] = ls;
    __syncthreads();
    if(t < 32){
        float r = (t < 8) ? red[t] : 0.f;
        #pragma unroll
        for(int o=4;o;o>>=1) r += __shfl_xor_sync(0xffffffffu, r, o);
        if(t==0) red[0] = r;
    }
    __syncthreads();
    float inv = 1.f/red[0];
    for(int i=t;i<L_;i+=256) alpha[b*L_+i] = al[i]*inv;
}

// ---------------- attentive stats ----------------
__global__ void __launch_bounds__(128) stats_kernel(const float* __restrict__ h,
        const float* __restrict__ alpha, float* __restrict__ feat){
    __shared__ float al[L_];
    int b = blockIdx.x;
    int dd = blockIdx.y*128 + threadIdx.x;
    for(int i=threadIdx.x;i<L_;i+=128) al[i] = alpha[b*L_+i];
    __syncthreads();
    float mu = 0.f, m2 = 0.f;
    for(int l=0;l<L_;l++){
        float a  = al[l];
        float hv = h[((size_t)(b*L_ + l))*D_ + dd];
        mu += a*hv;
        m2 += a*hv*hv;
    }
    feat[b*1024 + dd]       = mu;
    feat[b*1024 + 512 + dd] = sqrtf(fmaxf(m2 - mu*mu, 1e-8f));
}

// ---------------- final classifier head ----------------
__global__ void head_kernel(const float* __restrict__ feat, const float* __restrict__ W,
                            const float* __restrict__ bb, float* __restrict__ out){
    __shared__ float fs[1024];
    int b = blockIdx.x, t = threadIdx.x;   // 320 threads
    for(int i=t;i<1024;i+=320) fs[i] = feat[b*1024 + i];
    __syncthreads();
    int w = t >> 5, lane = t & 31;
    if(w < NC_){
        float s = 0.f;
        for(int k=lane;k<1024;k+=32) s += fs[k]*W[k*NC_ + w];
        #pragma unroll
        for(int o=16;o;o>>=1) s += __shfl_xor_sync(0xffffffffu, s, o);
        if(lane==0) out[b*NC_ + w] = s + bb[w];
    }
}

// ---------------- launch ----------------
template<typename T> static void* symaddr_(T& s){
    void* p = nullptr;
    cudaGetSymbolAddress(&p, s);
    return p;
}

extern "C" void kernel_launch(void* const* d_in, const int* in_sizes, int n_in,
                              void* d_out, int out_size){
    const float* x        = (const float*)d_in[0];
    const float* patch_W  = (const float*)d_in[1];
    const float* patch_b  = (const float*)d_in[2];
    const float* patch_g  = (const float*)d_in[3];
    const float* patch_be = (const float*)d_in[4];
    const float* ln1_g    = (const float*)d_in[5];
    const float* ln1_b    = (const float*)d_in[6];
    const float* qW       = (const float*)d_in[7];
    const float* kW       = (const float*)d_in[8];
    const float* vW       = (const float*)d_in[9];
    const float* oW       = (const float*)d_in[10];
    const float* ob       = (const float*)d_in[11];
    const float* omega    = (const float*)d_in[12];
    const float* ln2_g    = (const float*)d_in[13];
    const float* ln2_b    = (const float*)d_in[14];
    const float* f1W      = (const float*)d_in[15];
    const float* f1b      = (const float*)d_in[16];
    const float* f2W      = (const float*)d_in[17];
    const float* f2b      = (const float*)d_in[18];
    const float* poolW1   = (const float*)d_in[19];
    const float* poolW2   = (const float*)d_in[20];
    const float* headW    = (const float*)d_in[21];
    const float* headb    = (const float*)d_in[22];
    float* out = (float*)d_out;

    float* h     = (float*)symaddr_(g_h);
    float* tmp   = (float*)symaddr_(g_tmp);
    float* Ksum  = (float*)symaddr_(g_Ksum);
    float* sc    = (float*)symaddr_(g_scores);
    float* alpha = (float*)symaddr_(g_alpha);
    float* feat  = (float*)symaddr_(g_feat);
    __nv_bfloat16* tokb   = (__nv_bfloat16*)symaddr_(g_tokb);
    __nv_bfloat16* x1b    = (__nv_bfloat16*)symaddr_(g_x1b);
    __nv_bfloat16* QKV    = (__nv_bfloat16*)symaddr_(g_QKV);
    __nv_bfloat16* tmpb   = (__nv_bfloat16*)symaddr_(g_tmpb);
    __nv_bfloat16* attnob = (__nv_bfloat16*)symaddr_(g_attnob);
    __nv_bfloat16* hb     = (__nv_bfloat16*)symaddr_(g_hb);
    __nv_bfloat16* Qf     = (__nv_bfloat16*)symaddr_(g_Qf);
    __nv_bfloat16* Kf     = (__nv_bfloat16*)symaddr_(g_Kf);
    __nv_bfloat16* KVT    = (__nv_bfloat16*)symaddr_(g_KVT);
    __nv_bfloat16* qkvWT  = (__nv_bfloat16*)symaddr_(g_qkvWT);
    __nv_bfloat16* oWT    = (__nv_bfloat16*)symaddr_(g_oWT);
    __nv_bfloat16* f1WT   = (__nv_bfloat16*)symaddr_(g_f1WT);
    __nv_bfloat16* f2WT   = (__nv_bfloat16*)symaddr_(g_f2WT);
    __nv_bfloat16* patchWT= (__nv_bfloat16*)symaddr_(g_patchWT);
    __nv_bfloat16* poolW1T= (__nv_bfloat16*)symaddr_(g_poolW1T);
    __nv_bfloat16* omT    = (__nv_bfloat16*)symaddr_(g_omT);

    static const int GEMM_SMEM = 3*2*128*SA*2;                       // 61440
    static const int ATTN_SMEM = (64*264 + 128*72)*2 + (256+128)*4;  // 53760
    cudaFuncSetAttribute(gemm_bf16<false,false>, cudaFuncAttributeMaxDynamicSharedMemorySize, GEMM_SMEM);
    cudaFuncSetAttribute(gemm_bf16<false,true>,  cudaFuncAttributeMaxDynamicSharedMemorySize, GEMM_SMEM);
    cudaFuncSetAttribute(gemm_bf16<true,true>,   cudaFuncAttributeMaxDynamicSharedMemorySize, GEMM_SMEM);
    cudaFuncSetAttribute(attn_tc,                cudaFuncAttributeMaxDynamicSharedMemorySize, ATTN_SMEM);

    const float SC = 0.35355339059327f;   // 64^{-1/4}
    WAll wa;
    for(int l=0;l<NL_;l++){
        wa.d[l*7+0] = { qW + (size_t)l*D_*D_,    qkvWT + (size_t)l*3*D_*D_,           D_,   D_,   D_,   1.f };
        wa.d[l*7+1] = { kW + (size_t)l*D_*D_,    qkvWT + (size_t)l*3*D_*D_ + D_*D_,   D_,   D_,   D_,   1.f };
        wa.d[l*7+2] = { vW + (size_t)l*D_*D_,    qkvWT + (size_t)l*3*D_*D_ + 2*D_*D_, D_,   D_,   D_,   1.f };
        wa.d[l*7+3] = { oW + (size_t)l*D_*D_,    oWT + (size_t)l*D_*D_,               D_,   D_,   D_,   1.f };
        wa.d[l*7+4] = { f1W + (size_t)l*D_*FFN_, f1WT + (size_t)l*FFN_*D_,            D_,   FFN_, D_,   1.f };
        wa.d[l*7+5] = { f2W + (size_t)l*FFN_*D_, f2WT + (size_t)l*D_*FFN_,            FFN_, D_,  FFN_, 1.f };
        wa.d[l*7+6] = { omega + (size_t)l*DH_*M_, omT + (size_t)l*M_*DH_,             DH_,  M_,   DH_,  SC  };
    }
    wa.d[14] = { patch_W, patchWT, C_*P_, D_,   KPATCH, 1.f };
    wa.d[15] = { poolW1,  poolW1T, D_,    HID_, D_,     1.f };
    wprep_all<<<dim3(32,32,16), dim3(32,8)>>>(wa);

    // patchify + patch embed + LN
    patchify_kernel<<<(B_*C_*T_ + 255)/256, 256>>>(x);
    gemm_bf16<false,false><<<dim3(D_/128, R_/128), 256, GEMM_SMEM>>>(tokb, patchWT, patch_b, nullptr, tmp, R_, D_, KPATCH);
    ln_kernel<false><<<R_/4, 256>>>(tmp, patch_g, patch_be, h);

    for(int l=0;l<NL_;l++){
        const float* obl = ob + l*D_;
        const __nv_bfloat16* omTl = omT + (size_t)l*M_*DH_;
        dim3 gq(D_/128, R_/128);

        // attention branch
        ln_kernel<true><<<R_/4, 256>>>(h, ln1_g + l*D_, ln1_b + l*D_, x1b);
        gemm_bf16<false,true><<<dim3(3*D_/128, R_/128), 256, GEMM_SMEM>>>(
            x1b, qkvWT + (size_t)l*3*D_*D_, nullptr, nullptr, QKV, R_, 3*D_, D_);
        phi_tc<<<dim3(B_*H_, LP_/128, M_/128), 256>>>(QKV,      omTl, Qf);
        phi_tc<<<dim3(B_*H_, LP_/128, M_/128), 256>>>(QKV + D_, omTl, Kf);
        kv_tc<<<B_*H_, 256>>>(Kf, QKV, KVT, Ksum);
        attn_tc<<<dim3(B_*H_, LP_/128), 256, ATTN_SMEM>>>(Qf, KVT, Ksum, attnob);
        gemm_bf16<false,false><<<gq, 256, GEMM_SMEM>>>(attnob, oWT + (size_t)l*D_*D_, obl, h, h, R_, D_, D_);

        // FFN branch
        ln_kernel<true><<<R_/4, 256>>>(h, ln2_g + l*D_, ln2_b + l*D_, x1b);
        gemm_bf16<true,true><<<dim3(FFN_/128, R_/128), 256, GEMM_SMEM>>>(
            x1b, f1WT + (size_t)l*FFN_*D_, f1b + l*FFN_, nullptr, tmpb, R_, FFN_, D_);
        gemm_bf16<false,false><<<gq, 256, GEMM_SMEM>>>(
            tmpb, f2WT + (size_t)l*D_*FFN_, f2b + l*D_, h, h, R_, D_, FFN_);
    }

    // pooling + head
    f2bf_kernel<<<(R_*D_/2 + 255)/256, 256>>>(h, hb, R_*D_/2);
    gemm_bf16<false,false><<<dim3(HID_/128, R_/128), 256, GEMM_SMEM>>>(hb, poolW1T, nullptr, nullptr, tmp, R_, HID_, D_);
    score2_kernel<<<R_/8, 256>>>(tmp, poolW2, sc);
    softmax_kernel<<<B_, 256>>>(sc, alpha);
    stats_kernel<<<dim3(B_, 4), 128>>>(h, alpha, feat);
    head_kernel<<<B_, 320>>>(feat, headW, headb, out);
}

// round 13
// speedup vs baseline: 6.2463x; 1.0742x over previous
#include <cuda_runtime.h>
#include <cuda_bf16.h>
#include <math.h>
#include <stdint.h>

// ---------------- problem dims ----------------
#define B_    32
#define C_    8
#define T_    20000
#define P_    25
#define D_    512
#define H_    8
#define M_    256
#define NL_   2
#define FFN_  1024
#define NC_   10
#define HID_  128
#define DH_   64
#define L_    800
#define R_    (B_*L_)        // 25600
#define KPATCH 224
#define LP_   896            // L padded to 7*128

// ---------------- scratch (device globals; zero-initialized at load) ----------------
__device__ float g_h[R_*D_];
__device__ float g_tmp[R_*D_];
__device__ float g_Ksum[B_*H_*M_];
__device__ float g_scores[R_];
__device__ float g_alpha[R_];
__device__ float g_feat[B_*2*D_];

__device__ __nv_bfloat16 g_tokb[R_*KPATCH];
__device__ __nv_bfloat16 g_x1b[R_*D_];
__device__ __nv_bfloat16 g_QKV[R_*3*D_];
__device__ __nv_bfloat16 g_tmpb[R_*FFN_];
__device__ __nv_bfloat16 g_attnob[R_*D_];
__device__ __nv_bfloat16 g_hb[R_*D_];
__device__ __nv_bfloat16 g_Qf[(size_t)B_*H_*LP_*M_];
__device__ __nv_bfloat16 g_KVT[B_*H_*DH_*M_];
// transposed bf16 weights WT[N][K]
__device__ __nv_bfloat16 g_qkvWT[NL_*3*D_*D_];
__device__ __nv_bfloat16 g_oWT[NL_*D_*D_];
__device__ __nv_bfloat16 g_f1WT[NL_*FFN_*D_];
__device__ __nv_bfloat16 g_f2WT[NL_*D_*FFN_];
__device__ __nv_bfloat16 g_patchWT[D_*KPATCH];
__device__ __nv_bfloat16 g_poolW1T[HID_*D_];
__device__ __nv_bfloat16 g_omT[NL_*M_*DH_];   // omega^T * sc, [256][64] per layer

// ---------------- batched weight prep ----------------
struct WDesc { const float* src; __nv_bfloat16* dst; int K, N, Kpad; float scale; };
struct WAll  { WDesc d[16]; };

__global__ void wprep_all(WAll wa){
    WDesc w = wa.d[blockIdx.z];
    int k0 = blockIdx.y*32, n0 = blockIdx.x*32;
    if(k0 >= w.Kpad || n0 >= w.N) return;
    __shared__ float t[32][33];
    int tx = threadIdx.x, ty = threadIdx.y;
    #pragma unroll
    for(int i=ty;i<32;i+=8){
        int k = k0+i, n = n0+tx;
        t[i][tx] = (k<w.K && n<w.N) ? w.src[(size_t)k*w.N+n] : 0.f;
    }
    __syncthreads();
    #pragma unroll
    for(int i=ty;i<32;i+=8){
        int n = n0+i, k = k0+tx;
        if(n<w.N && k<w.Kpad) w.dst[(size_t)n*w.Kpad+k] = __float2bfloat16(t[tx][i]*w.scale);
    }
}

// ---------------- patchify ----------------
__global__ void patchify_kernel(const float* __restrict__ x){
    int idx = blockIdx.x*blockDim.x + threadIdx.x;
    if(idx >= B_*C_*T_) return;
    int t  = idx % T_;
    int bc = idx / T_;
    int c  = bc % C_;
    int b  = bc / C_;
    int l = t / P_, p = t % P_;
    g_tokb[(size_t)(b*L_ + l)*KPATCH + c*P_ + p] = __float2bfloat16(x[idx]);
}

// ---------------- fp32 -> bf16 convert ----------------
__global__ void f2bf_kernel(const float* __restrict__ in, __nv_bfloat16* __restrict__ out, int n2){
    int i = blockIdx.x*blockDim.x + threadIdx.x;
    if(i >= n2) return;
    float2 v = ((const float2*)in)[i];
    ((__nv_bfloat162*)out)[i] = __floats2bfloat162_rn(v.x, v.y);
}

// ---------------- LayerNorm ----------------
template<bool BF16OUT>
__global__ void __launch_bounds__(256) ln_kernel(const float* __restrict__ X,
        const float* __restrict__ gg, const float* __restrict__ be, void* __restrict__ Yv){
    __shared__ float2 red[8];
    int t = threadIdx.x;
    int row = blockIdx.x*4 + (t>>6);
    int c = t & 63;
    const float4* xr = (const float4*)(X + (size_t)row*D_);
    float4 v0 = xr[c*2], v1 = xr[c*2+1];
    float s = v0.x+v0.y+v0.z+v0.w + v1.x+v1.y+v1.z+v1.w;
    float q = v0.x*v0.x+v0.y*v0.y+v0.z*v0.z+v0.w*v0.w
            + v1.x*v1.x+v1.y*v1.y+v1.z*v1.z+v1.w*v1.w;
    #pragma unroll
    for(int o=16;o;o>>=1){
        s += __shfl_xor_sync(0xffffffffu, s, o);
        q += __shfl_xor_sync(0xffffffffu, q, o);
    }
    int w = t>>5;
    if((t&31)==0) red[w] = make_float2(s, q);
    __syncthreads();
    float2 A = red[w], Bp = red[w^1];
    float mu  = (A.x + Bp.x) * (1.f/512.f);
    float msq = (A.y + Bp.y) * (1.f/512.f);
    float inv = rsqrtf(fmaxf(msq - mu*mu, 0.f) + 1e-5f);
    float4 g0 = ((const float4*)gg)[c*2], g1 = ((const float4*)gg)[c*2+1];
    float4 b0 = ((const float4*)be)[c*2], b1 = ((const float4*)be)[c*2+1];
    float y[8];
    y[0]=(v0.x-mu)*inv*g0.x+b0.x; y[1]=(v0.y-mu)*inv*g0.y+b0.y;
    y[2]=(v0.z-mu)*inv*g0.z+b0.z; y[3]=(v0.w-mu)*inv*g0.w+b0.w;
    y[4]=(v1.x-mu)*inv*g1.x+b1.x; y[5]=(v1.y-mu)*inv*g1.y+b1.y;
    y[6]=(v1.z-mu)*inv*g1.z+b1.z; y[7]=(v1.w-mu)*inv*g1.w+b1.w;
    if(BF16OUT){
        __nv_bfloat162 p[4];
        #pragma unroll
        for(int i=0;i<4;i++) p[i] = __floats2bfloat162_rn(y[2*i], y[2*i+1]);
        ((uint4*)((__nv_bfloat16*)Yv + (size_t)row*D_))[c] = *(uint4*)p;
    }else{
        float* yr = (float*)Yv + (size_t)row*D_;
        ((float4*)yr)[c*2]   = make_float4(y[0],y[1],y[2],y[3]);
        ((float4*)yr)[c*2+1] = make_float4(y[4],y[5],y[6],y[7]);
    }
}

// ---------------- mma / ldmatrix / cp.async primitives ----------------
__device__ __forceinline__ void mma_bf16(float* d, const uint32_t* a, const uint32_t* b){
    asm volatile("mma.sync.aligned.m16n8k16.row.col.f32.bf16.bf16.f32 "
        "{%0,%1,%2,%3}, {%4,%5,%6,%7}, {%8,%9}, {%0,%1,%2,%3};"
        : "+f"(d[0]), "+f"(d[1]), "+f"(d[2]), "+f"(d[3])
        : "r"(a[0]), "r"(a[1]), "r"(a[2]), "r"(a[3]), "r"(b[0]), "r"(b[1]));
}
__device__ __forceinline__ void ldsm4(uint32_t* r, uint32_t addr){
    asm volatile("ldmatrix.sync.aligned.m8n8.x4.shared.b16 {%0,%1,%2,%3},[%4];"
        : "=r"(r[0]),"=r"(r[1]),"=r"(r[2]),"=r"(r[3]) : "r"(addr));
}
__device__ __forceinline__ void cp16(uint32_t saddr, const void* g){
    asm volatile("cp.async.cg.shared.global [%0],[%1],16;\n" :: "r"(saddr), "l"(g));
}

// ---------------- bf16 TC GEMM: 256x128 tile, cp.async 3-stage + ldmatrix ----------------
#define KT 32
#define SA 40

template<bool GELU, bool BF16OUT>
__global__ void __launch_bounds__(256,1) gemm_bf16(
        const __nv_bfloat16* __restrict__ A, const __nv_bfloat16* __restrict__ BT,
        const float* __restrict__ bias, const float* __restrict__ res,
        void* __restrict__ Cv, int M, int N, int K)
{
    extern __shared__ __nv_bfloat16 smg[];
    __nv_bfloat16* As = smg;                 // [3][256*SA]
    __nv_bfloat16* Bs = smg + 3*256*SA;      // [3][128*SA]
    int tid = threadIdx.x;
    int row0 = blockIdx.y*256, col0 = blockIdx.x*128;
    int wid = tid>>5, lane = tid&31;
    int wm = (wid>>1)*64, wn = (wid&1)*64;   // warp tile 64x64
    int g = lane>>2, t2 = (lane&3)*2;
    int lr = tid>>2, lq = (tid&3)*8;

    uint32_t aBase = (uint32_t)__cvta_generic_to_shared(As);
    uint32_t bBase = (uint32_t)__cvta_generic_to_shared(Bs);
    const int aStg = 256*SA, bStg = 128*SA;
    const __nv_bfloat16* Ag = A + (size_t)(row0+lr)*K + lq;
    const __nv_bfloat16* Bg = BT + (size_t)(col0+lr)*K + lq;
    size_t rstep = (size_t)64*K;

    auto issue = [&](int stg, int k0){
        uint32_t sa = aBase + (stg*aStg + lr*SA + lq)*2;
        cp16(sa,              Ag + k0);
        cp16(sa + 64*SA*2,    Ag + rstep + k0);
        cp16(sa + 128*SA*2,   Ag + 2*rstep + k0);
        cp16(sa + 192*SA*2,   Ag + 3*rstep + k0);
        uint32_t sb = bBase + (stg*bStg + lr*SA + lq)*2;
        cp16(sb,              Bg + k0);
        cp16(sb + 64*SA*2,    Bg + rstep + k0);
        asm volatile("cp.async.commit_group;\n"::);
    };

    float acc[4][8][4];
    #pragma unroll
    for(int mi=0;mi<4;mi++)
        #pragma unroll
        for(int ni=0;ni<8;ni++)
            #pragma unroll
            for(int q=0;q<4;q++) acc[mi][ni][q]=0.f;

    int nsteps = K/KT;
    issue(0, 0);
    issue(1, KT);

    int aRow = wm + (lane&15);
    int aK   = (lane>>4)<<3;
    int bRow = wn + (lane&7) + ((lane>>4)<<3);
    int bK   = ((lane>>3)&1)<<3;

    for(int s=0; s<nsteps; s++){
        asm volatile("cp.async.wait_group 1;\n"::);
        __syncthreads();
        int buf = s % 3;
        uint32_t aS = aBase + buf*aStg*2;
        uint32_t bS = bBase + buf*bStg*2;
        #pragma unroll
        for(int ks=0; ks<2; ks++){
            int k0 = ks*16;
            uint32_t af[4][4], bv[4][4];
            #pragma unroll
            for(int mi=0;mi<4;mi++)
                ldsm4(af[mi], aS + (((aRow+mi*16)*SA) + k0 + aK)*2);
            #pragma unroll
            for(int p=0;p<4;p++)
                ldsm4(bv[p], bS + (((bRow+p*16)*SA) + k0 + bK)*2);
            #pragma unroll
            for(int mi=0;mi<4;mi++){
                #pragma unroll
                for(int ni=0;ni<8;ni++){
                    uint32_t bb[2] = { bv[ni>>1][(ni&1)*2], bv[ni>>1][(ni&1)*2+1] };
                    mma_bf16(acc[mi][ni], af[mi], bb);
                }
            }
        }
        if(s+2 < nsteps) issue((s+2)%3, (s+2)*KT);
        else asm volatile("cp.async.commit_group;\n"::);
    }

    #pragma unroll
    for(int mi=0;mi<4;mi++){
        #pragma unroll
        for(int ni=0;ni<8;ni++){
            int r  = row0 + wm + mi*16 + g;
            int cc = col0 + wn + ni*8 + t2;
            #pragma unroll
            for(int half=0; half<2; half++){
                int rr = r + half*8;
                float v0 = acc[mi][ni][half*2+0];
                float v1 = acc[mi][ni][half*2+1];
                if(bias){ v0 += bias[cc]; v1 += bias[cc+1]; }
                if(GELU){
                    v0 = 0.5f*v0*(1.f + erff(v0*0.70710678118f));
                    v1 = 0.5f*v1*(1.f + erff(v1*0.70710678118f));
                }
                if(res){
                    v0 += res[(size_t)rr*N + cc];
                    v1 += res[(size_t)rr*N + cc + 1];
                }
                if(BF16OUT){
                    *(__nv_bfloat162*)((__nv_bfloat16*)Cv + (size_t)rr*N + cc)
                        = __floats2bfloat162_rn(v0, v1);
                }else{
                    float* C = (float*)Cv;
                    C[(size_t)rr*N + cc]     = v0;
                    C[(size_t)rr*N + cc + 1] = v1;
                }
            }
        }
    }
}

// ---------------- FAVOR+ feature map via tensor cores (used for Q) ----------------
__global__ void __launch_bounds__(256) phi_tc(const __nv_bfloat16* __restrict__ X,
        const __nv_bfloat16* __restrict__ omT, __nv_bfloat16* __restrict__ F){
    __shared__ __nv_bfloat16 Xs[128*72];
    __shared__ __nv_bfloat16 Om[128*72];
    __shared__ float n2s[128];
    int bh = blockIdx.x, b = bh>>3, h = bh&7;
    int l0 = blockIdx.y*128;
    int nt = blockIdx.z;
    int tid = threadIdx.x, wid = tid>>5, lane = tid&31;
    {
        int r = tid>>1, off = (tid&1)*32;
        int l = l0 + r;
        uint4 v0 = make_uint4(0,0,0,0), v1 = v0, v2 = v0, v3 = v0;
        if(l < L_){
            const __nv_bfloat16* xr = X + (size_t)(b*L_ + l)*(3*D_) + h*DH_ + off;
            v0 = *(const uint4*)xr;
            v1 = *(const uint4*)(xr+8);
            v2 = *(const uint4*)(xr+16);
            v3 = *(const uint4*)(xr+24);
        }
        *(uint4*)&Xs[r*72+off]    = v0;
        *(uint4*)&Xs[r*72+off+8]  = v1;
        *(uint4*)&Xs[r*72+off+16] = v2;
        *(uint4*)&Xs[r*72+off+24] = v3;
        const __nv_bfloat16* orow = omT + (size_t)(nt*128 + r)*DH_ + off;
        *(uint4*)&Om[r*72+off]    = *(const uint4*)orow;
        *(uint4*)&Om[r*72+off+8]  = *(const uint4*)(orow+8);
        *(uint4*)&Om[r*72+off+16] = *(const uint4*)(orow+16);
        *(uint4*)&Om[r*72+off+24] = *(const uint4*)(orow+24);
    }
    __syncthreads();
    if(tid < 128){
        float s = 0.f;
        #pragma unroll
        for(int u=0;u<32;u++){
            float2 f = __bfloat1622float2(*(const __nv_bfloat162*)&Xs[tid*72 + 2*u]);
            s += f.x*f.x + f.y*f.y;
        }
        n2s[tid] = 0.0625f * s;   // 0.5 * sc^2, sc^2 = 1/8
    }
    __syncthreads();

    int wm = (wid>>2)*64, wn = (wid&3)*32;
    int g = lane>>2, t2 = (lane&3)*2;
    int aRow = wm + (lane&15), aK = (lane>>4)<<3;
    int bRow = wn + (lane&7) + ((lane>>4)<<3), bK = ((lane>>3)&1)<<3;
    uint32_t xB = (uint32_t)__cvta_generic_to_shared(Xs);
    uint32_t oB = (uint32_t)__cvta_generic_to_shared(Om);
    float acc[4][4][4];
    #pragma unroll
    for(int mi=0;mi<4;mi++)
        #pragma unroll
        for(int ni=0;ni<4;ni++)
            #pragma unroll
            for(int q=0;q<4;q++) acc[mi][ni][q]=0.f;

    #pragma unroll
    for(int ks=0;ks<4;ks++){
        int k0 = ks*16;
        uint32_t af[4][4], bfv[2][4];
        #pragma unroll
        for(int mi=0;mi<4;mi++)
            ldsm4(af[mi], xB + (((aRow+mi*16)*72) + k0 + aK)*2);
        #pragma unroll
        for(int p=0;p<2;p++)
            ldsm4(bfv[p], oB + (((bRow+p*16)*72) + k0 + bK)*2);
        #pragma unroll
        for(int mi=0;mi<4;mi++){
            #pragma unroll
            for(int ni=0;ni<4;ni++){
                uint32_t bb[2] = { bfv[ni>>1][(ni&1)*2], bfv[ni>>1][(ni&1)*2+1] };
                mma_bf16(acc[mi][ni], af[mi], bb);
            }
        }
    }

    __nv_bfloat16* Fb = F + ((size_t)bh*LP_ + l0)*M_ + nt*128;
    #pragma unroll
    for(int mi=0;mi<4;mi++){
        #pragma unroll
        for(int ni=0;ni<4;ni++){
            int row = wm + mi*16 + g, col = wn + ni*8 + t2;
            float n2a = n2s[row], n2b = n2s[row+8];
            float e0 = __expf(acc[mi][ni][0]-n2a)*0.0625f;
            float e1 = __expf(acc[mi][ni][1]-n2a)*0.0625f;
            float e2 = __expf(acc[mi][ni][2]-n2b)*0.0625f;
            float e3 = __expf(acc[mi][ni][3]-n2b)*0.0625f;
            *(__nv_bfloat162*)&Fb[(size_t)row*M_ + col]     = __floats2bfloat162_rn(e0,e1);
            *(__nv_bfloat162*)&Fb[(size_t)(row+8)*M_ + col] = __floats2bfloat162_rn(e2,e3);
        }
    }
}

// ---------------- fused phi(K)+KV: KVT = (phi(K)^T V)^T, Ksum = sum_l phi(K) ----------------
__global__ void __launch_bounds__(256) kvphi_tc(const __nv_bfloat16* __restrict__ QKV,
        const __nv_bfloat16* __restrict__ omT,
        __nv_bfloat16* __restrict__ KVT, float* __restrict__ Ksum){
    extern __shared__ char smraw[];
    __nv_bfloat16* Om  = (__nv_bfloat16*)smraw;          // [256*72]
    __nv_bfloat16* Ks  = Om + 256*72;                    // [32*72]
    __nv_bfloat16* VT  = Ks + 32*72;                     // [64*40]
    __nv_bfloat16* KfT = VT + 64*40;                     // [256*40]
    float* n2s  = (float*)(KfT + 256*40);                // [32]
    float* ksum = n2s + 32;                              // [256]
    int bh = blockIdx.x, b = bh>>3, h = bh&7;
    int t = threadIdx.x, wid = t>>5, lane = t&31;
    int g = lane>>2, t2 = (lane&3)*2;

    // load omega [256][64] into smem (stride 72)
    {
        int off = (t&1)*32;
        #pragma unroll
        for(int rr=0;rr<2;rr++){
            int r = rr*128 + (t>>1);
            const __nv_bfloat16* orow = omT + (size_t)r*DH_ + off;
            *(uint4*)&Om[r*72+off]    = *(const uint4*)orow;
            *(uint4*)&Om[r*72+off+8]  = *(const uint4*)(orow+8);
            *(uint4*)&Om[r*72+off+16] = *(const uint4*)(orow+16);
            *(uint4*)&Om[r*72+off+24] = *(const uint4*)(orow+24);
        }
    }
    ksum[t] = 0.f;

    // kv accumulators (m x d)
    int wm = (wid>>1)*64, wn = (wid&1)*32;
    float acc[4][4][4];
    #pragma unroll
    for(int mi=0;mi<4;mi++)
        #pragma unroll
        for(int ni=0;ni<4;ni++)
            #pragma unroll
            for(int q=0;q<4;q++) acc[mi][ni][q]=0.f;

    // phi partition: each warp owns 32 m-columns
    int pwn = wid*32;
    int aK = (lane>>4)<<3;
    int bK = ((lane>>3)&1)<<3;
    int pbRow = pwn + (lane&7) + ((lane>>4)<<3);
    uint32_t ksB = (uint32_t)__cvta_generic_to_shared(Ks);
    uint32_t omB = (uint32_t)__cvta_generic_to_shared(Om);

    const __nv_bfloat16* Vb = QKV + ((size_t)b*L_)*(3*D_) + 2*D_ + h*DH_;
    int lrow = t>>3, lj = t&7;
    int krow = t>>3, koff = (t&7)*8;

    __syncthreads();

    for(int l0=0;l0<L_;l0+=32){
        // load K chunk [32 l][64 d]
        *(uint4*)&Ks[krow*72 + koff] =
            *(const uint4*)&QKV[((size_t)(b*L_ + l0 + krow))*(3*D_) + D_ + h*DH_ + koff];
        // load V chunk transposed -> VT[d][l]
        {
            uint4 v = *(const uint4*)&Vb[(size_t)(l0+lrow)*(3*D_) + lj*8];
            const __nv_bfloat16* pv = (const __nv_bfloat16*)&v;
            #pragma unroll
            for(int i=0;i<8;i++) VT[(lj*8+i)*40 + lrow] = pv[i];
        }
        __syncthreads();
        if(t < 32){
            float s = 0.f;
            #pragma unroll
            for(int u=0;u<32;u++){
                float2 f = __bfloat1622float2(*(const __nv_bfloat162*)&Ks[t*72 + 2*u]);
                s += f.x*f.x + f.y*f.y;
            }
            n2s[t] = 0.0625f*s;
        }
        __syncthreads();

        // phi mma: [32 l] x [32 m/warp] x 64
        float pacc[2][4][4];
        #pragma unroll
        for(int mi=0;mi<2;mi++)
            #pragma unroll
            for(int ni=0;ni<4;ni++)
                #pragma unroll
                for(int q=0;q<4;q++) pacc[mi][ni][q]=0.f;
        #pragma unroll
        for(int ks_=0;ks_<4;ks_++){
            int k0 = ks_*16;
            uint32_t af[2][4], bv[2][4];
            #pragma unroll
            for(int mi=0;mi<2;mi++)
                ldsm4(af[mi], ksB + ((((lane&15) + mi*16)*72) + k0 + aK)*2);
            #pragma unroll
            for(int p=0;p<2;p++)
                ldsm4(bv[p], omB + (((pbRow + p*16)*72) + k0 + bK)*2);
            #pragma unroll
            for(int mi=0;mi<2;mi++){
                #pragma unroll
                for(int ni=0;ni<4;ni++){
                    uint32_t bb[2] = { bv[ni>>1][(ni&1)*2], bv[ni>>1][(ni&1)*2+1] };
                    mma_bf16(pacc[mi][ni], af[mi], bb);
                }
            }
        }
        // epilogue: exp -> KfT[m][l], ksum partials
        float kp[4][2];
        #pragma unroll
        for(int ni=0;ni<4;ni++){ kp[ni][0]=0.f; kp[ni][1]=0.f; }
        #pragma unroll
        for(int mi=0;mi<2;mi++){
            #pragma unroll
            for(int ni=0;ni<4;ni++){
                int row = mi*16 + g;
                int col = pwn + ni*8 + t2;
                float e0 = __expf(pacc[mi][ni][0] - n2s[row])*0.0625f;
                float e1 = __expf(pacc[mi][ni][1] - n2s[row])*0.0625f;
                float e2 = __expf(pacc[mi][ni][2] - n2s[row+8])*0.0625f;
                float e3 = __expf(pacc[mi][ni][3] - n2s[row+8])*0.0625f;
                __nv_bfloat16 b0 = __float2bfloat16(e0), b1 = __float2bfloat16(e1);
                __nv_bfloat16 b2 = __float2bfloat16(e2), b3 = __float2bfloat16(e3);
                KfT[col*40 + row]         = b0;
                KfT[(col+1)*40 + row]     = b1;
                KfT[col*40 + row+8]       = b2;
                KfT[(col+1)*40 + row+8]   = b3;
                kp[ni][0] += __bfloat162float(b0) + __bfloat162float(b2);
                kp[ni][1] += __bfloat162float(b1) + __bfloat162float(b3);
            }
        }
        #pragma unroll
        for(int ni=0;ni<4;ni++){
            float v0 = kp[ni][0], v1 = kp[ni][1];
            #pragma unroll
            for(int o=4;o<32;o<<=1){
                v0 += __shfl_xor_sync(0xffffffffu, v0, o);
                v1 += __shfl_xor_sync(0xffffffffu, v1, o);
            }
            if(lane < 4){
                int col = pwn + ni*8 + lane*2;
                ksum[col]   += v0;
                ksum[col+1] += v1;
            }
        }
        __syncthreads();   // KfT ready

        // kv mma: KVT accum [m x d] over 32 l
        #pragma unroll
        for(int kk=0;kk<2;kk++){
            int k0 = kk*16;
            uint32_t a[4][4], bb[4][2];
            #pragma unroll
            for(int mi=0;mi<4;mi++){
                int row = wm + mi*16 + g;
                a[mi][0] = *(const uint32_t*)&KfT[row*40 + k0+t2];
                a[mi][1] = *(const uint32_t*)&KfT[(row+8)*40 + k0+t2];
                a[mi][2] = *(const uint32_t*)&KfT[row*40 + k0+t2+8];
                a[mi][3] = *(const uint32_t*)&KfT[(row+8)*40 + k0+t2+8];
            }
            #pragma unroll
            for(int ni=0;ni<4;ni++){
                int n = wn + ni*8 + g;
                bb[ni][0] = *(const uint32_t*)&VT[n*40 + k0+t2];
                bb[ni][1] = *(const uint32_t*)&VT[n*40 + k0+t2+8];
            }
            #pragma unroll
            for(int mi=0;mi<4;mi++)
                #pragma unroll
                for(int ni=0;ni<4;ni++)
                    mma_bf16(acc[mi][ni], a[mi], bb[ni]);
        }
        __syncthreads();   // protect Ks/VT/KfT overwrite next chunk
    }

    __nv_bfloat16* kvt = KVT + (size_t)bh*DH_*M_;
    #pragma unroll
    for(int mi=0;mi<4;mi++){
        #pragma unroll
        for(int ni=0;ni<4;ni++){
            int m = wm + mi*16 + g;
            int d = wn + ni*8 + t2;
            kvt[(size_t)d*M_ + m]       = __float2bfloat16(acc[mi][ni][0]);
            kvt[(size_t)(d+1)*M_ + m]   = __float2bfloat16(acc[mi][ni][1]);
            kvt[(size_t)d*M_ + m+8]     = __float2bfloat16(acc[mi][ni][2]);
            kvt[(size_t)(d+1)*M_ + m+8] = __float2bfloat16(acc[mi][ni][3]);
        }
    }
    Ksum[bh*M_ + t] = ksum[t];
}

// ---------------- attn out = (Qf @ KV) / max(Qf·Ksum, 1e-6), norm fused ----------------
__global__ void __launch_bounds__(256) attn_tc(const __nv_bfloat16* __restrict__ Qf,
        const __nv_bfloat16* __restrict__ KVT, const float* __restrict__ Ksum,
        __nv_bfloat16* __restrict__ out){
    extern __shared__ char smraw[];
    __nv_bfloat16* KVs = (__nv_bfloat16*)smraw;      // [64][264]
    __nv_bfloat16* Qs  = KVs + 64*264;               // [128][72]
    float* Kss = (float*)(Qs + 128*72);              // [256]
    float* nrm = Kss + 256;                          // [128]
    int bh = blockIdx.x, lt = blockIdx.y;
    int b = bh>>3, h = bh&7;
    int tid = threadIdx.x, wid = tid>>5, lane = tid&31;
    int g = lane>>2, t2 = (lane&3)*2;

    {
        const __nv_bfloat16* kvt = KVT + (size_t)bh*DH_*M_;
        int r = tid>>2, s4 = tid&3;
        #pragma unroll
        for(int i=0;i<8;i++){
            int q = s4*8 + i;
            *(uint4*)&KVs[r*264 + q*8] = *(const uint4*)&kvt[(size_t)r*M_ + q*8];
        }
    }
    Kss[tid] = Ksum[bh*M_ + tid];

    float acc[8][4];
    #pragma unroll
    for(int ni=0;ni<8;ni++)
        #pragma unroll
        for(int q=0;q<4;q++) acc[ni][q]=0.f;
    float nacc = 0.f;

    int l0 = lt*128;
    const __nv_bfloat16* Qb = Qf + ((size_t)bh*LP_ + l0)*M_;
    int aRow = wid*16 + (lane&15), aK = (lane>>4)<<3;
    int bRowB = (lane&7) + ((lane>>4)<<3), bK = ((lane>>3)&1)<<3;
    uint32_t qB = (uint32_t)__cvta_generic_to_shared(Qs);
    uint32_t kB = (uint32_t)__cvta_generic_to_shared(KVs);

    for(int kc=0;kc<4;kc++){
        __syncthreads();
        {
            int r = tid>>1, off = (tid&1)*32;
            const __nv_bfloat16* src = &Qb[(size_t)r*M_ + kc*64 + off];
            *(uint4*)&Qs[r*72+off]    = *(const uint4*)src;
            *(uint4*)&Qs[r*72+off+8]  = *(const uint4*)(src+8);
            *(uint4*)&Qs[r*72+off+16] = *(const uint4*)(src+16);
            *(uint4*)&Qs[r*72+off+24] = *(const uint4*)(src+24);
        }
        __syncthreads();
        {
            int rr = tid>>1, hf = (tid&1)*32;
            const __nv_bfloat16* qp = &Qs[rr*72 + hf];
            const float* kp = &Kss[kc*64 + hf];
            #pragma unroll
            for(int j=0;j<16;j++){
                float2 f = __bfloat1622float2(*(const __nv_bfloat162*)&qp[2*j]);
                nacc += f.x*kp[2*j] + f.y*kp[2*j+1];
            }
        }
        #pragma unroll
        for(int kk=0;kk<4;kk++){
            int k0 = kk*16;
            uint32_t a[4];
            ldsm4(a, qB + ((aRow*72) + k0 + aK)*2);
            uint32_t bv[4][4];
            #pragma unroll
            for(int p=0;p<4;p++)
                ldsm4(bv[p], kB + (((p*16+bRowB)*264) + kc*64 + k0 + bK)*2);
            #pragma unroll
            for(int ni=0;ni<8;ni++){
                uint32_t bb[2] = { bv[ni>>1][(ni&1)*2], bv[ni>>1][(ni&1)*2+1] };
                mma_bf16(acc[ni], a, bb);
            }
        }
    }
    nacc += __shfl_xor_sync(0xffffffffu, nacc, 1);
    if((tid&1)==0) nrm[tid>>1] = nacc;
    __syncthreads();

    int lr0 = l0 + wid*16 + g;
    float rn0 = 1.f/fmaxf(nrm[wid*16+g], 1e-6f);
    float rn1 = 1.f/fmaxf(nrm[wid*16+g+8], 1e-6f);
    #pragma unroll
    for(int ni=0;ni<8;ni++){
        int d = ni*8 + t2;
        if(lr0 < L_){
            __nv_bfloat16* o = out + ((size_t)(b*L_ + lr0))*D_ + h*DH_ + d;
            *(__nv_bfloat162*)o = __floats2bfloat162_rn(acc[ni][0]*rn0, acc[ni][1]*rn0);
        }
        if(lr0+8 < L_){
            __nv_bfloat16* o = out + ((size_t)(b*L_ + lr0 + 8))*D_ + h*DH_ + d;
            *(__nv_bfloat162*)o = __floats2bfloat162_rn(acc[ni][2]*rn1, acc[ni][3]*rn1);
        }
    }
}

// ---------------- pooling scores ----------------
__global__ void __launch_bounds__(256) score2_kernel(const float* __restrict__ Tt,
        const float* __restrict__ W2, float* __restrict__ sc){
    int r = blockIdx.x*8 + (threadIdx.x>>5);
    int lane = threadIdx.x & 31;
    const float* tr = Tt + (size_t)r*HID_;
    float s = 0.f;
    #pragma unroll
    for(int i=0;i<4;i++){
        int j = lane + 32*i;
        s += tanhf(tr[j]) * __ldg(&W2[j]);
    }
    #pragma unroll
    for(int o=16;o;o>>=1) s += __shfl_xor_sync(0xffffffffu, s, o);
    if(lane==0) sc[r] = s;
}

// ---------------- softmax over L ----------------
__global__ void __launch_bounds__(256) softmax_kernel(const float* __restrict__ sc,
        float* __restrict__ alpha){
    __shared__ float al[L_];
    __shared__ float red[32];
    int b = blockIdx.x, t = threadIdx.x;
    float lmax = -1e30f;
    for(int i=t;i<L_;i+=256){ float v = sc[b*L_+i]; al[i]=v; lmax=fmaxf(lmax,v); }
    #pragma unroll
    for(int o=16;o;o>>=1) lmax = fmaxf(lmax, __shfl_xor_sync(0xffffffffu, lmax, o));
    if((t&31)==0) red[t>>5] = lmax;
    __syncthreads();
    if(t < 32){
        float r = (t < 8) ? red[t] : -1e30f;
        #pragma unroll
        for(int o=4;o;o>>=1) r = fmaxf(r, __shfl_xor_sync(0xffffffffu, r, o));
        if(t==0) red[0] = r;
    }
    __syncthreads();
    float mx = red[0];
    __syncthreads();
    float ls = 0.f;
    for(int i=t;i<L_;i+=256){ float e = __expf(al[i]-mx); al[i]=e; ls += e; }
    #pragma unroll
    for(int o=16;o;o>>=1) ls += __shfl_xor_sync(0xffffffffu, ls, o);
    if((t&31)==0) red[t>>5] = ls;
    __syncthreads();
    if(t < 32){
        float r = (t < 8) ? red[t] : 0.f;
        #pragma unroll
        for(int o=4;o;o>>=1) r += __shfl_xor_sync(0xffffffffu, r, o);
        if(t==0) red[0] = r;
    }
    __syncthreads();
    float inv = 1.f/red[0];
    for(int i=t;i<L_;i+=256) alpha[b*L_+i] = al[i]*inv;
}

// ---------------- attentive stats ----------------
__global__ void __launch_bounds__(128) stats_kernel(const float* __restrict__ h,
        const float* __restrict__ alpha, float* __restrict__ feat){
    __shared__ float al[L_];
    int b = blockIdx.x;
    int dd = blockIdx.y*128 + threadIdx.x;
    for(int i=threadIdx.x;i<L_;i+=128) al[i] = alpha[b*L_+i];
    __syncthreads();
    float mu = 0.f, m2 = 0.f;
    for(int l=0;l<L_;l++){
        float a  = al[l];
        float hv = h[((size_t)(b*L_ + l))*D_ + dd];
        mu += a*hv;
        m2 += a*hv*hv;
    }
    feat[b*1024 + dd]       = mu;
    feat[b*1024 + 512 + dd] = sqrtf(fmaxf(m2 - mu*mu, 1e-8f));
}

// ---------------- final classifier head ----------------
__global__ void head_kernel(const float* __restrict__ feat, const float* __restrict__ W,
                            const float* __restrict__ bb, float* __restrict__ out){
    __shared__ float fs[1024];
    int b = blockIdx.x, t = threadIdx.x;   // 320 threads
    for(int i=t;i<1024;i+=320) fs[i] = feat[b*1024 + i];
    __syncthreads();
    int w = t >> 5, lane = t & 31;
    if(w < NC_){
        float s = 0.f;
        for(int k=lane;k<1024;k+=32) s += fs[k]*W[k*NC_ + w];
        #pragma unroll
        for(int o=16;o;o>>=1) s += __shfl_xor_sync(0xffffffffu, s, o);
        if(lane==0) out[b*NC_ + w] = s + bb[w];
    }
}

// ---------------- launch ----------------
template<typename T> static void* symaddr_(T& s){
    void* p = nullptr;
    cudaGetSymbolAddress(&p, s);
    return p;
}

extern "C" void kernel_launch(void* const* d_in, const int* in_sizes, int n_in,
                              void* d_out, int out_size){
    const float* x        = (const float*)d_in[0];
    const float* patch_W  = (const float*)d_in[1];
    const float* patch_b  = (const float*)d_in[2];
    const float* patch_g  = (const float*)d_in[3];
    const float* patch_be = (const float*)d_in[4];
    const float* ln1_g    = (const float*)d_in[5];
    const float* ln1_b    = (const float*)d_in[6];
    const float* qW       = (const float*)d_in[7];
    const float* kW       = (const float*)d_in[8];
    const float* vW       = (const float*)d_in[9];
    const float* oW       = (const float*)d_in[10];
    const float* ob       = (const float*)d_in[11];
    const float* omega    = (const float*)d_in[12];
    const float* ln2_g    = (const float*)d_in[13];
    const float* ln2_b    = (const float*)d_in[14];
    const float* f1W      = (const float*)d_in[15];
    const float* f1b      = (const float*)d_in[16];
    const float* f2W      = (const float*)d_in[17];
    const float* f2b      = (const float*)d_in[18];
    const float* poolW1   = (const float*)d_in[19];
    const float* poolW2   = (const float*)d_in[20];
    const float* headW    = (const float*)d_in[21];
    const float* headb    = (const float*)d_in[22];
    float* out = (float*)d_out;

    float* h     = (float*)symaddr_(g_h);
    float* tmp   = (float*)symaddr_(g_tmp);
    float* Ksum  = (float*)symaddr_(g_Ksum);
    float* sc    = (float*)symaddr_(g_scores);
    float* alpha = (float*)symaddr_(g_alpha);
    float* feat  = (float*)symaddr_(g_feat);
    __nv_bfloat16* tokb   = (__nv_bfloat16*)symaddr_(g_tokb);
    __nv_bfloat16* x1b    = (__nv_bfloat16*)symaddr_(g_x1b);
    __nv_bfloat16* QKV    = (__nv_bfloat16*)symaddr_(g_QKV);
    __nv_bfloat16* tmpb   = (__nv_bfloat16*)symaddr_(g_tmpb);
    __nv_bfloat16* attnob = (__nv_bfloat16*)symaddr_(g_attnob);
    __nv_bfloat16* hb     = (__nv_bfloat16*)symaddr_(g_hb);
    __nv_bfloat16* Qf     = (__nv_bfloat16*)symaddr_(g_Qf);
    __nv_bfloat16* KVT    = (__nv_bfloat16*)symaddr_(g_KVT);
    __nv_bfloat16* qkvWT  = (__nv_bfloat16*)symaddr_(g_qkvWT);
    __nv_bfloat16* oWT    = (__nv_bfloat16*)symaddr_(g_oWT);
    __nv_bfloat16* f1WT   = (__nv_bfloat16*)symaddr_(g_f1WT);
    __nv_bfloat16* f2WT   = (__nv_bfloat16*)symaddr_(g_f2WT);
    __nv_bfloat16* patchWT= (__nv_bfloat16*)symaddr_(g_patchWT);
    __nv_bfloat16* poolW1T= (__nv_bfloat16*)symaddr_(g_poolW1T);
    __nv_bfloat16* omT    = (__nv_bfloat16*)symaddr_(g_omT);

    static const int GEMM_SMEM  = 3*(256+128)*SA*2;                  // 92160
    static const int ATTN_SMEM  = (64*264 + 128*72)*2 + (256+128)*4; // 53760
    static const int KVPHI_SMEM = (256*72 + 32*72 + 64*40 + 256*40)*2 + (32+256)*4; // 68224
    cudaFuncSetAttribute(gemm_bf16<false,false>, cudaFuncAttributeMaxDynamicSharedMemorySize, GEMM_SMEM);
    cudaFuncSetAttribute(gemm_bf16<false,true>,  cudaFuncAttributeMaxDynamicSharedMemorySize, GEMM_SMEM);
    cudaFuncSetAttribute(gemm_bf16<true,true>,   cudaFuncAttributeMaxDynamicSharedMemorySize, GEMM_SMEM);
    cudaFuncSetAttribute(attn_tc,                cudaFuncAttributeMaxDynamicSharedMemorySize, ATTN_SMEM);
    cudaFuncSetAttribute(kvphi_tc,               cudaFuncAttributeMaxDynamicSharedMemorySize, KVPHI_SMEM);

    const float SC = 0.35355339059327f;   // 64^{-1/4}
    WAll wa;
    for(int l=0;l<NL_;l++){
        wa.d[l*7+0] = { qW + (size_t)l*D_*D_,    qkvWT + (size_t)l*3*D_*D_,           D_,   D_,   D_,   1.f };
        wa.d[l*7+1] = { kW + (size_t)l*D_*D_,    qkvWT + (size_t)l*3*D_*D_ + D_*D_,   D_,   D_,   D_,   1.f };
        wa.d[l*7+2] = { vW + (size_t)l*D_*D_,    qkvWT + (size_t)l*3*D_*D_ + 2*D_*D_, D_,   D_,   D_,   1.f };
        wa.d[l*7+3] = { oW + (size_t)l*D_*D_,    oWT + (size_t)l*D_*D_,               D_,   D_,   D_,   1.f };
        wa.d[l*7+4] = { f1W + (size_t)l*D_*FFN_, f1WT + (size_t)l*FFN_*D_,            D_,   FFN_, D_,   1.f };
        wa.d[l*7+5] = { f2W + (size_t)l*FFN_*D_, f2WT + (size_t)l*D_*FFN_,            FFN_, D_,   FFN_, 1.f };
        wa.d[l*7+6] = { omega + (size_t)l*DH_*M_, omT + (size_t)l*M_*DH_,             DH_,  M_,   DH_,  SC  };
    }
    wa.d[14] = { patch_W, patchWT, C_*P_, D_,   KPATCH, 1.f };
    wa.d[15] = { poolW1,  poolW1T, D_,    HID_, D_,     1.f };
    wprep_all<<<dim3(32,32,16), dim3(32,8)>>>(wa);

    // patchify + patch embed + LN
    patchify_kernel<<<(B_*C_*T_ + 255)/256, 256>>>(x);
    gemm_bf16<false,false><<<dim3(D_/128, R_/256), 256, GEMM_SMEM>>>(tokb, patchWT, patch_b, nullptr, tmp, R_, D_, KPATCH);
    ln_kernel<false><<<R_/4, 256>>>(tmp, patch_g, patch_be, h);

    for(int l=0;l<NL_;l++){
        const float* obl = ob + l*D_;
        const __nv_bfloat16* omTl = omT + (size_t)l*M_*DH_;
        dim3 gq(D_/128, R_/256);

        // attention branch
        ln_kernel<true><<<R_/4, 256>>>(h, ln1_g + l*D_, ln1_b + l*D_, x1b);
        gemm_bf16<false,true><<<dim3(3*D_/128, R_/256), 256, GEMM_SMEM>>>(
            x1b, qkvWT + (size_t)l*3*D_*D_, nullptr, nullptr, QKV, R_, 3*D_, D_);
        kvphi_tc<<<B_*H_, 256, KVPHI_SMEM>>>(QKV, omTl, KVT, Ksum);
        phi_tc<<<dim3(B_*H_, LP_/128, M_/128), 256>>>(QKV, omTl, Qf);
        attn_tc<<<dim3(B_*H_, LP_/128), 256, ATTN_SMEM>>>(Qf, KVT, Ksum, attnob);
        gemm_bf16<false,false><<<gq, 256, GEMM_SMEM>>>(attnob, oWT + (size_t)l*D_*D_, obl, h, h, R_, D_, D_);

        // FFN branch
        ln_kernel<true><<<R_/4, 256>>>(h, ln2_g + l*D_, ln2_b + l*D_, x1b);
        gemm_bf16<true,true><<<dim3(FFN_/128, R_/256), 256, GEMM_SMEM>>>(
            x1b, f1WT + (size_t)l*FFN_*D_, f1b + l*FFN_, nullptr, tmpb, R_, FFN_, D_);
        gemm_bf16<false,false><<<gq, 256, GEMM_SMEM>>>(
            tmpb, f2WT + (size_t)l*D_*FFN_, f2b + l*D_, h, h, R_, D_, FFN_);
    }

    // pooling + head
    f2bf_kernel<<<(R_*D_/2 + 255)/256, 256>>>(h, hb, R_*D_/2);
    gemm_bf16<false,false><<<dim3(HID_/128, R_/256), 256, GEMM_SMEM>>>(hb, poolW1T, nullptr, nullptr, tmp, R_, HID_, D_);
    score2_kernel<<<R_/8, 256>>>(tmp, poolW2, sc);
    softmax_kernel<<<B_, 256>>>(sc, alpha);
    stats_kernel<<<dim3(B_, 4), 128>>>(h, alpha, feat);
    head_kernel<<<B_, 320>>>(feat, headW, headb, out);
}

// round 17
// speedup vs baseline: 6.6544x; 1.0653x over previous
#include <cuda_runtime.h>
#include <cuda_bf16.h>
#include <math.h>
#include <stdint.h>

// ---------------- problem dims ----------------
#define B_    32
#define C_    8
#define T_    20000
#define P_    25
#define D_    512
#define H_    8
#define M_    256
#define NL_   2
#define FFN_  1024
#define NC_   10
#define HID_  128
#define DH_   64
#define L_    800
#define R_    (B_*L_)        // 25600
#define KPATCH 256
#define LP_   896

// ---------------- scratch (device globals; zero-initialized at load) ----------------
__device__ float g_h[R_*D_];
__device__ float g_tmp[R_*D_];
__device__ float g_Ksum[B_*H_*M_];
__device__ float g_scores[R_];
__device__ float g_alpha[R_];
__device__ float g_feat[B_*2*D_];

__device__ __nv_bfloat16 g_tokb[(size_t)R_*KPATCH];
__device__ __nv_bfloat16 g_x1b[R_*D_];
__device__ __nv_bfloat16 g_QKV[R_*3*D_];
__device__ __nv_bfloat16 g_tmpb[R_*FFN_];
__device__ __nv_bfloat16 g_attnob[R_*D_];
__device__ __nv_bfloat16 g_hb[R_*D_];
__device__ __nv_bfloat16 g_KVT[B_*H_*DH_*M_];
// transposed bf16 weights WT[N][K]
__device__ __nv_bfloat16 g_qkvWT[NL_*3*D_*D_];
__device__ __nv_bfloat16 g_oWT[NL_*D_*D_];
__device__ __nv_bfloat16 g_f1WT[NL_*FFN_*D_];
__device__ __nv_bfloat16 g_f2WT[NL_*D_*FFN_];
__device__ __nv_bfloat16 g_patchWT[D_*KPATCH];
__device__ __nv_bfloat16 g_poolW1T[HID_*D_];
__device__ __nv_bfloat16 g_omT[NL_*M_*DH_];   // omega^T * sc, [256][64] per layer

// ---------------- batched weight prep ----------------
struct WDesc { const float* src; __nv_bfloat16* dst; int K, N, Kpad; float scale; };
struct WAll  { WDesc d[16]; };

__global__ void wprep_all(WAll wa){
    WDesc w = wa.d[blockIdx.z];
    int k0 = blockIdx.y*32, n0 = blockIdx.x*32;
    if(k0 >= w.Kpad || n0 >= w.N) return;
    __shared__ float t[32][33];
    int tx = threadIdx.x, ty = threadIdx.y;
    #pragma unroll
    for(int i=ty;i<32;i+=8){
        int k = k0+i, n = n0+tx;
        t[i][tx] = (k<w.K && n<w.N) ? w.src[(size_t)k*w.N+n] : 0.f;
    }
    __syncthreads();
    #pragma unroll
    for(int i=ty;i<32;i+=8){
        int n = n0+i, k = k0+tx;
        if(n<w.N && k<w.Kpad) w.dst[(size_t)n*w.Kpad+k] = __float2bfloat16(t[tx][i]*w.scale);
    }
}

// ---------------- patchify ----------------
__global__ void patchify_kernel(const float* __restrict__ x){
    int idx = blockIdx.x*blockDim.x + threadIdx.x;
    if(idx >= B_*C_*T_) return;
    int t  = idx % T_;
    int bc = idx / T_;
    int c  = bc % C_;
    int b  = bc / C_;
    int l = t / P_, p = t % P_;
    g_tokb[(size_t)(b*L_ + l)*KPATCH + c*P_ + p] = __float2bfloat16(x[idx]);
}

// ---------------- LayerNorm ----------------
template<bool BF16OUT>
__global__ void __launch_bounds__(256) ln_kernel(const float* __restrict__ X,
        const float* __restrict__ gg, const float* __restrict__ be, void* __restrict__ Yv){
    __shared__ float2 red[8];
    int t = threadIdx.x;
    int row = blockIdx.x*4 + (t>>6);
    int c = t & 63;
    const float4* xr = (const float4*)(X + (size_t)row*D_);
    float4 v0 = xr[c*2], v1 = xr[c*2+1];
    float s = v0.x+v0.y+v0.z+v0.w + v1.x+v1.y+v1.z+v1.w;
    float q = v0.x*v0.x+v0.y*v0.y+v0.z*v0.z+v0.w*v0.w
            + v1.x*v1.x+v1.y*v1.y+v1.z*v1.z+v1.w*v1.w;
    #pragma unroll
    for(int o=16;o;o>>=1){
        s += __shfl_xor_sync(0xffffffffu, s, o);
        q += __shfl_xor_sync(0xffffffffu, q, o);
    }
    int w = t>>5;
    if((t&31)==0) red[w] = make_float2(s, q);
    __syncthreads();
    float2 A = red[w], Bp = red[w^1];
    float mu  = (A.x + Bp.x) * (1.f/512.f);
    float msq = (A.y + Bp.y) * (1.f/512.f);
    float inv = rsqrtf(fmaxf(msq - mu*mu, 0.f) + 1e-5f);
    float4 g0 = ((const float4*)gg)[c*2], g1 = ((const float4*)gg)[c*2+1];
    float4 b0 = ((const float4*)be)[c*2], b1 = ((const float4*)be)[c*2+1];
    float y[8];
    y[0]=(v0.x-mu)*inv*g0.x+b0.x; y[1]=(v0.y-mu)*inv*g0.y+b0.y;
    y[2]=(v0.z-mu)*inv*g0.z+b0.z; y[3]=(v0.w-mu)*inv*g0.w+b0.w;
    y[4]=(v1.x-mu)*inv*g1.x+b1.x; y[5]=(v1.y-mu)*inv*g1.y+b1.y;
    y[6]=(v1.z-mu)*inv*g1.z+b1.z; y[7]=(v1.w-mu)*inv*g1.w+b1.w;
    if(BF16OUT){
        __nv_bfloat162 p[4];
        #pragma unroll
        for(int i=0;i<4;i++) p[i] = __floats2bfloat162_rn(y[2*i], y[2*i+1]);
        ((uint4*)((__nv_bfloat16*)Yv + (size_t)row*D_))[c] = *(uint4*)p;
    }else{
        float* yr = (float*)Yv + (size_t)row*D_;
        ((float4*)yr)[c*2]   = make_float4(y[0],y[1],y[2],y[3]);
        ((float4*)yr)[c*2+1] = make_float4(y[4],y[5],y[6],y[7]);
    }
}

// ---------------- mma / ldmatrix / cp.async primitives ----------------
__device__ __forceinline__ void mma_bf16(float* d, const uint32_t* a, const uint32_t* b){
    asm volatile("mma.sync.aligned.m16n8k16.row.col.f32.bf16.bf16.f32 "
        "{%0,%1,%2,%3}, {%4,%5,%6,%7}, {%8,%9}, {%0,%1,%2,%3};"
        : "+f"(d[0]), "+f"(d[1]), "+f"(d[2]), "+f"(d[3])
        : "r"(a[0]), "r"(a[1]), "r"(a[2]), "r"(a[3]), "r"(b[0]), "r"(b[1]));
}
__device__ __forceinline__ void ldsm4(uint32_t* r, uint32_t addr){
    asm volatile("ldmatrix.sync.aligned.m8n8.x4.shared.b16 {%0,%1,%2,%3},[%4];"
        : "=r"(r[0]),"=r"(r[1]),"=r"(r[2]),"=r"(r[3]) : "r"(addr));
}
__device__ __forceinline__ void cp16(uint32_t saddr, const void* g){
    asm volatile("cp.async.cg.shared.global [%0],[%1],16;\n" :: "r"(saddr), "l"(g));
}

// ---------------- bf16 TC GEMM: 256x128 tile, cp.async 3-stage + ldmatrix ----------------
#define KT 32
#define SA 40

template<bool GELU, bool BF16OUT>
__global__ void __launch_bounds__(256,1) gemm_bf16(
        const __nv_bfloat16* __restrict__ A, const __nv_bfloat16* __restrict__ BT,
        const float* __restrict__ bias, const float* __restrict__ res,
        void* __restrict__ Cv, __nv_bfloat16* __restrict__ Cb, int M, int N, int K)
{
    extern __shared__ __nv_bfloat16 smg[];
    __nv_bfloat16* As = smg;                 // [3][256*SA]
    __nv_bfloat16* Bs = smg + 3*256*SA;      // [3][128*SA]
    int tid = threadIdx.x;
    int row0 = blockIdx.y*256, col0 = blockIdx.x*128;
    int wid = tid>>5, lane = tid&31;
    int wm = (wid>>1)*64, wn = (wid&1)*64;   // warp tile 64x64
    int g = lane>>2, t2 = (lane&3)*2;
    int lr = tid>>2, lq = (tid&3)*8;

    uint32_t aBase = (uint32_t)__cvta_generic_to_shared(As);
    uint32_t bBase = (uint32_t)__cvta_generic_to_shared(Bs);
    const int aStg = 256*SA, bStg = 128*SA;
    const __nv_bfloat16* Ag = A + (size_t)(row0+lr)*K + lq;
    const __nv_bfloat16* Bg = BT + (size_t)(col0+lr)*K + lq;
    size_t rstep = (size_t)64*K;

    auto issue = [&](int stg, int k0){
        uint32_t sa = aBase + (stg*aStg + lr*SA + lq)*2;
        cp16(sa,              Ag + k0);
        cp16(sa + 64*SA*2,    Ag + rstep + k0);
        cp16(sa + 128*SA*2,   Ag + 2*rstep + k0);
        cp16(sa + 192*SA*2,   Ag + 3*rstep + k0);
        uint32_t sb = bBase + (stg*bStg + lr*SA + lq)*2;
        cp16(sb,              Bg + k0);
        cp16(sb + 64*SA*2,    Bg + rstep + k0);
        asm volatile("cp.async.commit_group;\n"::);
    };

    float acc[4][8][4];
    #pragma unroll
    for(int mi=0;mi<4;mi++)
        #pragma unroll
        for(int ni=0;ni<8;ni++)
            #pragma unroll
            for(int q=0;q<4;q++) acc[mi][ni][q]=0.f;

    int nsteps = K/KT;
    issue(0, 0);
    issue(1, KT);

    int aRow = wm + (lane&15);
    int aK   = (lane>>4)<<3;
    int bRow = wn + (lane&7) + ((lane>>4)<<3);
    int bK   = ((lane>>3)&1)<<3;

    for(int s=0; s<nsteps; s++){
        asm volatile("cp.async.wait_group 1;\n"::);
        __syncthreads();
        int buf = s % 3;
        uint32_t aS = aBase + buf*aStg*2;
        uint32_t bS = bBase + buf*bStg*2;
        #pragma unroll
        for(int ks=0; ks<2; ks++){
            int k0 = ks*16;
            uint32_t af[4][4], bv[4][4];
            #pragma unroll
            for(int mi=0;mi<4;mi++)
                ldsm4(af[mi], aS + (((aRow+mi*16)*SA) + k0 + aK)*2);
            #pragma unroll
            for(int p=0;p<4;p++)
                ldsm4(bv[p], bS + (((bRow+p*16)*SA) + k0 + bK)*2);
            #pragma unroll
            for(int mi=0;mi<4;mi++){
                #pragma unroll
                for(int ni=0;ni<8;ni++){
                    uint32_t bb[2] = { bv[ni>>1][(ni&1)*2], bv[ni>>1][(ni&1)*2+1] };
                    mma_bf16(acc[mi][ni], af[mi], bb);
                }
            }
        }
        if(s+2 < nsteps) issue((s+2)%3, (s+2)*KT);
        else asm volatile("cp.async.commit_group;\n"::);
    }

    #pragma unroll
    for(int mi=0;mi<4;mi++){
        #pragma unroll
        for(int ni=0;ni<8;ni++){
            int r  = row0 + wm + mi*16 + g;
            int cc = col0 + wn + ni*8 + t2;
            #pragma unroll
            for(int half=0; half<2; half++){
                int rr = r + half*8;
                float v0 = acc[mi][ni][half*2+0];
                float v1 = acc[mi][ni][half*2+1];
                if(bias){ v0 += bias[cc]; v1 += bias[cc+1]; }
                if(GELU){
                    v0 = 0.5f*v0*(1.f + erff(v0*0.70710678118f));
                    v1 = 0.5f*v1*(1.f + erff(v1*0.70710678118f));
                }
                if(res){
                    v0 += res[(size_t)rr*N + cc];
                    v1 += res[(size_t)rr*N + cc + 1];
                }
                if(BF16OUT){
                    *(__nv_bfloat162*)((__nv_bfloat16*)Cv + (size_t)rr*N + cc)
                        = __floats2bfloat162_rn(v0, v1);
                }else{
                    float* C = (float*)Cv;
                    C[(size_t)rr*N + cc]     = v0;
                    C[(size_t)rr*N + cc + 1] = v1;
                    if(Cb)
                        *(__nv_bfloat162*)(Cb + (size_t)rr*N + cc)
                            = __floats2bfloat162_rn(v0, v1);
                }
            }
        }
    }
}

// ---------------- fused phi(K)+KV: KVT = (phi(K)^T V)^T, Ksum = sum_l phi(K) ----------------
__global__ void __launch_bounds__(256) kvphi_tc(const __nv_bfloat16* __restrict__ QKV,
        const __nv_bfloat16* __restrict__ omT,
        __nv_bfloat16* __restrict__ KVT, float* __restrict__ Ksum){
    extern __shared__ char smraw[];
    __nv_bfloat16* Om  = (__nv_bfloat16*)smraw;          // [256*72]
    __nv_bfloat16* Ks  = Om + 256*72;                    // [32*72]
    __nv_bfloat16* VT  = Ks + 32*72;                     // [64*40]
    __nv_bfloat16* KfT = VT + 64*40;                     // [256*40]
    float* n2s  = (float*)(KfT + 256*40);                // [32]
    float* ksum = n2s + 32;                              // [256]
    int bh = blockIdx.x, b = bh>>3, h = bh&7;
    int t = threadIdx.x, wid = t>>5, lane = t&31;
    int g = lane>>2, t2 = (lane&3)*2;

    {
        int off = (t&1)*32;
        #pragma unroll
        for(int rr=0;rr<2;rr++){
            int r = rr*128 + (t>>1);
            const __nv_bfloat16* orow = omT + (size_t)r*DH_ + off;
            *(uint4*)&Om[r*72+off]    = *(const uint4*)orow;
            *(uint4*)&Om[r*72+off+8]  = *(const uint4*)(orow+8);
            *(uint4*)&Om[r*72+off+16] = *(const uint4*)(orow+16);
            *(uint4*)&Om[r*72+off+24] = *(const uint4*)(orow+24);
        }
    }
    ksum[t] = 0.f;

    int wm = (wid>>1)*64, wn = (wid&1)*32;
    float acc[4][4][4];
    #pragma unroll
    for(int mi=0;mi<4;mi++)
        #pragma unroll
        for(int ni=0;ni<4;ni++)
            #pragma unroll
            for(int q=0;q<4;q++) acc[mi][ni][q]=0.f;

    int pwn = wid*32;
    int aK = (lane>>4)<<3;
    int bK = ((lane>>3)&1)<<3;
    int pbRow = pwn + (lane&7) + ((lane>>4)<<3);
    uint32_t ksB = (uint32_t)__cvta_generic_to_shared(Ks);
    uint32_t omB = (uint32_t)__cvta_generic_to_shared(Om);

    const __nv_bfloat16* Vb = QKV + ((size_t)b*L_)*(3*D_) + 2*D_ + h*DH_;
    int lrow = t>>3, lj = t&7;
    int krow = t>>3, koff = (t&7)*8;

    __syncthreads();

    for(int l0=0;l0<L_;l0+=32){
        *(uint4*)&Ks[krow*72 + koff] =
            *(const uint4*)&QKV[((size_t)(b*L_ + l0 + krow))*(3*D_) + D_ + h*DH_ + koff];
        {
            uint4 v = *(const uint4*)&Vb[(size_t)(l0+lrow)*(3*D_) + lj*8];
            const __nv_bfloat16* pv = (const __nv_bfloat16*)&v;
            #pragma unroll
            for(int i=0;i<8;i++) VT[(lj*8+i)*40 + lrow] = pv[i];
        }
        __syncthreads();
        if(t < 32){
            float s = 0.f;
            #pragma unroll
            for(int u=0;u<32;u++){
                float2 f = __bfloat1622float2(*(const __nv_bfloat162*)&Ks[t*72 + 2*u]);
                s += f.x*f.x + f.y*f.y;
            }
            n2s[t] = 0.0625f*s;
        }
        __syncthreads();

        float pacc[2][4][4];
        #pragma unroll
        for(int mi=0;mi<2;mi++)
            #pragma unroll
            for(int ni=0;ni<4;ni++)
                #pragma unroll
                for(int q=0;q<4;q++) pacc[mi][ni][q]=0.f;
        #pragma unroll
        for(int ks_=0;ks_<4;ks_++){
            int k0 = ks_*16;
            uint32_t af[2][4], bv[2][4];
            #pragma unroll
            for(int mi=0;mi<2;mi++)
                ldsm4(af[mi], ksB + ((((lane&15) + mi*16)*72) + k0 + aK)*2);
            #pragma unroll
            for(int p=0;p<2;p++)
                ldsm4(bv[p], omB + (((pbRow + p*16)*72) + k0 + bK)*2);
            #pragma unroll
            for(int mi=0;mi<2;mi++){
                #pragma unroll
                for(int ni=0;ni<4;ni++){
                    uint32_t bb[2] = { bv[ni>>1][(ni&1)*2], bv[ni>>1][(ni&1)*2+1] };
                    mma_bf16(pacc[mi][ni], af[mi], bb);
                }
            }
        }
        float kp[4][2];
        #pragma unroll
        for(int ni=0;ni<4;ni++){ kp[ni][0]=0.f; kp[ni][1]=0.f; }
        #pragma unroll
        for(int mi=0;mi<2;mi++){
            #pragma unroll
            for(int ni=0;ni<4;ni++){
                int row = mi*16 + g;
                int col = pwn + ni*8 + t2;
                float e0 = __expf(pacc[mi][ni][0] - n2s[row])*0.0625f;
                float e1 = __expf(pacc[mi][ni][1] - n2s[row])*0.0625f;
                float e2 = __expf(pacc[mi][ni][2] - n2s[row+8])*0.0625f;
                float e3 = __expf(pacc[mi][ni][3] - n2s[row+8])*0.0625f;
                __nv_bfloat16 b0 = __float2bfloat16(e0), b1 = __float2bfloat16(e1);
                __nv_bfloat16 b2 = __float2bfloat16(e2), b3 = __float2bfloat16(e3);
                KfT[col*40 + row]         = b0;
                KfT[(col+1)*40 + row]     = b1;
                KfT[col*40 + row+8]       = b2;
                KfT[(col+1)*40 + row+8]   = b3;
                kp[ni][0] += __bfloat162float(b0) + __bfloat162float(b2);
                kp[ni][1] += __bfloat162float(b1) + __bfloat162float(b3);
            }
        }
        #pragma unroll
        for(int ni=0;ni<4;ni++){
            float v0 = kp[ni][0], v1 = kp[ni][1];
            #pragma unroll
            for(int o=4;o<32;o<<=1){
                v0 += __shfl_xor_sync(0xffffffffu, v0, o);
                v1 += __shfl_xor_sync(0xffffffffu, v1, o);
            }
            if(lane < 4){
                int col = pwn + ni*8 + lane*2;
                ksum[col]   += v0;
                ksum[col+1] += v1;
            }
        }
        __syncthreads();

        #pragma unroll
        for(int kk=0;kk<2;kk++){
            int k0 = kk*16;
            uint32_t a[4][4], bb[4][2];
            #pragma unroll
            for(int mi=0;mi<4;mi++){
                int row = wm + mi*16 + g;
                a[mi][0] = *(const uint32_t*)&KfT[row*40 + k0+t2];
                a[mi][1] = *(const uint32_t*)&KfT[(row+8)*40 + k0+t2];
                a[mi][2] = *(const uint32_t*)&KfT[row*40 + k0+t2+8];
                a[mi][3] = *(const uint32_t*)&KfT[(row+8)*40 + k0+t2+8];
            }
            #pragma unroll
            for(int ni=0;ni<4;ni++){
                int n = wn + ni*8 + g;
                bb[ni][0] = *(const uint32_t*)&VT[n*40 + k0+t2];
                bb[ni][1] = *(const uint32_t*)&VT[n*40 + k0+t2+8];
            }
            #pragma unroll
            for(int mi=0;mi<4;mi++)
                #pragma unroll
                for(int ni=0;ni<4;ni++)
                    mma_bf16(acc[mi][ni], a[mi], bb[ni]);
        }
        __syncthreads();
    }

    __nv_bfloat16* kvt = KVT + (size_t)bh*DH_*M_;
    #pragma unroll
    for(int mi=0;mi<4;mi++){
        #pragma unroll
        for(int ni=0;ni<4;ni++){
            int m = wm + mi*16 + g;
            int d = wn + ni*8 + t2;
            kvt[(size_t)d*M_ + m]       = __float2bfloat16(acc[mi][ni][0]);
            kvt[(size_t)(d+1)*M_ + m]   = __float2bfloat16(acc[mi][ni][1]);
            kvt[(size_t)d*M_ + m+8]     = __float2bfloat16(acc[mi][ni][2]);
            kvt[(size_t)(d+1)*M_ + m+8] = __float2bfloat16(acc[mi][ni][3]);
        }
    }
    Ksum[bh*M_ + t] = ksum[t];
}

// ---------------- fused phi(Q)+attn: out = (phi(Q) @ KV) / max(phi(Q)·Ksum, 1e-6) ----------------
__global__ void __launch_bounds__(256) attn_fused(const __nv_bfloat16* __restrict__ QKV,
        const __nv_bfloat16* __restrict__ omT,
        const __nv_bfloat16* __restrict__ KVT, const float* __restrict__ Ksum,
        __nv_bfloat16* __restrict__ out){
    extern __shared__ char smraw[];
    __nv_bfloat16* KVs = (__nv_bfloat16*)smraw;      // [64][264]   33792 B
    __nv_bfloat16* Xq  = KVs + 64*264;               // [128][72]   18432 B
    __nv_bfloat16* Qs  = Xq + 128*72;                // [128][72]   18432 B
    __nv_bfloat16* Om  = Qs + 128*72;                // [64][72]     9216 B
    float* Kss = (float*)(Om + 64*72);               // [256]
    float* n2s = Kss + 256;                          // [128]
    int bh = blockIdx.x, lt = blockIdx.y;
    int b = bh>>3, h = bh&7;
    int tid = threadIdx.x, wid = tid>>5, lane = tid&31;
    int g = lane>>2, t2 = (lane&3)*2;
    int l0 = lt*128;

    // load KVT [64][256] -> KVs padded
    {
        const __nv_bfloat16* kvt = KVT + (size_t)bh*DH_*M_;
        int r = tid>>2, s4 = tid&3;
        #pragma unroll
        for(int i=0;i<8;i++){
            int q = s4*8 + i;
            *(uint4*)&KVs[r*264 + q*8] = *(const uint4*)&kvt[(size_t)r*M_ + q*8];
        }
    }
    Kss[tid] = Ksum[bh*M_ + tid];
    // load Q rows tile [128][64] (zero-padded beyond L_)
    {
        int r = tid>>1, off = (tid&1)*32;
        int l = l0 + r;
        uint4 v0 = make_uint4(0,0,0,0), v1 = v0, v2 = v0, v3 = v0;
        if(l < L_){
            const __nv_bfloat16* xr = QKV + (size_t)(b*L_ + l)*(3*D_) + h*DH_ + off;
            v0 = *(const uint4*)xr;
            v1 = *(const uint4*)(xr+8);
            v2 = *(const uint4*)(xr+16);
            v3 = *(const uint4*)(xr+24);
        }
        *(uint4*)&Xq[r*72+off]    = v0;
        *(uint4*)&Xq[r*72+off+8]  = v1;
        *(uint4*)&Xq[r*72+off+16] = v2;
        *(uint4*)&Xq[r*72+off+24] = v3;
    }
    __syncthreads();
    if(tid < 128){
        float s = 0.f;
        #pragma unroll
        for(int u=0;u<32;u++){
            float2 f = __bfloat1622float2(*(const __nv_bfloat162*)&Xq[tid*72 + 2*u]);
            s += f.x*f.x + f.y*f.y;
        }
        n2s[tid] = 0.0625f * s;   // 0.5 * sc^2, sc^2 = 1/8
    }

    float acc[8][4];
    #pragma unroll
    for(int ni=0;ni<8;ni++)
        #pragma unroll
        for(int q=0;q<4;q++) acc[ni][q]=0.f;
    float nacc0 = 0.f, nacc1 = 0.f;   // normalizer partials for rows (wid*16+g) and (+8)

    int aRow = wid*16 + (lane&15), aK = (lane>>4)<<3;
    int bRowB = (lane&7) + ((lane>>4)<<3), bK = ((lane>>3)&1)<<3;
    uint32_t xB = (uint32_t)__cvta_generic_to_shared(Xq);
    uint32_t qB = (uint32_t)__cvta_generic_to_shared(Qs);
    uint32_t kB = (uint32_t)__cvta_generic_to_shared(KVs);
    uint32_t oB = (uint32_t)__cvta_generic_to_shared(Om);

    for(int kc=0;kc<4;kc++){
        __syncthreads();   // protects Om/Qs from previous chunk's readers
        // load omega chunk: rows kc*64 .. +63 of omT[256][64]
        {
            int r = tid>>2, off = (tid&3)*16;
            const __nv_bfloat16* orow = omT + (size_t)(kc*64 + r)*DH_ + off;
            *(uint4*)&Om[r*72+off]   = *(const uint4*)orow;
            *(uint4*)&Om[r*72+off+8] = *(const uint4*)(orow+8);
        }
        __syncthreads();
        // phi mma: proj[128 l][64 m] = Xq @ Om^T  (k = 64)
        float pacc[8][4];
        #pragma unroll
        for(int ni=0;ni<8;ni++)
            #pragma unroll
            for(int q=0;q<4;q++) pacc[ni][q]=0.f;
        #pragma unroll
        for(int ks=0;ks<4;ks++){
            int k0 = ks*16;
            uint32_t a[4];
            ldsm4(a, xB + ((aRow*72) + k0 + aK)*2);
            uint32_t bv[4][4];
            #pragma unroll
            for(int p=0;p<4;p++)
                ldsm4(bv[p], oB + (((p*16+bRowB)*72) + k0 + bK)*2);
            #pragma unroll
            for(int ni=0;ni<8;ni++){
                uint32_t bb[2] = { bv[ni>>1][(ni&1)*2], bv[ni>>1][(ni&1)*2+1] };
                mma_bf16(pacc[ni], a, bb);
            }
        }
        // epilogue: exp -> Qs, accumulate normalizer
        {
            int row = wid*16 + g;
            float na = n2s[row], nb = n2s[row+8];
            #pragma unroll
            for(int ni=0;ni<8;ni++){
                int col = ni*8 + t2;
                float ks0 = Kss[kc*64 + col], ks1 = Kss[kc*64 + col + 1];
                float e0 = __expf(pacc[ni][0]-na)*0.0625f;
                float e1 = __expf(pacc[ni][1]-na)*0.0625f;
                float e2 = __expf(pacc[ni][2]-nb)*0.0625f;
                float e3 = __expf(pacc[ni][3]-nb)*0.0625f;
                __nv_bfloat162 p01 = __floats2bfloat162_rn(e0,e1);
                __nv_bfloat162 p23 = __floats2bfloat162_rn(e2,e3);
                *(__nv_bfloat162*)&Qs[row*72 + col]     = p01;
                *(__nv_bfloat162*)&Qs[(row+8)*72 + col] = p23;
                float2 f01 = __bfloat1622float2(p01);
                float2 f23 = __bfloat1622float2(p23);
                nacc0 += f01.x*ks0 + f01.y*ks1;
                nacc1 += f23.x*ks0 + f23.y*ks1;
            }
        }
        __syncthreads();   // Qs ready
        // attn mma over this k-chunk
        #pragma unroll
        for(int kk=0;kk<4;kk++){
            int k0 = kk*16;
            uint32_t a[4];
            ldsm4(a, qB + ((aRow*72) + k0 + aK)*2);
            uint32_t bv[4][4];
            #pragma unroll
            for(int p=0;p<4;p++)
                ldsm4(bv[p], kB + (((p*16+bRowB)*264) + kc*64 + k0 + bK)*2);
            #pragma unroll
            for(int ni=0;ni<8;ni++){
                uint32_t bb[2] = { bv[ni>>1][(ni&1)*2], bv[ni>>1][(ni&1)*2+1] };
                mma_bf16(acc[ni], a, bb);
            }
        }
    }
    // reduce normalizer across quad (lanes sharing the same row)
    nacc0 += __shfl_xor_sync(0xffffffffu, nacc0, 1);
    nacc0 += __shfl_xor_sync(0xffffffffu, nacc0, 2);
    nacc1 += __shfl_xor_sync(0xffffffffu, nacc1, 1);
    nacc1 += __shfl_xor_sync(0xffffffffu, nacc1, 2);

    int lr0 = l0 + wid*16 + g;
    float rn0 = 1.f/fmaxf(nacc0, 1e-6f);
    float rn1 = 1.f/fmaxf(nacc1, 1e-6f);
    #pragma unroll
    for(int ni=0;ni<8;ni++){
        int d = ni*8 + t2;
        if(lr0 < L_){
            __nv_bfloat16* o = out + ((size_t)(b*L_ + lr0))*D_ + h*DH_ + d;
            *(__nv_bfloat162*)o = __floats2bfloat162_rn(acc[ni][0]*rn0, acc[ni][1]*rn0);
        }
        if(lr0+8 < L_){
            __nv_bfloat16* o = out + ((size_t)(b*L_ + lr0 + 8))*D_ + h*DH_ + d;
            *(__nv_bfloat162*)o = __floats2bfloat162_rn(acc[ni][2]*rn1, acc[ni][3]*rn1);
        }
    }
}

// ---------------- pooling scores ----------------
__global__ void __launch_bounds__(256) score2_kernel(const float* __restrict__ Tt,
        const float* __restrict__ W2, float* __restrict__ sc){
    int r = blockIdx.x*8 + (threadIdx.x>>5);
    int lane = threadIdx.x & 31;
    const float* tr = Tt + (size_t)r*HID_;
    float s = 0.f;
    #pragma unroll
    for(int i=0;i<4;i++){
        int j = lane + 32*i;
        s += tanhf(tr[j]) * __ldg(&W2[j]);
    }
    #pragma unroll
    for(int o=16;o;o>>=1) s += __shfl_xor_sync(0xffffffffu, s, o);
    if(lane==0) sc[r] = s;
}

// ---------------- softmax over L ----------------
__global__ void __launch_bounds__(256) softmax_kernel(const float* __restrict__ sc,
        float* __restrict__ alpha){
    __shared__ float al[L_];
    __shared__ float red[32];
    int b = blockIdx.x, t = threadIdx.x;
    float lmax = -1e30f;
    for(int i=t;i<L_;i+=256){ float v = sc[b*L_+i]; al[i]=v; lmax=fmaxf(lmax,v); }
    #pragma unroll
    for(int o=16;o;o>>=1) lmax = fmaxf(lmax, __shfl_xor_sync(0xffffffffu, lmax, o));
    if((t&31)==0) red[t>>5] = lmax;
    __syncthreads();
    if(t < 32){
        float r = (t < 8) ? red[t] : -1e30f;
        #pragma unroll
        for(int o=4;o;o>>=1) r = fmaxf(r, __shfl_xor_sync(0xffffffffu, r, o));
        if(t==0) red[0] = r;
    }
    __syncthreads();
    float mx = red[0];
    __syncthreads();
    float ls = 0.f;
    for(int i=t;i<L_;i+=256){ float e = __expf(al[i]-mx); al[i]=e; ls += e; }
    #pragma unroll
    for(int o=16;o;o>>=1) ls += __shfl_xor_sync(0xffffffffu, ls, o);
    if((t&31)==0) red[t>>5] = ls;
    __syncthreads();
    if(t < 32){
        float r = (t < 8) ? red[t] : 0.f;
        #pragma unroll
        for(int o=4;o;o>>=1) r += __shfl_xor_sync(0xffffffffu, r, o);
        if(t==0) red[0] = r;
    }
    __syncthreads();
    float inv = 1.f/red[0];
    for(int i=t;i<L_;i+=256) alpha[b*L_+i] = al[i]*inv;
}

// ---------------- attentive stats ----------------
__global__ void __launch_bounds__(128) stats_kernel(const float* __restrict__ h,
        const float* __restrict__ alpha, float* __restrict__ feat){
    __shared__ float al[L_];
    int b = blockIdx.x;
    int dd = blockIdx.y*128 + threadIdx.x;
    for(int i=threadIdx.x;i<L_;i+=128) al[i] = alpha[b*L_+i];
    __syncthreads();
    float mu = 0.f, m2 = 0.f;
    for(int l=0;l<L_;l++){
        float a  = al[l];
        float hv = h[((size_t)(b*L_ + l))*D_ + dd];
        mu += a*hv;
        m2 += a*hv*hv;
    }
    feat[b*1024 + dd]       = mu;
    feat[b*1024 + 512 + dd] = sqrtf(fmaxf(m2 - mu*mu, 1e-8f));
}

// ---------------- final classifier head ----------------
__global__ void head_kernel(const float* __restrict__ feat, const float* __restrict__ W,
                            const float* __restrict__ bb, float* __restrict__ out){
    __shared__ float fs[1024];
    int b = blockIdx.x, t = threadIdx.x;   // 320 threads
    for(int i=t;i<1024;i+=320) fs[i] = feat[b*1024 + i];
    __syncthreads();
    int w = t >> 5, lane = t & 31;
    if(w < NC_){
        float s = 0.f;
        for(int k=lane;k<1024;k+=32) s += fs[k]*W[k*NC_ + w];
        #pragma unroll
        for(int o=16;o;o>>=1) s += __shfl_xor_sync(0xffffffffu, s, o);
        if(lane==0) out[b*NC_ + w] = s + bb[w];
    }
}

// ---------------- launch ----------------
template<typename T> static void* symaddr_(T& s){
    void* p = nullptr;
    cudaGetSymbolAddress(&p, s);
    return p;
}

extern "C" void kernel_launch(void* const* d_in, const int* in_sizes, int n_in,
                              void* d_out, int out_size){
    const float* x        = (const float*)d_in[0];
    const float* patch_W  = (const float*)d_in[1];
    const float* patch_b  = (const float*)d_in[2];
    const float* patch_g  = (const float*)d_in[3];
    const float* patch_be = (const float*)d_in[4];
    const float* ln1_g    = (const float*)d_in[5];
    const float* ln1_b    = (const float*)d_in[6];
    const float* qW       = (const float*)d_in[7];
    const float* kW       = (const float*)d_in[8];
    const float* vW       = (const float*)d_in[9];
    const float* oW       = (const float*)d_in[10];
    const float* ob       = (const float*)d_in[11];
    const float* omega    = (const float*)d_in[12];
    const float* ln2_g    = (const float*)d_in[13];
    const float* ln2_b    = (const float*)d_in[14];
    const float* f1W      = (const float*)d_in[15];
    const float* f1b      = (const float*)d_in[16];
    const float* f2W      = (const float*)d_in[17];
    const float* f2b      = (const float*)d_in[18];
    const float* poolW1   = (const float*)d_in[19];
    const float* poolW2   = (const float*)d_in[20];
    const float* headW    = (const float*)d_in[21];
    const float* headb    = (const float*)d_in[22];
    float* out = (float*)d_out;

    float* h     = (float*)symaddr_(g_h);
    float* tmp   = (float*)symaddr_(g_tmp);
    float* Ksum  = (float*)symaddr_(g_Ksum);
    float* sc    = (float*)symaddr_(g_scores);
    float* alpha = (float*)symaddr_(g_alpha);
    float* feat  = (float*)symaddr_(g_feat);
    __nv_bfloat16* tokb   = (__nv_bfloat16*)symaddr_(g_tokb);
    __nv_bfloat16* x1b    = (__nv_bfloat16*)symaddr_(g_x1b);
    __nv_bfloat16* QKV    = (__nv_bfloat16*)symaddr_(g_QKV);
    __nv_bfloat16* tmpb   = (__nv_bfloat16*)symaddr_(g_tmpb);
    __nv_bfloat16* attnob = (__nv_bfloat16*)symaddr_(g_attnob);
    __nv_bfloat16* hb     = (__nv_bfloat16*)symaddr_(g_hb);
    __nv_bfloat16* KVT    = (__nv_bfloat16*)symaddr_(g_KVT);
    __nv_bfloat16* qkvWT  = (__nv_bfloat16*)symaddr_(g_qkvWT);
    __nv_bfloat16* oWT    = (__nv_bfloat16*)symaddr_(g_oWT);
    __nv_bfloat16* f1WT   = (__nv_bfloat16*)symaddr_(g_f1WT);
    __nv_bfloat16* f2WT   = (__nv_bfloat16*)symaddr_(g_f2WT);
    __nv_bfloat16* patchWT= (__nv_bfloat16*)symaddr_(g_patchWT);
    __nv_bfloat16* poolW1T= (__nv_bfloat16*)symaddr_(g_poolW1T);
    __nv_bfloat16* omT    = (__nv_bfloat16*)symaddr_(g_omT);

    static const int GEMM_SMEM   = 3*(256+128)*SA*2;                  // 92160
    static const int ATTNF_SMEM  = (64*264 + 128*72 + 128*72 + 64*72)*2 + (256+128)*4; // 81408+1536
    static const int KVPHI_SMEM  = (256*72 + 32*72 + 64*40 + 256*40)*2 + (32+256)*4;   // 68224
    cudaFuncSetAttribute(gemm_bf16<false,false>, cudaFuncAttributeMaxDynamicSharedMemorySize, GEMM_SMEM);
    cudaFuncSetAttribute(gemm_bf16<false,true>,  cudaFuncAttributeMaxDynamicSharedMemorySize, GEMM_SMEM);
    cudaFuncSetAttribute(gemm_bf16<true,true>,   cudaFuncAttributeMaxDynamicSharedMemorySize, GEMM_SMEM);
    cudaFuncSetAttribute(attn_fused,             cudaFuncAttributeMaxDynamicSharedMemorySize, ATTNF_SMEM);
    cudaFuncSetAttribute(kvphi_tc,               cudaFuncAttributeMaxDynamicSharedMemorySize, KVPHI_SMEM);

    const float SC = 0.35355339059327f;   // 64^{-1/4}
    WAll wa;
    for(int l=0;l<NL_;l++){
        wa.d[l*7+0] = { qW + (size_t)l*D_*D_,    qkvWT + (size_t)l*3*D_*D_,           D_,   D_,   D_,   1.f };
        wa.d[l*7+1] = { kW + (size_t)l*D_*D_,    qkvWT + (size_t)l*3*D_*D_ + D_*D_,   D_,   D_,   D_,   1.f };
        wa.d[l*7+2] = { vW + (size_t)l*D_*D_,    qkvWT + (size_t)l*3*D_*D_ + 2*D_*D_, D_,   D_,   D_,   1.f };
        wa.d[l*7+3] = { oW + (size_t)l*D_*D_,    oWT + (size_t)l*D_*D_,               D_,   D_,   D_,   1.f };
        wa.d[l*7+4] = { f1W + (size_t)l*D_*FFN_, f1WT + (size_t)l*FFN_*D_,            D_,   FFN_, D_,   1.f };
        wa.d[l*7+5] = { f2W + (size_t)l*FFN_*D_, f2WT + (size_t)l*D_*FFN_,            FFN_, D_,   FFN_, 1.f };
        wa.d[l*7+6] = { omega + (size_t)l*DH_*M_, omT + (size_t)l*M_*DH_,             DH_,  M_,   DH_,  SC  };
    }
    wa.d[14] = { patch_W, patchWT, C_*P_, D_,   KPATCH, 1.f };
    wa.d[15] = { poolW1,  poolW1T, D_,    HID_, D_,     1.f };
    wprep_all<<<dim3(32,32,16), dim3(32,8)>>>(wa);

    // patchify + patch embed + LN
    patchify_kernel<<<(B_*C_*T_ + 255)/256, 256>>>(x);
    gemm_bf16<false,false><<<dim3(D_/128, R_/256), 256, GEMM_SMEM>>>(tokb, patchWT, patch_b, nullptr, tmp, nullptr, R_, D_, KPATCH);
    ln_kernel<false><<<R_/4, 256>>>(tmp, patch_g, patch_be, h);

    for(int l=0;l<NL_;l++){
        const float* obl = ob + l*D_;
        const __nv_bfloat16* omTl = omT + (size_t)l*M_*DH_;
        dim3 gq(D_/128, R_/256);

        // attention branch
        ln_kernel<true><<<R_/4, 256>>>(h, ln1_g + l*D_, ln1_b + l*D_, x1b);
        gemm_bf16<false,true><<<dim3(3*D_/128, R_/256), 256, GEMM_SMEM>>>(
            x1b, qkvWT + (size_t)l*3*D_*D_, nullptr, nullptr, QKV, nullptr, R_, 3*D_, D_);
        kvphi_tc<<<B_*H_, 256, KVPHI_SMEM>>>(QKV, omTl, KVT, Ksum);
        attn_fused<<<dim3(B_*H_, LP_/128), 256, ATTNF_SMEM>>>(QKV, omTl, KVT, Ksum, attnob);
        gemm_bf16<false,false><<<gq, 256, GEMM_SMEM>>>(attnob, oWT + (size_t)l*D_*D_, obl, h, h, nullptr, R_, D_, D_);

        // FFN branch
        ln_kernel<true><<<R_/4, 256>>>(h, ln2_g + l*D_, ln2_b + l*D_, x1b);
        gemm_bf16<true,true><<<dim3(FFN_/128, R_/256), 256, GEMM_SMEM>>>(
            x1b, f1WT + (size_t)l*FFN_*D_, f1b + l*FFN_, nullptr, tmpb, nullptr, R_, FFN_, D_);
        gemm_bf16<false,false><<<gq, 256, GEMM_SMEM>>>(
            tmpb, f2WT + (size_t)l*D_*FFN_, f2b + l*D_, h, h,
            (l==NL_-1) ? hb : nullptr, R_, D_, FFN_);
    }

    // pooling + head
    gemm_bf16<false,false><<<dim3(HID_/128, R_/256), 256, GEMM_SMEM>>>(hb, poolW1T, nullptr, nullptr, tmp, nullptr, R_, HID_, D_);
    score2_kernel<<<R_/8, 256>>>(tmp, poolW2, sc);
    softmax_kernel<<<B_, 256>>>(sc, alpha);
    stats_kernel<<<dim3(B_, 4), 128>>>(h, alpha, feat);
    head_kernel<<<B_, 320>>>(feat, headW, headb, out);
}